// round 2
// baseline (speedup 1.0000x reference)
#include <cuda_runtime.h>

#define NN   50000
#define EE   800000
#define FEAT 128
#define HID  128
#define EPSL 1e-5f
#define HSS  132          // padded smem row stride (floats)

// ---------------- scratch (device globals; no allocation allowed) -------------
__device__ float g_A[NN * FEAT];      // x @ Wa   (e_w1 rows   0..127)
__device__ float g_B[NN * FEAT];      // x @ Wb   (e_w1 rows 128..255)
__device__ float g_aggm[NN * HID];    // segment-sum of m_ij
__device__ int   g_src[EE];
__device__ int   g_dst[EE];

__device__ __forceinline__ float silu_f(float v) { return v / (1.0f + expf(-v)); }

// acc += As[128x128, stride HSS] @ Bs[128x128, stride 128]
// 256 threads: (ty,tx) in 16x16, each computes an 8x8 microtile.
__device__ __forceinline__ void gemm128(const float* __restrict__ As,
                                        const float* __restrict__ Bs,
                                        float acc[8][8], int ty, int tx)
{
#pragma unroll 1
    for (int k = 0; k < 128; k += 4) {
        float4 av[8];
#pragma unroll
        for (int i = 0; i < 8; i++)
            av[i] = *reinterpret_cast<const float4*>(As + (ty * 8 + i) * HSS + k);
#pragma unroll
        for (int kk = 0; kk < 4; kk++) {
            float4 b0 = *reinterpret_cast<const float4*>(Bs + (k + kk) * 128 + tx * 8);
            float4 b1 = *reinterpret_cast<const float4*>(Bs + (k + kk) * 128 + tx * 8 + 4);
#pragma unroll
            for (int i = 0; i < 8; i++) {
                float a = (kk == 0) ? av[i].x : (kk == 1) ? av[i].y : (kk == 2) ? av[i].z : av[i].w;
                acc[i][0] += a * b0.x; acc[i][1] += a * b0.y;
                acc[i][2] += a * b0.z; acc[i][3] += a * b0.w;
                acc[i][4] += a * b1.x; acc[i][5] += a * b1.y;
                acc[i][6] += a * b1.z; acc[i][7] += a * b1.w;
            }
        }
    }
}

// In-place LayerNorm over 128-float rows of hs; warp-per-row, 16 rows/warp.
__device__ __forceinline__ void ln_rows(float* __restrict__ hs,
                                        const float* __restrict__ g,
                                        const float* __restrict__ be,
                                        int warp, int lane)
{
    int k = lane * 4;
    float4 gv  = *reinterpret_cast<const float4*>(g  + k);
    float4 bev = *reinterpret_cast<const float4*>(be + k);
#pragma unroll 1
    for (int r = 0; r < 16; r++) {
        int row = warp * 16 + r;
        float4 v = *reinterpret_cast<float4*>(hs + row * HSS + k);
        float s = v.x + v.y + v.z + v.w;
        float q = v.x * v.x + v.y * v.y + v.z * v.z + v.w * v.w;
#pragma unroll
        for (int off = 16; off > 0; off >>= 1) {
            s += __shfl_xor_sync(0xffffffffu, s, off);
            q += __shfl_xor_sync(0xffffffffu, q, off);
        }
        float mu  = s * (1.0f / 128.0f);
        float var = q * (1.0f / 128.0f) - mu * mu;
        float rs  = rsqrtf(var + EPSL);
        v.x = (v.x - mu) * rs * gv.x + bev.x;
        v.y = (v.y - mu) * rs * gv.y + bev.y;
        v.z = (v.z - mu) * rs * gv.z + bev.z;
        v.w = (v.w - mu) * rs * gv.w + bev.w;
        *reinterpret_cast<float4*>(hs + row * HSS + k) = v;
    }
}

// ---------------- K-1: normalize edge_index dtype (int64 vs int32) -----------
__global__ void conv_idx_kernel(const void* __restrict__ ei_raw)
{
    const long long* e64 = (const long long*)ei_raw;
    const int*       e32 = (const int*)ei_raw;
    // Detect: true int64 indices are all in [0, NN); int32 data reinterpreted
    // as int64 is >= 2^32 unless the paired high word is exactly 0.
    bool is64 = true;
#pragma unroll
    for (int j = 0; j < 8; j++) {
        long long v = e64[j];
        if (v < 0 || v >= NN) is64 = false;
    }
    int i = blockIdx.x * blockDim.x + threadIdx.x;
    int stride = gridDim.x * blockDim.x;
    if (is64) {
        for (int e = i; e < EE; e += stride) {
            g_src[e] = (int)e64[e];
            g_dst[e] = (int)e64[EE + e];
        }
    } else {
        for (int e = i; e < EE; e += stride) {
            g_src[e] = e32[e];
            g_dst[e] = e32[EE + e];
        }
    }
}

// ---------------- K0: zero agg_m, pos_out = pos ------------------------------
__global__ void init_kernel(const float* __restrict__ pos, float* __restrict__ out_pos)
{
    int i = blockIdx.x * blockDim.x + threadIdx.x;
    int stride = gridDim.x * blockDim.x;
    for (int j = i; j < NN * HID; j += stride) g_aggm[j] = 0.0f;
    for (int j = i; j < NN * 3;   j += stride) out_pos[j] = pos[j];
}

// ---------------- K1: A = x@Wa, B = x@Wb -------------------------------------
__global__ __launch_bounds__(256, 1)
void preab_kernel(const float* __restrict__ x, const float* __restrict__ e_w1)
{
    extern __shared__ float sm[];
    float* Bs = sm;              // 16384
    float* hs = sm + 16384;      // 128*HSS
    int tid = threadIdx.x, ty = tid >> 4, tx = tid & 15;
    int n0 = blockIdx.x * 128;

    for (int idx = tid; idx < 128 * 32; idx += 256) {
        int row = idx >> 5, q = idx & 31;
        float4 v = make_float4(0.f, 0.f, 0.f, 0.f);
        if (n0 + row < NN)
            v = *reinterpret_cast<const float4*>(x + (size_t)(n0 + row) * 128 + q * 4);
        *reinterpret_cast<float4*>(hs + row * HSS + q * 4) = v;
    }
    for (int i = tid; i < 4096; i += 256)
        reinterpret_cast<float4*>(Bs)[i] = reinterpret_cast<const float4*>(e_w1)[i];
    __syncthreads();

    float acc[8][8];
#pragma unroll
    for (int i = 0; i < 8; i++)
#pragma unroll
        for (int j = 0; j < 8; j++) acc[i][j] = 0.f;
    gemm128(hs, Bs, acc, ty, tx);
#pragma unroll
    for (int i = 0; i < 8; i++) {
        int row = n0 + ty * 8 + i;
        if (row < NN) {
            *reinterpret_cast<float4*>(g_A + (size_t)row * 128 + tx * 8) =
                make_float4(acc[i][0], acc[i][1], acc[i][2], acc[i][3]);
            *reinterpret_cast<float4*>(g_A + (size_t)row * 128 + tx * 8 + 4) =
                make_float4(acc[i][4], acc[i][5], acc[i][6], acc[i][7]);
        }
    }
    __syncthreads();
    for (int i = tid; i < 4096; i += 256)
        reinterpret_cast<float4*>(Bs)[i] = reinterpret_cast<const float4*>(e_w1 + 16384)[i];
    __syncthreads();
#pragma unroll
    for (int i = 0; i < 8; i++)
#pragma unroll
        for (int j = 0; j < 8; j++) acc[i][j] = 0.f;
    gemm128(hs, Bs, acc, ty, tx);
#pragma unroll
    for (int i = 0; i < 8; i++) {
        int row = n0 + ty * 8 + i;
        if (row < NN) {
            *reinterpret_cast<float4*>(g_B + (size_t)row * 128 + tx * 8) =
                make_float4(acc[i][0], acc[i][1], acc[i][2], acc[i][3]);
            *reinterpret_cast<float4*>(g_B + (size_t)row * 128 + tx * 8 + 4) =
                make_float4(acc[i][4], acc[i][5], acc[i][6], acc[i][7]);
        }
    }
}

// ---------------- K2: persistent edge kernel ---------------------------------
__global__ __launch_bounds__(256, 1)
void edge_kernel(const float* __restrict__ pos,
                 const float* __restrict__ ea,
                 const float* __restrict__ e_w1, const float* __restrict__ e_b1,
                 const float* __restrict__ e_g1, const float* __restrict__ e_be1,
                 const float* __restrict__ e_w2, const float* __restrict__ e_b2,
                 const float* __restrict__ e_g2, const float* __restrict__ e_be2,
                 const float* __restrict__ c_w1, const float* __restrict__ c_b1,
                 const float* __restrict__ c_w2, const float* __restrict__ c_b2,
                 float* __restrict__ out_pos)
{
    extern __shared__ float sm[];
    float* w2s  = sm;                  // 16384
    float* cw1s = w2s + 16384;         // 16384
    float* hs   = cw1s + 16384;        // 128*HSS = 16896
    float* sv   = hs + 16896;          // 1408 small vectors
    float* relx = sv + 1408;
    float* rely = relx + 128;
    float* relz = rely + 128;
    float* sr2  = relz + 128;
    float* sea0 = sr2 + 128;
    float* sea1 = sea0 + 128;
    float* scoef= sea1 + 128;
    int*   ssrc = reinterpret_cast<int*>(scoef + 128);
    int*   sdst = ssrc + 128;

    int tid = threadIdx.x, ty = tid >> 4, tx = tid & 15, warp = tid >> 5, lane = tid & 31;

    for (int i = tid; i < 4096; i += 256) {
        reinterpret_cast<float4*>(w2s)[i]  = reinterpret_cast<const float4*>(e_w2)[i];
        reinterpret_cast<float4*>(cw1s)[i] = reinterpret_cast<const float4*>(c_w1)[i];
    }
    if (tid < 128) {
        sv[tid]        = e_w1[256 * 128 + tid];  // wc0
        sv[128 + tid]  = e_w1[257 * 128 + tid];  // wc1
        sv[256 + tid]  = e_w1[258 * 128 + tid];  // wd
        sv[384 + tid]  = e_b1[tid];
        sv[512 + tid]  = e_g1[tid];
        sv[640 + tid]  = e_be1[tid];
        sv[768 + tid]  = e_b2[tid];
        sv[896 + tid]  = e_g2[tid];
        sv[1024 + tid] = e_be2[tid];
        sv[1152 + tid] = c_b1[tid];
        sv[1280 + tid] = c_w2[tid];
    }
    float cb2 = c_b2[0];
    __syncthreads();

    const int ntiles = EE / 128;   // 6250 exact
    for (int tile = blockIdx.x; tile < ntiles; tile += gridDim.x) {
        int e0 = tile * 128;
        if (tid < 128) {
            int e = e0 + tid;
            int si = g_src[e];
            int di = g_dst[e];
            float rx = pos[di * 3 + 0] - pos[si * 3 + 0];
            float ry = pos[di * 3 + 1] - pos[si * 3 + 1];
            float rz = pos[di * 3 + 2] - pos[si * 3 + 2];
            ssrc[tid] = si; sdst[tid] = di;
            relx[tid] = rx; rely[tid] = ry; relz[tid] = rz;
            sr2[tid]  = rx * rx + ry * ry + rz * rz;
            sea0[tid] = ea[2 * e];
            sea1[tid] = ea[2 * e + 1];
        }
        __syncthreads();

        // gather A[src] + B[dst] + small terms, SiLU, into hs
        {
            int k = lane * 4;
            float4 w0  = *reinterpret_cast<const float4*>(sv + k);          // wc0
            float4 w1  = *reinterpret_cast<const float4*>(sv + 128 + k);    // wc1
            float4 wdv = *reinterpret_cast<const float4*>(sv + 256 + k);    // wd
            float4 bv  = *reinterpret_cast<const float4*>(sv + 384 + k);    // b1
#pragma unroll 1
            for (int r = 0; r < 16; r++) {
                int erow = warp * 16 + r;
                int si = ssrc[erow], di = sdst[erow];
                float4 a = *reinterpret_cast<const float4*>(g_A + (size_t)si * 128 + k);
                float4 b = *reinterpret_cast<const float4*>(g_B + (size_t)di * 128 + k);
                float ea0v = sea0[erow], ea1v = sea1[erow], r2v = sr2[erow];
                float4 o;
                o.x = silu_f(a.x + b.x + ea0v * w0.x + ea1v * w1.x + r2v * wdv.x + bv.x);
                o.y = silu_f(a.y + b.y + ea0v * w0.y + ea1v * w1.y + r2v * wdv.y + bv.y);
                o.z = silu_f(a.z + b.z + ea0v * w0.z + ea1v * w1.z + r2v * wdv.z + bv.z);
                o.w = silu_f(a.w + b.w + ea0v * w0.w + ea1v * w1.w + r2v * wdv.w + bv.w);
                *reinterpret_cast<float4*>(hs + erow * HSS + k) = o;
            }
        }
        __syncthreads();
        ln_rows(hs, sv + 512, sv + 640, warp, lane);   // g1, be1
        __syncthreads();

        // GEMM1: h @ e_w2
        float acc[8][8];
#pragma unroll
        for (int i = 0; i < 8; i++)
#pragma unroll
            for (int j = 0; j < 8; j++) acc[i][j] = 0.f;
        gemm128(hs, w2s, acc, ty, tx);
        __syncthreads();

        // SiLU(acc + b2) -> hs
        {
            int c = tx * 8;
            float4 b2a = *reinterpret_cast<const float4*>(sv + 768 + c);
            float4 b2b = *reinterpret_cast<const float4*>(sv + 768 + c + 4);
#pragma unroll
            for (int i = 0; i < 8; i++) {
                int row = ty * 8 + i;
                float4 v0, v1;
                v0.x = silu_f(acc[i][0] + b2a.x); v0.y = silu_f(acc[i][1] + b2a.y);
                v0.z = silu_f(acc[i][2] + b2a.z); v0.w = silu_f(acc[i][3] + b2a.w);
                v1.x = silu_f(acc[i][4] + b2b.x); v1.y = silu_f(acc[i][5] + b2b.y);
                v1.z = silu_f(acc[i][6] + b2b.z); v1.w = silu_f(acc[i][7] + b2b.w);
                *reinterpret_cast<float4*>(hs + row * HSS + c)     = v0;
                *reinterpret_cast<float4*>(hs + row * HSS + c + 4) = v1;
            }
        }
        __syncthreads();
        ln_rows(hs, sv + 896, sv + 1024, warp, lane);  // g2, be2
        __syncthreads();

        // segment-sum m_ij into g_aggm (float RED)
        {
            int k = lane * 4;
#pragma unroll 1
            for (int r = 0; r < 16; r++) {
                int erow = warp * 16 + r;
                int di = sdst[erow];
                float4 v = *reinterpret_cast<const float4*>(hs + erow * HSS + k);
                float* base = g_aggm + (size_t)di * 128 + k;
                atomicAdd(base + 0, v.x);
                atomicAdd(base + 1, v.y);
                atomicAdd(base + 2, v.z);
                atomicAdd(base + 3, v.w);
            }
        }

        // GEMM2: m @ c_w1, then coef = sum SiLU(.)·c_w2 + c_b2
        float acc2[8][8];
#pragma unroll
        for (int i = 0; i < 8; i++)
#pragma unroll
            for (int j = 0; j < 8; j++) acc2[i][j] = 0.f;
        gemm128(hs, cw1s, acc2, ty, tx);

        float part[8];
        {
            int c = tx * 8;
            float4 cb1a = *reinterpret_cast<const float4*>(sv + 1152 + c);
            float4 cb1b = *reinterpret_cast<const float4*>(sv + 1152 + c + 4);
            float4 cw2a = *reinterpret_cast<const float4*>(sv + 1280 + c);
            float4 cw2b = *reinterpret_cast<const float4*>(sv + 1280 + c + 4);
#pragma unroll
            for (int i = 0; i < 8; i++) {
                float p = 0.f;
                p += silu_f(acc2[i][0] + cb1a.x) * cw2a.x;
                p += silu_f(acc2[i][1] + cb1a.y) * cw2a.y;
                p += silu_f(acc2[i][2] + cb1a.z) * cw2a.z;
                p += silu_f(acc2[i][3] + cb1a.w) * cw2a.w;
                p += silu_f(acc2[i][4] + cb1b.x) * cw2b.x;
                p += silu_f(acc2[i][5] + cb1b.y) * cw2b.y;
                p += silu_f(acc2[i][6] + cb1b.z) * cw2b.z;
                p += silu_f(acc2[i][7] + cb1b.w) * cw2b.w;
                part[i] = p;
            }
        }
#pragma unroll
        for (int off = 8; off > 0; off >>= 1)
#pragma unroll
            for (int i = 0; i < 8; i++)
                part[i] += __shfl_xor_sync(0xffffffffu, part[i], off);
        if (tx == 0) {
#pragma unroll
            for (int i = 0; i < 8; i++) scoef[ty * 8 + i] = part[i] + cb2;
        }
        __syncthreads();

        if (tid < 128) {
            float c = scoef[tid];
            int di = sdst[tid];
            atomicAdd(&out_pos[di * 3 + 0], relx[tid] * c);
            atomicAdd(&out_pos[di * 3 + 1], rely[tid] * c);
            atomicAdd(&out_pos[di * 3 + 2], relz[tid] * c);
        }
        __syncthreads();
    }
}

// ---------------- K3: node MLP + residual ------------------------------------
__global__ __launch_bounds__(256, 1)
void node_kernel(const float* __restrict__ x,
                 const float* __restrict__ n_w1, const float* __restrict__ n_b1,
                 const float* __restrict__ n_g1, const float* __restrict__ n_be1,
                 const float* __restrict__ n_w2, const float* __restrict__ n_b2,
                 float* __restrict__ out_x)
{
    extern __shared__ float sm[];
    float* Bs = sm;              // 16384
    float* hs = sm + 16384;      // 16896
    float* sv = hs + 16896;      // n_b1, n_g1, n_be1, n_b2 (4*128)
    int tid = threadIdx.x, ty = tid >> 4, tx = tid & 15, warp = tid >> 5, lane = tid & 31;
    int n0 = blockIdx.x * 128;

    if (tid < 128) {
        sv[tid]       = n_b1[tid];
        sv[128 + tid] = n_g1[tid];
        sv[256 + tid] = n_be1[tid];
        sv[384 + tid] = n_b2[tid];
    }

    // stage x tile + w1 rows 0..127
    for (int idx = tid; idx < 128 * 32; idx += 256) {
        int row = idx >> 5, q = idx & 31;
        float4 v = make_float4(0.f, 0.f, 0.f, 0.f);
        if (n0 + row < NN)
            v = *reinterpret_cast<const float4*>(x + (size_t)(n0 + row) * 128 + q * 4);
        *reinterpret_cast<float4*>(hs + row * HSS + q * 4) = v;
    }
    for (int i = tid; i < 4096; i += 256)
        reinterpret_cast<float4*>(Bs)[i] = reinterpret_cast<const float4*>(n_w1)[i];
    __syncthreads();

    float acc[8][8];
#pragma unroll
    for (int i = 0; i < 8; i++)
#pragma unroll
        for (int j = 0; j < 8; j++) acc[i][j] = 0.f;
    gemm128(hs, Bs, acc, ty, tx);
    __syncthreads();

    // stage agg_m tile + w1 rows 128..255, continue accumulation
    for (int idx = tid; idx < 128 * 32; idx += 256) {
        int row = idx >> 5, q = idx & 31;
        float4 v = make_float4(0.f, 0.f, 0.f, 0.f);
        if (n0 + row < NN)
            v = *reinterpret_cast<const float4*>(g_aggm + (size_t)(n0 + row) * 128 + q * 4);
        *reinterpret_cast<float4*>(hs + row * HSS + q * 4) = v;
    }
    for (int i = tid; i < 4096; i += 256)
        reinterpret_cast<float4*>(Bs)[i] = reinterpret_cast<const float4*>(n_w1 + 16384)[i];
    __syncthreads();
    gemm128(hs, Bs, acc, ty, tx);
    __syncthreads();

    // SiLU(acc + n_b1) -> hs ; LN(g1, be1)
    {
        int c = tx * 8;
        float4 ba = *reinterpret_cast<const float4*>(sv + c);
        float4 bb = *reinterpret_cast<const float4*>(sv + c + 4);
#pragma unroll
        for (int i = 0; i < 8; i++) {
            int row = ty * 8 + i;
            float4 v0, v1;
            v0.x = silu_f(acc[i][0] + ba.x); v0.y = silu_f(acc[i][1] + ba.y);
            v0.z = silu_f(acc[i][2] + ba.z); v0.w = silu_f(acc[i][3] + ba.w);
            v1.x = silu_f(acc[i][4] + bb.x); v1.y = silu_f(acc[i][5] + bb.y);
            v1.z = silu_f(acc[i][6] + bb.z); v1.w = silu_f(acc[i][7] + bb.w);
            *reinterpret_cast<float4*>(hs + row * HSS + c)     = v0;
            *reinterpret_cast<float4*>(hs + row * HSS + c + 4) = v1;
        }
    }
    __syncthreads();
    ln_rows(hs, sv + 128, sv + 256, warp, lane);
    __syncthreads();

    // GEMM2 vs n_w2, + n_b2 + residual x
    for (int i = tid; i < 4096; i += 256)
        reinterpret_cast<float4*>(Bs)[i] = reinterpret_cast<const float4*>(n_w2)[i];
    __syncthreads();
    float acc2[8][8];
#pragma unroll
    for (int i = 0; i < 8; i++)
#pragma unroll
        for (int j = 0; j < 8; j++) acc2[i][j] = 0.f;
    gemm128(hs, Bs, acc2, ty, tx);

    {
        int c = tx * 8;
        float4 ba = *reinterpret_cast<const float4*>(sv + 384 + c);
        float4 bb = *reinterpret_cast<const float4*>(sv + 384 + c + 4);
#pragma unroll
        for (int i = 0; i < 8; i++) {
            int row = n0 + ty * 8 + i;
            if (row < NN) {
                float4 xv0 = *reinterpret_cast<const float4*>(x + (size_t)row * 128 + c);
                float4 xv1 = *reinterpret_cast<const float4*>(x + (size_t)row * 128 + c + 4);
                float4 o0, o1;
                o0.x = acc2[i][0] + ba.x + xv0.x; o0.y = acc2[i][1] + ba.y + xv0.y;
                o0.z = acc2[i][2] + ba.z + xv0.z; o0.w = acc2[i][3] + ba.w + xv0.w;
                o1.x = acc2[i][4] + bb.x + xv1.x; o1.y = acc2[i][5] + bb.y + xv1.y;
                o1.z = acc2[i][6] + bb.z + xv1.z; o1.w = acc2[i][7] + bb.w + xv1.w;
                *reinterpret_cast<float4*>(out_x + (size_t)row * 128 + c)     = o0;
                *reinterpret_cast<float4*>(out_x + (size_t)row * 128 + c + 4) = o1;
            }
        }
    }
}

// ---------------- launch ------------------------------------------------------
extern "C" void kernel_launch(void* const* d_in, const int* in_sizes, int n_in,
                              void* d_out, int out_size)
{
    const float*     x     = (const float*)d_in[0];
    const float*     pos   = (const float*)d_in[1];
    const void*      ei    = d_in[2];
    const float*     ea    = (const float*)d_in[3];
    const float*     e_w1  = (const float*)d_in[4];
    const float*     e_b1  = (const float*)d_in[5];
    const float*     e_g1  = (const float*)d_in[6];
    const float*     e_be1 = (const float*)d_in[7];
    const float*     e_w2  = (const float*)d_in[8];
    const float*     e_b2  = (const float*)d_in[9];
    const float*     e_g2  = (const float*)d_in[10];
    const float*     e_be2 = (const float*)d_in[11];
    const float*     n_w1  = (const float*)d_in[12];
    const float*     n_b1  = (const float*)d_in[13];
    const float*     n_g1  = (const float*)d_in[14];
    const float*     n_be1 = (const float*)d_in[15];
    const float*     n_w2  = (const float*)d_in[16];
    const float*     n_b2  = (const float*)d_in[17];
    const float*     c_w1  = (const float*)d_in[18];
    const float*     c_b1  = (const float*)d_in[19];
    const float*     c_w2  = (const float*)d_in[20];
    const float*     c_b2  = (const float*)d_in[21];

    float* out_x   = (float*)d_out;
    float* out_pos = (float*)d_out + (size_t)NN * FEAT;

    const int SMEM_PRE  = (16384 + 16896) * 4;                 // 133120
    const int SMEM_EDGE = (16384 * 2 + 16896 + 1408 + 7 * 128 + 256) * 4; // 208896
    const int SMEM_NODE = (16384 + 16896 + 512) * 4;           // 135168

    cudaFuncSetAttribute(preab_kernel, cudaFuncAttributeMaxDynamicSharedMemorySize, SMEM_PRE);
    cudaFuncSetAttribute(edge_kernel,  cudaFuncAttributeMaxDynamicSharedMemorySize, SMEM_EDGE);
    cudaFuncSetAttribute(node_kernel,  cudaFuncAttributeMaxDynamicSharedMemorySize, SMEM_NODE);

    conv_idx_kernel<<<256, 256>>>(ei);
    init_kernel<<<256, 256>>>(pos, out_pos);
    preab_kernel<<<(NN + 127) / 128, 256, SMEM_PRE>>>(x, e_w1);
    edge_kernel<<<148, 256, SMEM_EDGE>>>(pos, ea,
                                         e_w1, e_b1, e_g1, e_be1,
                                         e_w2, e_b2, e_g2, e_be2,
                                         c_w1, c_b1, c_w2, c_b2,
                                         out_pos);
    node_kernel<<<(NN + 127) / 128, 256, SMEM_NODE>>>(x, n_w1, n_b1, n_g1, n_be1,
                                                      n_w2, n_b2, out_x);
}

// round 4
// speedup vs baseline: 1.5752x; 1.5752x over previous
#include <cuda_runtime.h>
#include <cstdint>

#define NN   50000
#define EE   800000
#define FEAT 128
#define HID  128
#define EPSL 1e-5f
#define HSS  132          // padded smem row stride (floats) for SIMT kernels

#define ASTR 132          // edge A-tile stride (floats)
#define BSTR 136          // edge weight-tile stride (floats)

// ---------------- scratch (device globals) -----------------------------------
__device__ float g_A[NN * FEAT];      // x @ Wa   (e_w1 rows   0..127)
__device__ float g_B[NN * FEAT];      // x @ Wb   (e_w1 rows 128..255)
__device__ float g_aggm[NN * HID];    // segment-sum of m_ij
__device__ int   g_src[EE];
__device__ int   g_dst[EE];

__device__ __forceinline__ float silu_f(float v) { return v / (1.0f + expf(-v)); }
__device__ __forceinline__ uint32_t f2tf32(float f) {
    uint32_t r; asm("cvt.rna.tf32.f32 %0, %1;" : "=r"(r) : "f"(f)); return r;
}
__device__ __forceinline__ void mma8(float* d, const uint32_t* a, const uint32_t* b) {
    asm volatile("mma.sync.aligned.m16n8k8.row.col.f32.tf32.tf32.f32 "
                 "{%0,%1,%2,%3}, {%4,%5,%6,%7}, {%8,%9}, {%0,%1,%2,%3};"
                 : "+f"(d[0]), "+f"(d[1]), "+f"(d[2]), "+f"(d[3])
                 : "r"(a[0]), "r"(a[1]), "r"(a[2]), "r"(a[3]), "r"(b[0]), "r"(b[1]));
}

// ======================= SIMT gemm helpers (preab/node) =======================
__device__ __forceinline__ void gemm128(const float* __restrict__ As,
                                        const float* __restrict__ Bs,
                                        float acc[8][8], int ty, int tx)
{
#pragma unroll 1
    for (int k = 0; k < 128; k += 4) {
        float4 av[8];
#pragma unroll
        for (int i = 0; i < 8; i++)
            av[i] = *reinterpret_cast<const float4*>(As + (ty * 8 + i) * HSS + k);
#pragma unroll
        for (int kk = 0; kk < 4; kk++) {
            float4 b0 = *reinterpret_cast<const float4*>(Bs + (k + kk) * 128 + tx * 8);
            float4 b1 = *reinterpret_cast<const float4*>(Bs + (k + kk) * 128 + tx * 8 + 4);
#pragma unroll
            for (int i = 0; i < 8; i++) {
                float a = (kk == 0) ? av[i].x : (kk == 1) ? av[i].y : (kk == 2) ? av[i].z : av[i].w;
                acc[i][0] += a * b0.x; acc[i][1] += a * b0.y;
                acc[i][2] += a * b0.z; acc[i][3] += a * b0.w;
                acc[i][4] += a * b1.x; acc[i][5] += a * b1.y;
                acc[i][6] += a * b1.z; acc[i][7] += a * b1.w;
            }
        }
    }
}

__device__ __forceinline__ void ln_rows(float* __restrict__ hs,
                                        const float* __restrict__ g,
                                        const float* __restrict__ be,
                                        int warp, int lane)
{
    int k = lane * 4;
    float4 gv  = *reinterpret_cast<const float4*>(g  + k);
    float4 bev = *reinterpret_cast<const float4*>(be + k);
#pragma unroll 1
    for (int r = 0; r < 16; r++) {
        int row = warp * 16 + r;
        float4 v = *reinterpret_cast<float4*>(hs + row * HSS + k);
        float s = v.x + v.y + v.z + v.w;
        float q = v.x * v.x + v.y * v.y + v.z * v.z + v.w * v.w;
#pragma unroll
        for (int off = 16; off > 0; off >>= 1) {
            s += __shfl_xor_sync(0xffffffffu, s, off);
            q += __shfl_xor_sync(0xffffffffu, q, off);
        }
        float mu  = s * (1.0f / 128.0f);
        float var = q * (1.0f / 128.0f) - mu * mu;
        float rs  = rsqrtf(var + EPSL);
        v.x = (v.x - mu) * rs * gv.x + bev.x;
        v.y = (v.y - mu) * rs * gv.y + bev.y;
        v.z = (v.z - mu) * rs * gv.z + bev.z;
        v.w = (v.w - mu) * rs * gv.w + bev.w;
        *reinterpret_cast<float4*>(hs + row * HSS + k) = v;
    }
}

// ---------------- K-1: normalize edge_index dtype ----------------------------
__global__ void conv_idx_kernel(const void* __restrict__ ei_raw)
{
    const long long* e64 = (const long long*)ei_raw;
    const int*       e32 = (const int*)ei_raw;
    bool is64 = true;
#pragma unroll
    for (int j = 0; j < 8; j++) {
        long long v = e64[j];
        if (v < 0 || v >= NN) is64 = false;
    }
    int i = blockIdx.x * blockDim.x + threadIdx.x;
    int stride = gridDim.x * blockDim.x;
    if (is64) {
        for (int e = i; e < EE; e += stride) {
            g_src[e] = (int)e64[e];
            g_dst[e] = (int)e64[EE + e];
        }
    } else {
        for (int e = i; e < EE; e += stride) {
            g_src[e] = e32[e];
            g_dst[e] = e32[EE + e];
        }
    }
}

// ---------------- K0: zero agg_m, pos_out = pos ------------------------------
__global__ void init_kernel(const float* __restrict__ pos, float* __restrict__ out_pos)
{
    int i = blockIdx.x * blockDim.x + threadIdx.x;
    int stride = gridDim.x * blockDim.x;
    for (int j = i; j < NN * HID; j += stride) g_aggm[j] = 0.0f;
    for (int j = i; j < NN * 3;   j += stride) out_pos[j] = pos[j];
}

// ---------------- K1: A = x@Wa, B = x@Wb -------------------------------------
__global__ __launch_bounds__(256, 1)
void preab_kernel(const float* __restrict__ x, const float* __restrict__ e_w1)
{
    extern __shared__ float sm[];
    float* Bs = sm;
    float* hs = sm + 16384;
    int tid = threadIdx.x, ty = tid >> 4, tx = tid & 15;
    int n0 = blockIdx.x * 128;

    for (int idx = tid; idx < 128 * 32; idx += 256) {
        int row = idx >> 5, q = idx & 31;
        float4 v = make_float4(0.f, 0.f, 0.f, 0.f);
        if (n0 + row < NN)
            v = *reinterpret_cast<const float4*>(x + (size_t)(n0 + row) * 128 + q * 4);
        *reinterpret_cast<float4*>(hs + row * HSS + q * 4) = v;
    }
    for (int i = tid; i < 4096; i += 256)
        reinterpret_cast<float4*>(Bs)[i] = reinterpret_cast<const float4*>(e_w1)[i];
    __syncthreads();

    float acc[8][8];
#pragma unroll
    for (int i = 0; i < 8; i++)
#pragma unroll
        for (int j = 0; j < 8; j++) acc[i][j] = 0.f;
    gemm128(hs, Bs, acc, ty, tx);
#pragma unroll
    for (int i = 0; i < 8; i++) {
        int row = n0 + ty * 8 + i;
        if (row < NN) {
            *reinterpret_cast<float4*>(g_A + (size_t)row * 128 + tx * 8) =
                make_float4(acc[i][0], acc[i][1], acc[i][2], acc[i][3]);
            *reinterpret_cast<float4*>(g_A + (size_t)row * 128 + tx * 8 + 4) =
                make_float4(acc[i][4], acc[i][5], acc[i][6], acc[i][7]);
        }
    }
    __syncthreads();
    for (int i = tid; i < 4096; i += 256)
        reinterpret_cast<float4*>(Bs)[i] = reinterpret_cast<const float4*>(e_w1 + 16384)[i];
    __syncthreads();
#pragma unroll
    for (int i = 0; i < 8; i++)
#pragma unroll
        for (int j = 0; j < 8; j++) acc[i][j] = 0.f;
    gemm128(hs, Bs, acc, ty, tx);
#pragma unroll
    for (int i = 0; i < 8; i++) {
        int row = n0 + ty * 8 + i;
        if (row < NN) {
            *reinterpret_cast<float4*>(g_B + (size_t)row * 128 + tx * 8) =
                make_float4(acc[i][0], acc[i][1], acc[i][2], acc[i][3]);
            *reinterpret_cast<float4*>(g_B + (size_t)row * 128 + tx * 8 + 4) =
                make_float4(acc[i][4], acc[i][5], acc[i][6], acc[i][7]);
        }
    }
}

// ---------------- K2: persistent edge kernel (mma.sync tf32) -----------------
// smem float layout
#define EO_A    0                       // 128*ASTR = 16896
#define EO_B1   16896                   // 128*BSTR = 17408
#define EO_B2   34304
#define EO_SV   51712
// sv float indices (relative to sv)
#define SV_WC0  0
#define SV_WC1  128
#define SV_WD   256
#define SV_B1   384
#define SV_G1   512
#define SV_BE1  640
#define SV_B2   768
#define SV_G2   896
#define SV_BE2  1024
#define SV_CB1  1152
#define SV_CW2  1280
#define SV_RELX 1408
#define SV_RELY 1536
#define SV_RELZ 1664
#define SV_R2   1792
#define SV_EA0  1920
#define SV_EA1  2048
#define SV_SUM  2176   // [128][4]
#define SV_SQ   2688   // [128][4]
#define SV_MU   3200   // 128
#define SV_RS   3328   // 128
#define SV_IDX  3456   // ints: 128 dst, 128 src
#define SV_FLOATS 3712
#define EDGE_SMEM ((EO_SV + SV_FLOATS) * 4)   // 221696 bytes

// per-warp tf32 GEMM: C[64x32] += A[64x128] * B[128x32]
// afrags from As (stride ASTR), bfrags from Bs (stride BSTR)
__device__ __forceinline__ void warp_gemm_tf32(const uint32_t* __restrict__ Au,
                                               const uint32_t* __restrict__ Bu,
                                               float c[4][4][4],
                                               int mbase, int nbase, int g, int t)
{
#pragma unroll 1
    for (int ks = 0; ks < 16; ks++) {
        int kk = ks * 8;
        uint32_t af[4][4];
#pragma unroll
        for (int mt = 0; mt < 4; mt++) {
            const uint32_t* p = Au + (mbase + mt * 16 + g) * ASTR + kk + t;
            af[mt][0] = p[0];
            af[mt][1] = p[8 * ASTR];
            af[mt][2] = p[4];
            af[mt][3] = p[8 * ASTR + 4];
        }
        uint32_t bf[4][2];
#pragma unroll
        for (int nt = 0; nt < 4; nt++) {
            const uint32_t* p = Bu + (kk + t) * BSTR + nbase + nt * 8 + g;
            bf[nt][0] = p[0];
            bf[nt][1] = p[4 * BSTR];
        }
#pragma unroll
        for (int mt = 0; mt < 4; mt++)
#pragma unroll
            for (int nt = 0; nt < 4; nt++)
                mma8(c[mt][nt], af[mt], bf[nt]);
    }
}

__global__ __launch_bounds__(256, 1)
void edge_kernel(const float* __restrict__ pos,
                 const float* __restrict__ ea,
                 const float* __restrict__ e_w1, const float* __restrict__ e_b1,
                 const float* __restrict__ e_g1, const float* __restrict__ e_be1,
                 const float* __restrict__ e_w2, const float* __restrict__ e_b2,
                 const float* __restrict__ e_g2, const float* __restrict__ e_be2,
                 const float* __restrict__ c_w1, const float* __restrict__ c_b1,
                 const float* __restrict__ c_w2, const float* __restrict__ c_b2,
                 float* __restrict__ out_pos)
{
    extern __shared__ float sm[];
    float* As  = sm + EO_A;
    float* B1s = sm + EO_B1;
    float* B2s = sm + EO_B2;
    float* sv  = sm + EO_SV;
    int*   sdst = (int*)(sv + SV_IDX);
    int*   ssrc = sdst + 128;
    const uint32_t* Au  = (const uint32_t*)As;
    const uint32_t* B1u = (const uint32_t*)B1s;
    const uint32_t* B2u = (const uint32_t*)B2s;

    int tid = threadIdx.x, warp = tid >> 5, lane = tid & 31;
    int g = lane >> 2, t = lane & 3;
    int wm = warp >> 2, wn = warp & 3;
    int mbase = wm * 64, nbase = wn * 32;

    // ---- stage weights (tf32) + small vectors ----
    for (int idx = tid; idx < 16384; idx += 256) {
        int k = idx >> 7, n = idx & 127;
        B1s[k * BSTR + n] = __uint_as_float(f2tf32(e_w2[k * 128 + n]));
        B2s[k * BSTR + n] = __uint_as_float(f2tf32(c_w1[k * 128 + n]));
    }
    if (tid < 128) {
        sv[SV_WC0 + tid] = e_w1[256 * 128 + tid];
        sv[SV_WC1 + tid] = e_w1[257 * 128 + tid];
        sv[SV_WD  + tid] = e_w1[258 * 128 + tid];
        sv[SV_B1  + tid] = e_b1[tid];
        sv[SV_G1  + tid] = e_g1[tid];
        sv[SV_BE1 + tid] = e_be1[tid];
        sv[SV_B2  + tid] = e_b2[tid];
        sv[SV_G2  + tid] = e_g2[tid];
        sv[SV_BE2 + tid] = e_be2[tid];
        sv[SV_CB1 + tid] = c_b1[tid];
        sv[SV_CW2 + tid] = c_w2[tid];
    }
    float cb2 = c_b2[0];
    __syncthreads();

    // per-thread layer-1 constants (lane-sliced float4)
    int k4 = lane * 4;
    float4 wc0 = *(const float4*)(sv + SV_WC0 + k4);
    float4 wc1 = *(const float4*)(sv + SV_WC1 + k4);
    float4 wdv = *(const float4*)(sv + SV_WD  + k4);
    float4 b1v = *(const float4*)(sv + SV_B1  + k4);
    float4 g1v = *(const float4*)(sv + SV_G1  + k4);
    float4 be1v= *(const float4*)(sv + SV_BE1 + k4);

    const int ntiles = EE / 128;
    for (int tile = blockIdx.x; tile < ntiles; tile += gridDim.x) {
        int e0 = tile * 128;
        // ---- stage edge meta ----
        if (tid < 128) {
            int e = e0 + tid;
            int si = g_src[e], di = g_dst[e];
            float rx = pos[di * 3 + 0] - pos[si * 3 + 0];
            float ry = pos[di * 3 + 1] - pos[si * 3 + 1];
            float rz = pos[di * 3 + 2] - pos[si * 3 + 2];
            ssrc[tid] = si; sdst[tid] = di;
            sv[SV_RELX + tid] = rx; sv[SV_RELY + tid] = ry; sv[SV_RELZ + tid] = rz;
            sv[SV_R2 + tid]  = rx * rx + ry * ry + rz * rz;
            sv[SV_EA0 + tid] = ea[2 * e];
            sv[SV_EA1 + tid] = ea[2 * e + 1];
        }
        __syncthreads();

        // ---- layer-1: gather + SiLU + LN -> As (tf32) ----
#pragma unroll 1
        for (int r = 0; r < 16; r++) {
            int row = warp * 16 + r;
            int si = ssrc[row], di = sdst[row];
            float4 a = *(const float4*)(g_A + (size_t)si * 128 + k4);
            float4 b = *(const float4*)(g_B + (size_t)di * 128 + k4);
            float e0v = sv[SV_EA0 + row], e1v = sv[SV_EA1 + row], r2v = sv[SV_R2 + row];
            float4 o;
            o.x = silu_f(a.x + b.x + e0v * wc0.x + e1v * wc1.x + r2v * wdv.x + b1v.x);
            o.y = silu_f(a.y + b.y + e0v * wc0.y + e1v * wc1.y + r2v * wdv.y + b1v.y);
            o.z = silu_f(a.z + b.z + e0v * wc0.z + e1v * wc1.z + r2v * wdv.z + b1v.z);
            o.w = silu_f(a.w + b.w + e0v * wc0.w + e1v * wc1.w + r2v * wdv.w + b1v.w);
            float s = o.x + o.y + o.z + o.w;
            float q = o.x * o.x + o.y * o.y + o.z * o.z + o.w * o.w;
#pragma unroll
            for (int off = 16; off > 0; off >>= 1) {
                s += __shfl_xor_sync(0xffffffffu, s, off);
                q += __shfl_xor_sync(0xffffffffu, q, off);
            }
            float mu = s * (1.0f / 128.0f);
            float rs = rsqrtf(q * (1.0f / 128.0f) - mu * mu + EPSL);
            uint4 tv;
            tv.x = f2tf32((o.x - mu) * rs * g1v.x + be1v.x);
            tv.y = f2tf32((o.y - mu) * rs * g1v.y + be1v.y);
            tv.z = f2tf32((o.z - mu) * rs * g1v.z + be1v.z);
            tv.w = f2tf32((o.w - mu) * rs * g1v.w + be1v.w);
            *(uint4*)(As + row * ASTR + k4) = tv;
        }
        __syncthreads();

        // ---- GEMM1: h @ e_w2 ----
        float c[4][4][4];
#pragma unroll
        for (int mt = 0; mt < 4; mt++)
#pragma unroll
            for (int nt = 0; nt < 4; nt++)
#pragma unroll
                for (int j = 0; j < 4; j++) c[mt][nt][j] = 0.f;
        warp_gemm_tf32(Au, B1u, c, mbase, nbase, g, t);
        __syncthreads();   // done reading As; will rewrite below

        // ---- epilogue1: bias + SiLU, rowsum, LN, agg atomics, store m ----
        float s0[4], s1[4], q0[4], q1[4];
#pragma unroll
        for (int mt = 0; mt < 4; mt++) {
            s0[mt] = s1[mt] = q0[mt] = q1[mt] = 0.f;
#pragma unroll
            for (int nt = 0; nt < 4; nt++) {
                int col = nbase + nt * 8 + 2 * t;
                float v0 = silu_f(c[mt][nt][0] + sv[SV_B2 + col]);
                float v1 = silu_f(c[mt][nt][1] + sv[SV_B2 + col + 1]);
                float v2 = silu_f(c[mt][nt][2] + sv[SV_B2 + col]);
                float v3 = silu_f(c[mt][nt][3] + sv[SV_B2 + col + 1]);
                c[mt][nt][0] = v0; c[mt][nt][1] = v1; c[mt][nt][2] = v2; c[mt][nt][3] = v3;
                s0[mt] += v0 + v1; q0[mt] += v0 * v0 + v1 * v1;
                s1[mt] += v2 + v3; q1[mt] += v2 * v2 + v3 * v3;
            }
#pragma unroll
            for (int off = 1; off <= 2; off <<= 1) {
                s0[mt] += __shfl_xor_sync(0xffffffffu, s0[mt], off);
                s1[mt] += __shfl_xor_sync(0xffffffffu, s1[mt], off);
                q0[mt] += __shfl_xor_sync(0xffffffffu, q0[mt], off);
                q1[mt] += __shfl_xor_sync(0xffffffffu, q1[mt], off);
            }
            if (t == 0) {
                int r0 = mbase + mt * 16 + g;
                sv[SV_SUM + r0 * 4 + wn] = s0[mt];
                sv[SV_SQ  + r0 * 4 + wn] = q0[mt];
                sv[SV_SUM + (r0 + 8) * 4 + wn] = s1[mt];
                sv[SV_SQ  + (r0 + 8) * 4 + wn] = q1[mt];
            }
        }
        __syncthreads();
        if (tid < 128) {
            float s = sv[SV_SUM + tid * 4] + sv[SV_SUM + tid * 4 + 1]
                    + sv[SV_SUM + tid * 4 + 2] + sv[SV_SUM + tid * 4 + 3];
            float q = sv[SV_SQ + tid * 4] + sv[SV_SQ + tid * 4 + 1]
                    + sv[SV_SQ + tid * 4 + 2] + sv[SV_SQ + tid * 4 + 3];
            float mu = s * (1.0f / 128.0f);
            sv[SV_MU + tid] = mu;
            sv[SV_RS + tid] = rsqrtf(q * (1.0f / 128.0f) - mu * mu + EPSL);
        }
        __syncthreads();
#pragma unroll
        for (int mt = 0; mt < 4; mt++) {
            int r0 = mbase + mt * 16 + g, r1 = r0 + 8;
            float mu0 = sv[SV_MU + r0], rs0 = sv[SV_RS + r0];
            float mu1 = sv[SV_MU + r1], rs1 = sv[SV_RS + r1];
            int d0 = sdst[r0], d1 = sdst[r1];
#pragma unroll
            for (int nt = 0; nt < 4; nt++) {
                int col = nbase + nt * 8 + 2 * t;
                float g2a = sv[SV_G2 + col],  g2b = sv[SV_G2 + col + 1];
                float bea = sv[SV_BE2 + col], beb = sv[SV_BE2 + col + 1];
                float n0 = (c[mt][nt][0] - mu0) * rs0 * g2a + bea;
                float n1 = (c[mt][nt][1] - mu0) * rs0 * g2b + beb;
                float n2 = (c[mt][nt][2] - mu1) * rs1 * g2a + bea;
                float n3 = (c[mt][nt][3] - mu1) * rs1 * g2b + beb;
                asm volatile("red.global.add.v2.f32 [%0], {%1, %2};"
                             :: "l"(g_aggm + (size_t)d0 * 128 + col), "f"(n0), "f"(n1) : "memory");
                asm volatile("red.global.add.v2.f32 [%0], {%1, %2};"
                             :: "l"(g_aggm + (size_t)d1 * 128 + col), "f"(n2), "f"(n3) : "memory");
                uint2 p0; p0.x = f2tf32(n0); p0.y = f2tf32(n1);
                uint2 p1; p1.x = f2tf32(n2); p1.y = f2tf32(n3);
                *(uint2*)(As + r0 * ASTR + col) = p0;
                *(uint2*)(As + r1 * ASTR + col) = p1;
            }
        }
        __syncthreads();

        // ---- GEMM2: m @ c_w1 ----
#pragma unroll
        for (int mt = 0; mt < 4; mt++)
#pragma unroll
            for (int nt = 0; nt < 4; nt++)
#pragma unroll
                for (int j = 0; j < 4; j++) c[mt][nt][j] = 0.f;
        warp_gemm_tf32(Au, B2u, c, mbase, nbase, g, t);

        // ---- epilogue2: coef = silu(. + cb1) . cw2 ; pos atomics ----
#pragma unroll
        for (int mt = 0; mt < 4; mt++) {
            float p0 = 0.f, p1 = 0.f;
#pragma unroll
            for (int nt = 0; nt < 4; nt++) {
                int col = nbase + nt * 8 + 2 * t;
                float ca = sv[SV_CB1 + col], cb = sv[SV_CB1 + col + 1];
                float wa = sv[SV_CW2 + col], wb = sv[SV_CW2 + col + 1];
                p0 += silu_f(c[mt][nt][0] + ca) * wa + silu_f(c[mt][nt][1] + cb) * wb;
                p1 += silu_f(c[mt][nt][2] + ca) * wa + silu_f(c[mt][nt][3] + cb) * wb;
            }
#pragma unroll
            for (int off = 1; off <= 2; off <<= 1) {
                p0 += __shfl_xor_sync(0xffffffffu, p0, off);
                p1 += __shfl_xor_sync(0xffffffffu, p1, off);
            }
            if (t == 0) {
                int r0 = mbase + mt * 16 + g;
                sv[SV_SUM + r0 * 4 + wn] = p0;
                sv[SV_SUM + (r0 + 8) * 4 + wn] = p1;
            }
        }
        __syncthreads();
        if (tid < 128) {
            float coef = sv[SV_SUM + tid * 4] + sv[SV_SUM + tid * 4 + 1]
                       + sv[SV_SUM + tid * 4 + 2] + sv[SV_SUM + tid * 4 + 3] + cb2;
            int di = sdst[tid];
            atomicAdd(&out_pos[di * 3 + 0], sv[SV_RELX + tid] * coef);
            atomicAdd(&out_pos[di * 3 + 1], sv[SV_RELY + tid] * coef);
            atomicAdd(&out_pos[di * 3 + 2], sv[SV_RELZ + tid] * coef);
        }
        __syncthreads();
    }
}

// ---------------- K3: node MLP + residual ------------------------------------
__global__ __launch_bounds__(256, 1)
void node_kernel(const float* __restrict__ x,
                 const float* __restrict__ n_w1, const float* __restrict__ n_b1,
                 const float* __restrict__ n_g1, const float* __restrict__ n_be1,
                 const float* __restrict__ n_w2, const float* __restrict__ n_b2,
                 float* __restrict__ out_x)
{
    extern __shared__ float smf[];
    float* Bs = smf;
    float* hs = smf + 16384;
    float* sv = hs + 16896;
    int tid = threadIdx.x, ty = tid >> 4, tx = tid & 15, warp = tid >> 5, lane = tid & 31;
    int n0 = blockIdx.x * 128;

    if (tid < 128) {
        sv[tid]       = n_b1[tid];
        sv[128 + tid] = n_g1[tid];
        sv[256 + tid] = n_be1[tid];
        sv[384 + tid] = n_b2[tid];
    }

    for (int idx = tid; idx < 128 * 32; idx += 256) {
        int row = idx >> 5, q = idx & 31;
        float4 v = make_float4(0.f, 0.f, 0.f, 0.f);
        if (n0 + row < NN)
            v = *reinterpret_cast<const float4*>(x + (size_t)(n0 + row) * 128 + q * 4);
        *reinterpret_cast<float4*>(hs + row * HSS + q * 4) = v;
    }
    for (int i = tid; i < 4096; i += 256)
        reinterpret_cast<float4*>(Bs)[i] = reinterpret_cast<const float4*>(n_w1)[i];
    __syncthreads();

    float acc[8][8];
#pragma unroll
    for (int i = 0; i < 8; i++)
#pragma unroll
        for (int j = 0; j < 8; j++) acc[i][j] = 0.f;
    gemm128(hs, Bs, acc, ty, tx);
    __syncthreads();

    for (int idx = tid; idx < 128 * 32; idx += 256) {
        int row = idx >> 5, q = idx & 31;
        float4 v = make_float4(0.f, 0.f, 0.f, 0.f);
        if (n0 + row < NN)
            v = *reinterpret_cast<const float4*>(g_aggm + (size_t)(n0 + row) * 128 + q * 4);
        *reinterpret_cast<float4*>(hs + row * HSS + q * 4) = v;
    }
    for (int i = tid; i < 4096; i += 256)
        reinterpret_cast<float4*>(Bs)[i] = reinterpret_cast<const float4*>(n_w1 + 16384)[i];
    __syncthreads();
    gemm128(hs, Bs, acc, ty, tx);
    __syncthreads();

    {
        int c = tx * 8;
        float4 ba = *reinterpret_cast<const float4*>(sv + c);
        float4 bb = *reinterpret_cast<const float4*>(sv + c + 4);
#pragma unroll
        for (int i = 0; i < 8; i++) {
            int row = ty * 8 + i;
            float4 v0, v1;
            v0.x = silu_f(acc[i][0] + ba.x); v0.y = silu_f(acc[i][1] + ba.y);
            v0.z = silu_f(acc[i][2] + ba.z); v0.w = silu_f(acc[i][3] + ba.w);
            v1.x = silu_f(acc[i][4] + bb.x); v1.y = silu_f(acc[i][5] + bb.y);
            v1.z = silu_f(acc[i][6] + bb.z); v1.w = silu_f(acc[i][7] + bb.w);
            *reinterpret_cast<float4*>(hs + row * HSS + c)     = v0;
            *reinterpret_cast<float4*>(hs + row * HSS + c + 4) = v1;
        }
    }
    __syncthreads();
    ln_rows(hs, sv + 128, sv + 256, warp, lane);
    __syncthreads();

    for (int i = tid; i < 4096; i += 256)
        reinterpret_cast<float4*>(Bs)[i] = reinterpret_cast<const float4*>(n_w2)[i];
    __syncthreads();
    float acc2[8][8];
#pragma unroll
    for (int i = 0; i < 8; i++)
#pragma unroll
        for (int j = 0; j < 8; j++) acc2[i][j] = 0.f;
    gemm128(hs, Bs, acc2, ty, tx);

    {
        int c = tx * 8;
        float4 ba = *reinterpret_cast<const float4*>(sv + 384 + c);
        float4 bb = *reinterpret_cast<const float4*>(sv + 384 + c + 4);
#pragma unroll
        for (int i = 0; i < 8; i++) {
            int row = n0 + ty * 8 + i;
            if (row < NN) {
                float4 xv0 = *reinterpret_cast<const float4*>(x + (size_t)row * 128 + c);
                float4 xv1 = *reinterpret_cast<const float4*>(x + (size_t)row * 128 + c + 4);
                float4 o0, o1;
                o0.x = acc2[i][0] + ba.x + xv0.x; o0.y = acc2[i][1] + ba.y + xv0.y;
                o0.z = acc2[i][2] + ba.z + xv0.z; o0.w = acc2[i][3] + ba.w + xv0.w;
                o1.x = acc2[i][4] + bb.x + xv1.x; o1.y = acc2[i][5] + bb.y + xv1.y;
                o1.z = acc2[i][6] + bb.z + xv1.z; o1.w = acc2[i][7] + bb.w + xv1.w;
                *reinterpret_cast<float4*>(out_x + (size_t)row * 128 + c)     = o0;
                *reinterpret_cast<float4*>(out_x + (size_t)row * 128 + c + 4) = o1;
            }
        }
    }
}

// ---------------- launch ------------------------------------------------------
extern "C" void kernel_launch(void* const* d_in, const int* in_sizes, int n_in,
                              void* d_out, int out_size)
{
    const float*     x     = (const float*)d_in[0];
    const float*     pos   = (const float*)d_in[1];
    const void*      ei    = d_in[2];
    const float*     ea    = (const float*)d_in[3];
    const float*     e_w1  = (const float*)d_in[4];
    const float*     e_b1  = (const float*)d_in[5];
    const float*     e_g1  = (const float*)d_in[6];
    const float*     e_be1 = (const float*)d_in[7];
    const float*     e_w2  = (const float*)d_in[8];
    const float*     e_b2  = (const float*)d_in[9];
    const float*     e_g2  = (const float*)d_in[10];
    const float*     e_be2 = (const float*)d_in[11];
    const float*     n_w1  = (const float*)d_in[12];
    const float*     n_b1  = (const float*)d_in[13];
    const float*     n_g1  = (const float*)d_in[14];
    const float*     n_be1 = (const float*)d_in[15];
    const float*     n_w2  = (const float*)d_in[16];
    const float*     n_b2  = (const float*)d_in[17];
    const float*     c_w1  = (const float*)d_in[18];
    const float*     c_b1  = (const float*)d_in[19];
    const float*     c_w2  = (const float*)d_in[20];
    const float*     c_b2  = (const float*)d_in[21];

    float* out_x   = (float*)d_out;
    float* out_pos = (float*)d_out + (size_t)NN * FEAT;

    const int SMEM_PRE  = (16384 + 16896) * 4;
    const int SMEM_NODE = (16384 + 16896 + 512) * 4;

    cudaFuncSetAttribute(preab_kernel, cudaFuncAttributeMaxDynamicSharedMemorySize, SMEM_PRE);
    cudaFuncSetAttribute(edge_kernel,  cudaFuncAttributeMaxDynamicSharedMemorySize, EDGE_SMEM);
    cudaFuncSetAttribute(node_kernel,  cudaFuncAttributeMaxDynamicSharedMemorySize, SMEM_NODE);

    conv_idx_kernel<<<256, 256>>>(ei);
    init_kernel<<<256, 256>>>(pos, out_pos);
    preab_kernel<<<(NN + 127) / 128, 256, SMEM_PRE>>>(x, e_w1);
    edge_kernel<<<148, 256, EDGE_SMEM>>>(pos, ea,
                                         e_w1, e_b1, e_g1, e_be1,
                                         e_w2, e_b2, e_g2, e_be2,
                                         c_w1, c_b1, c_w2, c_b2,
                                         out_pos);
    node_kernel<<<(NN + 127) / 128, 256, SMEM_NODE>>>(x, n_w1, n_b1, n_g1, n_be1,
                                                      n_w2, n_b2, out_x);
}

// round 6
// speedup vs baseline: 1.9426x; 1.2332x over previous
#include <cuda_runtime.h>
#include <cstdint>

#define NN   50000
#define EE   800000
#define FEAT 128
#define HID  128
#define EPSL 1e-5f
#define HSS  132          // padded smem row stride (floats) for SIMT kernels

#define ASTR 132          // edge A-tile stride (floats)
#define BSTR 136          // edge weight-tile stride (floats)

// ---------------- scratch (device globals) -----------------------------------
__device__ float g_A[NN * FEAT];      // x @ Wa   (e_w1 rows   0..127)
__device__ float g_B[NN * FEAT];      // x @ Wb   (e_w1 rows 128..255)
__device__ float g_aggm[NN * HID];    // segment-sum of m_ij
__device__ int   g_src[EE];
__device__ int   g_dst[EE];

__device__ __forceinline__ float silu_f(float v) { return v / (1.0f + expf(-v)); }
__device__ __forceinline__ uint32_t f2tf32(float f) {
    uint32_t r; asm("cvt.rna.tf32.f32 %0, %1;" : "=r"(r) : "f"(f)); return r;
}
__device__ __forceinline__ void mma8(float* d, const uint32_t* a, const uint32_t* b) {
    asm volatile("mma.sync.aligned.m16n8k8.row.col.f32.tf32.tf32.f32 "
                 "{%0,%1,%2,%3}, {%4,%5,%6,%7}, {%8,%9}, {%0,%1,%2,%3};"
                 : "+f"(d[0]), "+f"(d[1]), "+f"(d[2]), "+f"(d[3])
                 : "r"(a[0]), "r"(a[1]), "r"(a[2]), "r"(a[3]), "r"(b[0]), "r"(b[1]));
}

// ======================= SIMT gemm helpers (preab/node) =======================
__device__ __forceinline__ void gemm128(const float* __restrict__ As,
                                        const float* __restrict__ Bs,
                                        float acc[8][8], int ty, int tx)
{
#pragma unroll 1
    for (int k = 0; k < 128; k += 4) {
        float4 av[8];
#pragma unroll
        for (int i = 0; i < 8; i++)
            av[i] = *reinterpret_cast<const float4*>(As + (ty * 8 + i) * HSS + k);
#pragma unroll
        for (int kk = 0; kk < 4; kk++) {
            float4 b0 = *reinterpret_cast<const float4*>(Bs + (k + kk) * 128 + tx * 8);
            float4 b1 = *reinterpret_cast<const float4*>(Bs + (k + kk) * 128 + tx * 8 + 4);
#pragma unroll
            for (int i = 0; i < 8; i++) {
                float a = (kk == 0) ? av[i].x : (kk == 1) ? av[i].y : (kk == 2) ? av[i].z : av[i].w;
                acc[i][0] += a * b0.x; acc[i][1] += a * b0.y;
                acc[i][2] += a * b0.z; acc[i][3] += a * b0.w;
                acc[i][4] += a * b1.x; acc[i][5] += a * b1.y;
                acc[i][6] += a * b1.z; acc[i][7] += a * b1.w;
            }
        }
    }
}

__device__ __forceinline__ void ln_rows(float* __restrict__ hs,
                                        const float* __restrict__ g,
                                        const float* __restrict__ be,
                                        int warp, int lane)
{
    int k = lane * 4;
    float4 gv  = *reinterpret_cast<const float4*>(g  + k);
    float4 bev = *reinterpret_cast<const float4*>(be + k);
#pragma unroll 1
    for (int r = 0; r < 16; r++) {
        int row = warp * 16 + r;
        float4 v = *reinterpret_cast<float4*>(hs + row * HSS + k);
        float s = v.x + v.y + v.z + v.w;
        float q = v.x * v.x + v.y * v.y + v.z * v.z + v.w * v.w;
#pragma unroll
        for (int off = 16; off > 0; off >>= 1) {
            s += __shfl_xor_sync(0xffffffffu, s, off);
            q += __shfl_xor_sync(0xffffffffu, q, off);
        }
        float mu  = s * (1.0f / 128.0f);
        float var = q * (1.0f / 128.0f) - mu * mu;
        float rs  = rsqrtf(var + EPSL);
        v.x = (v.x - mu) * rs * gv.x + bev.x;
        v.y = (v.y - mu) * rs * gv.y + bev.y;
        v.z = (v.z - mu) * rs * gv.z + bev.z;
        v.w = (v.w - mu) * rs * gv.w + bev.w;
        *reinterpret_cast<float4*>(hs + row * HSS + k) = v;
    }
}

// ---------------- K-1: normalize edge_index dtype ----------------------------
__global__ void conv_idx_kernel(const void* __restrict__ ei_raw)
{
    const long long* e64 = (const long long*)ei_raw;
    const int*       e32 = (const int*)ei_raw;
    bool is64 = true;
#pragma unroll
    for (int j = 0; j < 8; j++) {
        long long v = e64[j];
        if (v < 0 || v >= NN) is64 = false;
    }
    int i = blockIdx.x * blockDim.x + threadIdx.x;
    int stride = gridDim.x * blockDim.x;
    if (is64) {
        for (int e = i; e < EE; e += stride) {
            g_src[e] = (int)e64[e];
            g_dst[e] = (int)e64[EE + e];
        }
    } else {
        for (int e = i; e < EE; e += stride) {
            g_src[e] = e32[e];
            g_dst[e] = e32[EE + e];
        }
    }
}

// ---------------- K0: zero agg_m, pos_out = pos ------------------------------
__global__ void init_kernel(const float* __restrict__ pos, float* __restrict__ out_pos)
{
    int i = blockIdx.x * blockDim.x + threadIdx.x;
    int stride = gridDim.x * blockDim.x;
    for (int j = i; j < NN * HID; j += stride) g_aggm[j] = 0.0f;
    for (int j = i; j < NN * 3;   j += stride) out_pos[j] = pos[j];
}

// ---------------- K1: A = x@Wa, B = x@Wb -------------------------------------
__global__ __launch_bounds__(256, 1)
void preab_kernel(const float* __restrict__ x, const float* __restrict__ e_w1)
{
    extern __shared__ float sm[];
    float* Bs = sm;
    float* hs = sm + 16384;
    int tid = threadIdx.x, ty = tid >> 4, tx = tid & 15;
    int n0 = blockIdx.x * 128;

    for (int idx = tid; idx < 128 * 32; idx += 256) {
        int row = idx >> 5, q = idx & 31;
        float4 v = make_float4(0.f, 0.f, 0.f, 0.f);
        if (n0 + row < NN)
            v = *reinterpret_cast<const float4*>(x + (size_t)(n0 + row) * 128 + q * 4);
        *reinterpret_cast<float4*>(hs + row * HSS + q * 4) = v;
    }
    for (int i = tid; i < 4096; i += 256)
        reinterpret_cast<float4*>(Bs)[i] = reinterpret_cast<const float4*>(e_w1)[i];
    __syncthreads();

    float acc[8][8];
#pragma unroll
    for (int i = 0; i < 8; i++)
#pragma unroll
        for (int j = 0; j < 8; j++) acc[i][j] = 0.f;
    gemm128(hs, Bs, acc, ty, tx);
#pragma unroll
    for (int i = 0; i < 8; i++) {
        int row = n0 + ty * 8 + i;
        if (row < NN) {
            *reinterpret_cast<float4*>(g_A + (size_t)row * 128 + tx * 8) =
                make_float4(acc[i][0], acc[i][1], acc[i][2], acc[i][3]);
            *reinterpret_cast<float4*>(g_A + (size_t)row * 128 + tx * 8 + 4) =
                make_float4(acc[i][4], acc[i][5], acc[i][6], acc[i][7]);
        }
    }
    __syncthreads();
    for (int i = tid; i < 4096; i += 256)
        reinterpret_cast<float4*>(Bs)[i] = reinterpret_cast<const float4*>(e_w1 + 16384)[i];
    __syncthreads();
#pragma unroll
    for (int i = 0; i < 8; i++)
#pragma unroll
        for (int j = 0; j < 8; j++) acc[i][j] = 0.f;
    gemm128(hs, Bs, acc, ty, tx);
#pragma unroll
    for (int i = 0; i < 8; i++) {
        int row = n0 + ty * 8 + i;
        if (row < NN) {
            *reinterpret_cast<float4*>(g_B + (size_t)row * 128 + tx * 8) =
                make_float4(acc[i][0], acc[i][1], acc[i][2], acc[i][3]);
            *reinterpret_cast<float4*>(g_B + (size_t)row * 128 + tx * 8 + 4) =
                make_float4(acc[i][4], acc[i][5], acc[i][6], acc[i][7]);
        }
    }
}

// ---------------- K2: persistent edge kernel (mma.sync tf32, 512 thr) --------
// smem float layout
#define EO_A    0                       // 128*ASTR = 16896
#define EO_B1   16896                   // 128*BSTR = 17408
#define EO_B2   34304
#define EO_SV   51712
// sv float indices (relative to sv)
#define SV_WC0  0
#define SV_WC1  128
#define SV_WD   256
#define SV_B1   384
#define SV_U1   512
#define SV_VB1  640
#define SV_G2   768
#define SV_BE2  896
#define SV_U2   1024
#define SV_VB2  1152
#define SV_CW2  1280
#define SV_RELX 1408
#define SV_RELY 1536
#define SV_RELZ 1664
#define SV_R2   1792
#define SV_EA0  1920
#define SV_EA1  2048
#define SV_MU1  2176
#define SV_RS1  2304
#define SV_MU2  2432
#define SV_RS2  2560
#define SV_SUM  2688   // [128][4]
#define SV_SQ   3200   // [128][4]
#define SV_IDX  3712   // ints: 128 dst, 128 src
#define SV_FLOATS 3968
#define EDGE_SMEM ((EO_SV + SV_FLOATS) * 4)   // 222720 bytes

// per-warp tf32 GEMM: C[32x32] += A[32x128] * B[128x32]
__device__ __forceinline__ void warp_gemm_tf32(const uint32_t* __restrict__ Au,
                                               const uint32_t* __restrict__ Bu,
                                               float c[2][4][4],
                                               int mbase, int nbase, int g, int t)
{
#pragma unroll 1
    for (int ks = 0; ks < 16; ks++) {
        int kk = ks * 8;
        uint32_t af[2][4];
#pragma unroll
        for (int mt = 0; mt < 2; mt++) {
            const uint32_t* p = Au + (mbase + mt * 16 + g) * ASTR + kk + t;
            af[mt][0] = p[0];
            af[mt][1] = p[8 * ASTR];
            af[mt][2] = p[4];
            af[mt][3] = p[8 * ASTR + 4];
        }
        uint32_t bf[4][2];
#pragma unroll
        for (int nt = 0; nt < 4; nt++) {
            const uint32_t* p = Bu + (kk + t) * BSTR + nbase + nt * 8 + g;
            bf[nt][0] = p[0];
            bf[nt][1] = p[4 * BSTR];
        }
#pragma unroll
        for (int mt = 0; mt < 2; mt++)
#pragma unroll
            for (int nt = 0; nt < 4; nt++)
                mma8(c[mt][nt], af[mt], bf[nt]);
    }
}

__global__ __launch_bounds__(512, 1)
void edge_kernel(const float* __restrict__ pos,
                 const float* __restrict__ ea,
                 const float* __restrict__ e_w1, const float* __restrict__ e_b1,
                 const float* __restrict__ e_g1, const float* __restrict__ e_be1,
                 const float* __restrict__ e_w2, const float* __restrict__ e_b2,
                 const float* __restrict__ e_g2, const float* __restrict__ e_be2,
                 const float* __restrict__ c_w1, const float* __restrict__ c_b1,
                 const float* __restrict__ c_w2, const float* __restrict__ c_b2,
                 float* __restrict__ out_pos)
{
    extern __shared__ float sm[];
    float* As  = sm + EO_A;
    float* B1s = sm + EO_B1;
    float* B2s = sm + EO_B2;
    float* sv  = sm + EO_SV;
    int*   sdst = (int*)(sv + SV_IDX);
    int*   ssrc = sdst + 128;
    const uint32_t* Au  = (const uint32_t*)As;
    const uint32_t* B1u = (const uint32_t*)B1s;
    const uint32_t* B2u = (const uint32_t*)B2s;

    int tid = threadIdx.x, warp = tid >> 5, lane = tid & 31;
    int g = lane >> 2, t = lane & 3;
    int wm = warp >> 2, wn = warp & 3;
    int mbase = wm * 32, nbase = wn * 32;

    // ---- stage LN-folded weights (tf32) + small vectors ----
    for (int idx = tid; idx < 16384; idx += 512) {
        int k = idx >> 7, n = idx & 127;
        B1s[k * BSTR + n] = __uint_as_float(f2tf32(e_g1[k] * e_w2[k * 128 + n]));
        B2s[k * BSTR + n] = __uint_as_float(f2tf32(e_g2[k] * c_w1[k * 128 + n]));
    }
    if (tid < 128) {
        sv[SV_WC0 + tid] = e_w1[256 * 128 + tid];
        sv[SV_WC1 + tid] = e_w1[257 * 128 + tid];
        sv[SV_WD  + tid] = e_w1[258 * 128 + tid];
        sv[SV_B1  + tid] = e_b1[tid];
        sv[SV_G2  + tid] = e_g2[tid];
        sv[SV_BE2 + tid] = e_be2[tid];
        sv[SV_CW2 + tid] = c_w2[tid];
    }
    {
        int quad = tid >> 7, n = tid & 127;
        float acc = 0.f;
        if (quad == 0) {
            for (int k = 0; k < 128; k++) acc += e_g1[k] * e_w2[k * 128 + n];
            sv[SV_U1 + n] = acc;
        } else if (quad == 1) {
            for (int k = 0; k < 128; k++) acc += e_be1[k] * e_w2[k * 128 + n];
            sv[SV_VB1 + n] = acc + e_b2[n];
        } else if (quad == 2) {
            for (int k = 0; k < 128; k++) acc += e_g2[k] * c_w1[k * 128 + n];
            sv[SV_U2 + n] = acc;
        } else {
            for (int k = 0; k < 128; k++) acc += e_be2[k] * c_w1[k * 128 + n];
            sv[SV_VB2 + n] = acc + c_b1[n];
        }
    }
    float cb2 = c_b2[0];
    __syncthreads();

    // per-thread layer-1 constants (lane-sliced float4)
    int k4 = lane * 4;
    float4 wc0 = *(const float4*)(sv + SV_WC0 + k4);
    float4 wc1 = *(const float4*)(sv + SV_WC1 + k4);
    float4 wdv = *(const float4*)(sv + SV_WD  + k4);
    float4 b1v = *(const float4*)(sv + SV_B1  + k4);

    const int ntiles = EE / 128;
    for (int tile = blockIdx.x; tile < ntiles; tile += gridDim.x) {
        int e0 = tile * 128;
        // ---- stage edge meta ----
        if (tid < 128) {
            int e = e0 + tid;
            int si = g_src[e], di = g_dst[e];
            float rx = pos[di * 3 + 0] - pos[si * 3 + 0];
            float ry = pos[di * 3 + 1] - pos[si * 3 + 1];
            float rz = pos[di * 3 + 2] - pos[si * 3 + 2];
            ssrc[tid] = si; sdst[tid] = di;
            sv[SV_RELX + tid] = rx; sv[SV_RELY + tid] = ry; sv[SV_RELZ + tid] = rz;
            sv[SV_R2 + tid]  = rx * rx + ry * ry + rz * rz;
            sv[SV_EA0 + tid] = ea[2 * e];
            sv[SV_EA1 + tid] = ea[2 * e + 1];
        }
        __syncthreads();

        // ---- layer-1: gather + SiLU -> As (raw h, tf32); row stats to smem ----
#pragma unroll 1
        for (int r = 0; r < 8; r++) {
            int row = warp * 8 + r;
            int si = ssrc[row], di = sdst[row];
            float4 a = *(const float4*)(g_A + (size_t)si * 128 + k4);
            float4 b = *(const float4*)(g_B + (size_t)di * 128 + k4);
            float e0v = sv[SV_EA0 + row], e1v = sv[SV_EA1 + row], r2v = sv[SV_R2 + row];
            float4 o;
            o.x = silu_f(a.x + b.x + e0v * wc0.x + e1v * wc1.x + r2v * wdv.x + b1v.x);
            o.y = silu_f(a.y + b.y + e0v * wc0.y + e1v * wc1.y + r2v * wdv.y + b1v.y);
            o.z = silu_f(a.z + b.z + e0v * wc0.z + e1v * wc1.z + r2v * wdv.z + b1v.z);
            o.w = silu_f(a.w + b.w + e0v * wc0.w + e1v * wc1.w + r2v * wdv.w + b1v.w);
            float s = o.x + o.y + o.z + o.w;
            float q = o.x * o.x + o.y * o.y + o.z * o.z + o.w * o.w;
#pragma unroll
            for (int off = 16; off > 0; off >>= 1) {
                s += __shfl_xor_sync(0xffffffffu, s, off);
                q += __shfl_xor_sync(0xffffffffu, q, off);
            }
            uint4 tv;
            tv.x = f2tf32(o.x); tv.y = f2tf32(o.y);
            tv.z = f2tf32(o.z); tv.w = f2tf32(o.w);
            *(uint4*)(As + row * ASTR + k4) = tv;
            if (lane == 0) {
                float mu = s * (1.0f / 128.0f);
                sv[SV_MU1 + row] = mu;
                sv[SV_RS1 + row] = rsqrtf(q * (1.0f / 128.0f) - mu * mu + EPSL);
            }
        }
        __syncthreads();

        // ---- GEMM1: h @ (g1 ∘ e_w2) ----
        float c[2][4][4];
#pragma unroll
        for (int mt = 0; mt < 2; mt++)
#pragma unroll
            for (int nt = 0; nt < 4; nt++)
#pragma unroll
                for (int j = 0; j < 4; j++) c[mt][nt][j] = 0.f;
        warp_gemm_tf32(Au, B1u, c, mbase, nbase, g, t);
        __syncthreads();   // all warps done reading As before z rewrite

        // ---- ep1: y = rs1*(d - mu1*u1) + vb1 ; z = silu(y) -> As + stats ----
#pragma unroll
        for (int mt = 0; mt < 2; mt++) {
            int r0 = mbase + mt * 16 + g, r1 = r0 + 8;
            float rsA = sv[SV_RS1 + r0], bA = rsA * sv[SV_MU1 + r0];
            float rsB = sv[SV_RS1 + r1], bB = rsB * sv[SV_MU1 + r1];
            float s0 = 0.f, q0 = 0.f, s1 = 0.f, q1 = 0.f;
#pragma unroll
            for (int nt = 0; nt < 4; nt++) {
                int c0 = nbase + nt * 8 + 2 * t;
                float u1a = sv[SV_U1 + c0],  u1b = sv[SV_U1 + c0 + 1];
                float vba = sv[SV_VB1 + c0], vbb = sv[SV_VB1 + c0 + 1];
                float z0 = silu_f(rsA * c[mt][nt][0] - bA * u1a + vba);
                float z1 = silu_f(rsA * c[mt][nt][1] - bA * u1b + vbb);
                float z2 = silu_f(rsB * c[mt][nt][2] - bB * u1a + vba);
                float z3 = silu_f(rsB * c[mt][nt][3] - bB * u1b + vbb);
                c[mt][nt][0] = z0; c[mt][nt][1] = z1; c[mt][nt][2] = z2; c[mt][nt][3] = z3;
                uint2 p0; p0.x = f2tf32(z0); p0.y = f2tf32(z1);
                uint2 p1; p1.x = f2tf32(z2); p1.y = f2tf32(z3);
                *(uint2*)(As + r0 * ASTR + c0) = p0;
                *(uint2*)(As + r1 * ASTR + c0) = p1;
                s0 += z0 + z1; q0 += z0 * z0 + z1 * z1;
                s1 += z2 + z3; q1 += z2 * z2 + z3 * z3;
            }
#pragma unroll
            for (int off = 1; off <= 2; off <<= 1) {
                s0 += __shfl_xor_sync(0xffffffffu, s0, off);
                s1 += __shfl_xor_sync(0xffffffffu, s1, off);
                q0 += __shfl_xor_sync(0xffffffffu, q0, off);
                q1 += __shfl_xor_sync(0xffffffffu, q1, off);
            }
            if (t == 0) {
                sv[SV_SUM + r0 * 4 + wn] = s0;
                sv[SV_SQ  + r0 * 4 + wn] = q0;
                sv[SV_SUM + r1 * 4 + wn] = s1;
                sv[SV_SQ  + r1 * 4 + wn] = q1;
            }
        }
        __syncthreads();
        if (tid < 128) {
            float s = sv[SV_SUM + tid * 4] + sv[SV_SUM + tid * 4 + 1]
                    + sv[SV_SUM + tid * 4 + 2] + sv[SV_SUM + tid * 4 + 3];
            float q = sv[SV_SQ + tid * 4] + sv[SV_SQ + tid * 4 + 1]
                    + sv[SV_SQ + tid * 4 + 2] + sv[SV_SQ + tid * 4 + 3];
            float mu = s * (1.0f / 128.0f);
            sv[SV_MU2 + tid] = mu;
            sv[SV_RS2 + tid] = rsqrtf(q * (1.0f / 128.0f) - mu * mu + EPSL);
        }
        __syncthreads();

        // ---- aggm atomics: m = (z - mu2)*rs2*g2 + be2 ----
#pragma unroll
        for (int mt = 0; mt < 2; mt++) {
            int r0 = mbase + mt * 16 + g, r1 = r0 + 8;
            float mu0 = sv[SV_MU2 + r0], rs0 = sv[SV_RS2 + r0];
            float mu1 = sv[SV_MU2 + r1], rs1 = sv[SV_RS2 + r1];
            int d0 = sdst[r0], d1 = sdst[r1];
#pragma unroll
            for (int nt = 0; nt < 4; nt++) {
                int c0 = nbase + nt * 8 + 2 * t;
                float g2a = sv[SV_G2 + c0],  g2b = sv[SV_G2 + c0 + 1];
                float bea = sv[SV_BE2 + c0], beb = sv[SV_BE2 + c0 + 1];
                float m0 = (c[mt][nt][0] - mu0) * rs0 * g2a + bea;
                float m1 = (c[mt][nt][1] - mu0) * rs0 * g2b + beb;
                float m2 = (c[mt][nt][2] - mu1) * rs1 * g2a + bea;
                float m3 = (c[mt][nt][3] - mu1) * rs1 * g2b + beb;
                asm volatile("red.global.add.v2.f32 [%0], {%1, %2};"
                             :: "l"(g_aggm + (size_t)d0 * 128 + c0), "f"(m0), "f"(m1) : "memory");
                asm volatile("red.global.add.v2.f32 [%0], {%1, %2};"
                             :: "l"(g_aggm + (size_t)d1 * 128 + c0), "f"(m2), "f"(m3) : "memory");
            }
        }

        // ---- GEMM2: z @ (g2 ∘ c_w1) ----
#pragma unroll
        for (int mt = 0; mt < 2; mt++)
#pragma unroll
            for (int nt = 0; nt < 4; nt++)
#pragma unroll
                for (int j = 0; j < 4; j++) c[mt][nt][j] = 0.f;
        warp_gemm_tf32(Au, B2u, c, mbase, nbase, g, t);

        // ---- ep2: val = rs2*(d - mu2*u2) + vb2 ; coef partials ----
#pragma unroll
        for (int mt = 0; mt < 2; mt++) {
            int r0 = mbase + mt * 16 + g, r1 = r0 + 8;
            float rs0 = sv[SV_RS2 + r0], b0 = rs0 * sv[SV_MU2 + r0];
            float rs1 = sv[SV_RS2 + r1], b1 = rs1 * sv[SV_MU2 + r1];
            float p0 = 0.f, p1 = 0.f;
#pragma unroll
            for (int nt = 0; nt < 4; nt++) {
                int c0 = nbase + nt * 8 + 2 * t;
                float u2a = sv[SV_U2 + c0],  u2b = sv[SV_U2 + c0 + 1];
                float vba = sv[SV_VB2 + c0], vbb = sv[SV_VB2 + c0 + 1];
                float wa  = sv[SV_CW2 + c0], wb  = sv[SV_CW2 + c0 + 1];
                p0 += silu_f(rs0 * c[mt][nt][0] - b0 * u2a + vba) * wa
                    + silu_f(rs0 * c[mt][nt][1] - b0 * u2b + vbb) * wb;
                p1 += silu_f(rs1 * c[mt][nt][2] - b1 * u2a + vba) * wa
                    + silu_f(rs1 * c[mt][nt][3] - b1 * u2b + vbb) * wb;
            }
#pragma unroll
            for (int off = 1; off <= 2; off <<= 1) {
                p0 += __shfl_xor_sync(0xffffffffu, p0, off);
                p1 += __shfl_xor_sync(0xffffffffu, p1, off);
            }
            if (t == 0) {
                sv[SV_SUM + r0 * 4 + wn] = p0;
                sv[SV_SUM + r1 * 4 + wn] = p1;
            }
        }
        __syncthreads();
        if (tid < 128) {
            float coef = sv[SV_SUM + tid * 4] + sv[SV_SUM + tid * 4 + 1]
                       + sv[SV_SUM + tid * 4 + 2] + sv[SV_SUM + tid * 4 + 3] + cb2;
            int di = sdst[tid];
            atomicAdd(&out_pos[di * 3 + 0], sv[SV_RELX + tid] * coef);
            atomicAdd(&out_pos[di * 3 + 1], sv[SV_RELY + tid] * coef);
            atomicAdd(&out_pos[di * 3 + 2], sv[SV_RELZ + tid] * coef);
        }
        __syncthreads();
    }
}

// ---------------- K3: node MLP + residual ------------------------------------
__global__ __launch_bounds__(256, 1)
void node_kernel(const float* __restrict__ x,
                 const float* __restrict__ n_w1, const float* __restrict__ n_b1,
                 const float* __restrict__ n_g1, const float* __restrict__ n_be1,
                 const float* __restrict__ n_w2, const float* __restrict__ n_b2,
                 float* __restrict__ out_x)
{
    extern __shared__ float smf[];
    float* Bs = smf;
    float* hs = smf + 16384;
    float* sv = hs + 16896;
    int tid = threadIdx.x, ty = tid >> 4, tx = tid & 15, warp = tid >> 5, lane = tid & 31;
    int n0 = blockIdx.x * 128;

    if (tid < 128) {
        sv[tid]       = n_b1[tid];
        sv[128 + tid] = n_g1[tid];
        sv[256 + tid] = n_be1[tid];
        sv[384 + tid] = n_b2[tid];
    }

    for (int idx = tid; idx < 128 * 32; idx += 256) {
        int row = idx >> 5, q = idx & 31;
        float4 v = make_float4(0.f, 0.f, 0.f, 0.f);
        if (n0 + row < NN)
            v = *reinterpret_cast<const float4*>(x + (size_t)(n0 + row) * 128 + q * 4);
        *reinterpret_cast<float4*>(hs + row * HSS + q * 4) = v;
    }
    for (int i = tid; i < 4096; i += 256)
        reinterpret_cast<float4*>(Bs)[i] = reinterpret_cast<const float4*>(n_w1)[i];
    __syncthreads();

    float acc[8][8];
#pragma unroll
    for (int i = 0; i < 8; i++)
#pragma unroll
        for (int j = 0; j < 8; j++) acc[i][j] = 0.f;
    gemm128(hs, Bs, acc, ty, tx);
    __syncthreads();

    for (int idx = tid; idx < 128 * 32; idx += 256) {
        int row = idx >> 5, q = idx & 31;
        float4 v = make_float4(0.f, 0.f, 0.f, 0.f);
        if (n0 + row < NN)
            v = *reinterpret_cast<const float4*>(g_aggm + (size_t)(n0 + row) * 128 + q * 4);
        *reinterpret_cast<float4*>(hs + row * HSS + q * 4) = v;
    }
    for (int i = tid; i < 4096; i += 256)
        reinterpret_cast<float4*>(Bs)[i] = reinterpret_cast<const float4*>(n_w1 + 16384)[i];
    __syncthreads();
    gemm128(hs, Bs, acc, ty, tx);
    __syncthreads();

    {
        int c = tx * 8;
        float4 ba = *reinterpret_cast<const float4*>(sv + c);
        float4 bb = *reinterpret_cast<const float4*>(sv + c + 4);
#pragma unroll
        for (int i = 0; i < 8; i++) {
            int row = ty * 8 + i;
            float4 v0, v1;
            v0.x = silu_f(acc[i][0] + ba.x); v0.y = silu_f(acc[i][1] + ba.y);
            v0.z = silu_f(acc[i][2] + ba.z); v0.w = silu_f(acc[i][3] + ba.w);
            v1.x = silu_f(acc[i][4] + bb.x); v1.y = silu_f(acc[i][5] + bb.y);
            v1.z = silu_f(acc[i][6] + bb.z); v1.w = silu_f(acc[i][7] + bb.w);
            *reinterpret_cast<float4*>(hs + row * HSS + c)     = v0;
            *reinterpret_cast<float4*>(hs + row * HSS + c + 4) = v1;
        }
    }
    __syncthreads();
    ln_rows(hs, sv + 128, sv + 256, warp, lane);
    __syncthreads();

    for (int i = tid; i < 4096; i += 256)
        reinterpret_cast<float4*>(Bs)[i] = reinterpret_cast<const float4*>(n_w2)[i];
    __syncthreads();
    float acc2[8][8];
#pragma unroll
    for (int i = 0; i < 8; i++)
#pragma unroll
        for (int j = 0; j < 8; j++) acc2[i][j] = 0.f;
    gemm128(hs, Bs, acc2, ty, tx);

    {
        int c = tx * 8;
        float4 ba = *reinterpret_cast<const float4*>(sv + 384 + c);
        float4 bb = *reinterpret_cast<const float4*>(sv + 384 + c + 4);
#pragma unroll
        for (int i = 0; i < 8; i++) {
            int row = n0 + ty * 8 + i;
            if (row < NN) {
                float4 xv0 = *reinterpret_cast<const float4*>(x + (size_t)row * 128 + c);
                float4 xv1 = *reinterpret_cast<const float4*>(x + (size_t)row * 128 + c + 4);
                float4 o0, o1;
                o0.x = acc2[i][0] + ba.x + xv0.x; o0.y = acc2[i][1] + ba.y + xv0.y;
                o0.z = acc2[i][2] + ba.z + xv0.z; o0.w = acc2[i][3] + ba.w + xv0.w;
                o1.x = acc2[i][4] + bb.x + xv1.x; o1.y = acc2[i][5] + bb.y + xv1.y;
                o1.z = acc2[i][6] + bb.z + xv1.z; o1.w = acc2[i][7] + bb.w + xv1.w;
                *reinterpret_cast<float4*>(out_x + (size_t)row * 128 + c)     = o0;
                *reinterpret_cast<float4*>(out_x + (size_t)row * 128 + c + 4) = o1;
            }
        }
    }
}

// ---------------- launch ------------------------------------------------------
extern "C" void kernel_launch(void* const* d_in, const int* in_sizes, int n_in,
                              void* d_out, int out_size)
{
    const float*     x     = (const float*)d_in[0];
    const float*     pos   = (const float*)d_in[1];
    const void*      ei    = d_in[2];
    const float*     ea    = (const float*)d_in[3];
    const float*     e_w1  = (const float*)d_in[4];
    const float*     e_b1  = (const float*)d_in[5];
    const float*     e_g1  = (const float*)d_in[6];
    const float*     e_be1 = (const float*)d_in[7];
    const float*     e_w2  = (const float*)d_in[8];
    const float*     e_b2  = (const float*)d_in[9];
    const float*     e_g2  = (const float*)d_in[10];
    const float*     e_be2 = (const float*)d_in[11];
    const float*     n_w1  = (const float*)d_in[12];
    const float*     n_b1  = (const float*)d_in[13];
    const float*     n_g1  = (const float*)d_in[14];
    const float*     n_be1 = (const float*)d_in[15];
    const float*     n_w2  = (const float*)d_in[16];
    const float*     n_b2  = (const float*)d_in[17];
    const float*     c_w1  = (const float*)d_in[18];
    const float*     c_b1  = (const float*)d_in[19];
    const float*     c_w2  = (const float*)d_in[20];
    const float*     c_b2  = (const float*)d_in[21];

    float* out_x   = (float*)d_out;
    float* out_pos = (float*)d_out + (size_t)NN * FEAT;

    const int SMEM_PRE  = (16384 + 16896) * 4;
    const int SMEM_NODE = (16384 + 16896 + 512) * 4;

    cudaFuncSetAttribute(preab_kernel, cudaFuncAttributeMaxDynamicSharedMemorySize, SMEM_PRE);
    cudaFuncSetAttribute(edge_kernel,  cudaFuncAttributeMaxDynamicSharedMemorySize, EDGE_SMEM);
    cudaFuncSetAttribute(node_kernel,  cudaFuncAttributeMaxDynamicSharedMemorySize, SMEM_NODE);

    conv_idx_kernel<<<256, 256>>>(ei);
    init_kernel<<<256, 256>>>(pos, out_pos);
    preab_kernel<<<(NN + 127) / 128, 256, SMEM_PRE>>>(x, e_w1);
    edge_kernel<<<148, 512, EDGE_SMEM>>>(pos, ea,
                                         e_w1, e_b1, e_g1, e_be1,
                                         e_w2, e_b2, e_g2, e_be2,
                                         c_w1, c_b1, c_w2, c_b2,
                                         out_pos);
    node_kernel<<<(NN + 127) / 128, 256, SMEM_NODE>>>(x, n_w1, n_b1, n_g1, n_be1,
                                                      n_w2, n_b2, out_x);
}

// round 7
// speedup vs baseline: 1.9853x; 1.0219x over previous
#include <cuda_runtime.h>
#include <cstdint>

#define NN   50000
#define EE   800000
#define FEAT 128
#define HID  128
#define EPSL 1e-5f
#define HSS  132          // padded smem row stride (floats) for SIMT kernels

#define ASTR 132          // edge A-tile stride (floats)
#define BSTR 136          // edge weight-tile stride (floats)

// ---------------- scratch (device globals) -----------------------------------
__device__ float g_A[NN * FEAT];      // x @ Wa   (e_w1 rows   0..127)
__device__ float g_B[NN * FEAT];      // x @ Wb   (e_w1 rows 128..255)
__device__ float g_aggm[NN * HID];    // segment-sum of m_ij
__device__ int   g_src[EE];
__device__ int   g_dst[EE];

__device__ __forceinline__ float silu_f(float v) { return v / (1.0f + expf(-v)); }
__device__ __forceinline__ uint32_t f2tf32(float f) {
    uint32_t r; asm("cvt.rna.tf32.f32 %0, %1;" : "=r"(r) : "f"(f)); return r;
}
__device__ __forceinline__ void mma8(float* d, const uint32_t* a, const uint32_t* b) {
    asm volatile("mma.sync.aligned.m16n8k8.row.col.f32.tf32.tf32.f32 "
                 "{%0,%1,%2,%3}, {%4,%5,%6,%7}, {%8,%9}, {%0,%1,%2,%3};"
                 : "+f"(d[0]), "+f"(d[1]), "+f"(d[2]), "+f"(d[3])
                 : "r"(a[0]), "r"(a[1]), "r"(a[2]), "r"(a[3]), "r"(b[0]), "r"(b[1]));
}

// ======================= SIMT gemm helpers (preab/node) =======================
__device__ __forceinline__ void gemm128(const float* __restrict__ As,
                                        const float* __restrict__ Bs,
                                        float acc[8][8], int ty, int tx)
{
#pragma unroll 1
    for (int k = 0; k < 128; k += 4) {
        float4 av[8];
#pragma unroll
        for (int i = 0; i < 8; i++)
            av[i] = *reinterpret_cast<const float4*>(As + (ty * 8 + i) * HSS + k);
#pragma unroll
        for (int kk = 0; kk < 4; kk++) {
            float4 b0 = *reinterpret_cast<const float4*>(Bs + (k + kk) * 128 + tx * 8);
            float4 b1 = *reinterpret_cast<const float4*>(Bs + (k + kk) * 128 + tx * 8 + 4);
#pragma unroll
            for (int i = 0; i < 8; i++) {
                float a = (kk == 0) ? av[i].x : (kk == 1) ? av[i].y : (kk == 2) ? av[i].z : av[i].w;
                acc[i][0] += a * b0.x; acc[i][1] += a * b0.y;
                acc[i][2] += a * b0.z; acc[i][3] += a * b0.w;
                acc[i][4] += a * b1.x; acc[i][5] += a * b1.y;
                acc[i][6] += a * b1.z; acc[i][7] += a * b1.w;
            }
        }
    }
}

__device__ __forceinline__ void ln_rows(float* __restrict__ hs,
                                        const float* __restrict__ g,
                                        const float* __restrict__ be,
                                        int warp, int lane)
{
    int k = lane * 4;
    float4 gv  = *reinterpret_cast<const float4*>(g  + k);
    float4 bev = *reinterpret_cast<const float4*>(be + k);
#pragma unroll 1
    for (int r = 0; r < 16; r++) {
        int row = warp * 16 + r;
        float4 v = *reinterpret_cast<float4*>(hs + row * HSS + k);
        float s = v.x + v.y + v.z + v.w;
        float q = v.x * v.x + v.y * v.y + v.z * v.z + v.w * v.w;
#pragma unroll
        for (int off = 16; off > 0; off >>= 1) {
            s += __shfl_xor_sync(0xffffffffu, s, off);
            q += __shfl_xor_sync(0xffffffffu, q, off);
        }
        float mu  = s * (1.0f / 128.0f);
        float var = q * (1.0f / 128.0f) - mu * mu;
        float rs  = rsqrtf(var + EPSL);
        v.x = (v.x - mu) * rs * gv.x + bev.x;
        v.y = (v.y - mu) * rs * gv.y + bev.y;
        v.z = (v.z - mu) * rs * gv.z + bev.z;
        v.w = (v.w - mu) * rs * gv.w + bev.w;
        *reinterpret_cast<float4*>(hs + row * HSS + k) = v;
    }
}

// ---------------- K-1: normalize edge_index dtype ----------------------------
__global__ void conv_idx_kernel(const void* __restrict__ ei_raw)
{
    const long long* e64 = (const long long*)ei_raw;
    const int*       e32 = (const int*)ei_raw;
    bool is64 = true;
#pragma unroll
    for (int j = 0; j < 8; j++) {
        long long v = e64[j];
        if (v < 0 || v >= NN) is64 = false;
    }
    int i = blockIdx.x * blockDim.x + threadIdx.x;
    int stride = gridDim.x * blockDim.x;
    if (is64) {
        for (int e = i; e < EE; e += stride) {
            g_src[e] = (int)e64[e];
            g_dst[e] = (int)e64[EE + e];
        }
    } else {
        for (int e = i; e < EE; e += stride) {
            g_src[e] = e32[e];
            g_dst[e] = e32[EE + e];
        }
    }
}

// ---------------- K0: zero agg_m, pos_out = pos ------------------------------
__global__ void init_kernel(const float* __restrict__ pos, float* __restrict__ out_pos)
{
    int i = blockIdx.x * blockDim.x + threadIdx.x;
    int stride = gridDim.x * blockDim.x;
    for (int j = i; j < NN * HID; j += stride) g_aggm[j] = 0.0f;
    for (int j = i; j < NN * 3;   j += stride) out_pos[j] = pos[j];
}

// ---------------- K1: A = x@Wa, B = x@Wb -------------------------------------
__global__ __launch_bounds__(256, 1)
void preab_kernel(const float* __restrict__ x, const float* __restrict__ e_w1)
{
    extern __shared__ float sm[];
    float* Bs = sm;
    float* hs = sm + 16384;
    int tid = threadIdx.x, ty = tid >> 4, tx = tid & 15;
    int n0 = blockIdx.x * 128;

    for (int idx = tid; idx < 128 * 32; idx += 256) {
        int row = idx >> 5, q = idx & 31;
        float4 v = make_float4(0.f, 0.f, 0.f, 0.f);
        if (n0 + row < NN)
            v = *reinterpret_cast<const float4*>(x + (size_t)(n0 + row) * 128 + q * 4);
        *reinterpret_cast<float4*>(hs + row * HSS + q * 4) = v;
    }
    for (int i = tid; i < 4096; i += 256)
        reinterpret_cast<float4*>(Bs)[i] = reinterpret_cast<const float4*>(e_w1)[i];
    __syncthreads();

    float acc[8][8];
#pragma unroll
    for (int i = 0; i < 8; i++)
#pragma unroll
        for (int j = 0; j < 8; j++) acc[i][j] = 0.f;
    gemm128(hs, Bs, acc, ty, tx);
#pragma unroll
    for (int i = 0; i < 8; i++) {
        int row = n0 + ty * 8 + i;
        if (row < NN) {
            *reinterpret_cast<float4*>(g_A + (size_t)row * 128 + tx * 8) =
                make_float4(acc[i][0], acc[i][1], acc[i][2], acc[i][3]);
            *reinterpret_cast<float4*>(g_A + (size_t)row * 128 + tx * 8 + 4) =
                make_float4(acc[i][4], acc[i][5], acc[i][6], acc[i][7]);
        }
    }
    __syncthreads();
    for (int i = tid; i < 4096; i += 256)
        reinterpret_cast<float4*>(Bs)[i] = reinterpret_cast<const float4*>(e_w1 + 16384)[i];
    __syncthreads();
#pragma unroll
    for (int i = 0; i < 8; i++)
#pragma unroll
        for (int j = 0; j < 8; j++) acc[i][j] = 0.f;
    gemm128(hs, Bs, acc, ty, tx);
#pragma unroll
    for (int i = 0; i < 8; i++) {
        int row = n0 + ty * 8 + i;
        if (row < NN) {
            *reinterpret_cast<float4*>(g_B + (size_t)row * 128 + tx * 8) =
                make_float4(acc[i][0], acc[i][1], acc[i][2], acc[i][3]);
            *reinterpret_cast<float4*>(g_B + (size_t)row * 128 + tx * 8 + 4) =
                make_float4(acc[i][4], acc[i][5], acc[i][6], acc[i][7]);
        }
    }
}

// ---------------- K2: persistent edge kernel (mma.sync tf32, 1024 thr) -------
// smem float layout
#define EO_A    0                       // 128*ASTR = 16896
#define EO_B1   16896                   // 128*BSTR = 17408
#define EO_B2   34304
#define EO_SV   51712
// sv float indices (relative to sv)
#define SV_WC0  0
#define SV_WC1  128
#define SV_WD   256
#define SV_B1   384
#define SV_U1   512
#define SV_VB1  640
#define SV_G2   768
#define SV_BE2  896
#define SV_U2   1024
#define SV_VB2  1152
#define SV_CW2  1280
#define SV_RELX 1408
#define SV_RELY 1536
#define SV_RELZ 1664
#define SV_R2   1792
#define SV_EA0  1920
#define SV_EA1  2048
#define SV_MU1  2176
#define SV_RS1  2304
#define SV_MU2  2432
#define SV_RS2  2560
#define SV_SUM  2688   // [128][4]
#define SV_SQ   3200   // [128][4]
#define SV_IDX  3712   // ints: 128 dst, 128 src
#define SV_FLOATS 3968
#define EDGE_SMEM ((EO_SV + SV_FLOATS) * 4)   // 222720 bytes

// per-warp tf32 GEMM: C[16x32] += A[16x128] * B[128x32]
__device__ __forceinline__ void warp_gemm_tf32(const uint32_t* __restrict__ Au,
                                               const uint32_t* __restrict__ Bu,
                                               float c[4][4],
                                               int mbase, int nbase, int g, int t)
{
#pragma unroll 1
    for (int ks = 0; ks < 16; ks++) {
        int kk = ks * 8;
        uint32_t af[4];
        {
            const uint32_t* p = Au + (mbase + g) * ASTR + kk + t;
            af[0] = p[0];
            af[1] = p[8 * ASTR];
            af[2] = p[4];
            af[3] = p[8 * ASTR + 4];
        }
        uint32_t bf[4][2];
#pragma unroll
        for (int nt = 0; nt < 4; nt++) {
            const uint32_t* p = Bu + (kk + t) * BSTR + nbase + nt * 8 + g;
            bf[nt][0] = p[0];
            bf[nt][1] = p[4 * BSTR];
        }
#pragma unroll
        for (int nt = 0; nt < 4; nt++)
            mma8(c[nt], af, bf[nt]);
    }
}

__global__ __launch_bounds__(1024, 1)
void edge_kernel(const float* __restrict__ pos,
                 const float* __restrict__ ea,
                 const float* __restrict__ e_w1, const float* __restrict__ e_b1,
                 const float* __restrict__ e_g1, const float* __restrict__ e_be1,
                 const float* __restrict__ e_w2, const float* __restrict__ e_b2,
                 const float* __restrict__ e_g2, const float* __restrict__ e_be2,
                 const float* __restrict__ c_w1, const float* __restrict__ c_b1,
                 const float* __restrict__ c_w2, const float* __restrict__ c_b2,
                 float* __restrict__ out_pos)
{
    extern __shared__ float sm[];
    float* As  = sm + EO_A;
    float* B1s = sm + EO_B1;
    float* B2s = sm + EO_B2;
    float* sv  = sm + EO_SV;
    int*   sdst = (int*)(sv + SV_IDX);
    int*   ssrc = sdst + 128;
    const uint32_t* Au  = (const uint32_t*)As;
    const uint32_t* B1u = (const uint32_t*)B1s;
    const uint32_t* B2u = (const uint32_t*)B2s;

    int tid = threadIdx.x, warp = tid >> 5, lane = tid & 31;
    int g = lane >> 2, t = lane & 3;
    int wm = warp >> 2, wn = warp & 3;
    int mbase = wm * 16, nbase = wn * 32;

    // ---- stage LN-folded weights (tf32) + small vectors ----
    for (int idx = tid; idx < 16384; idx += 1024) {
        int k = idx >> 7, n = idx & 127;
        B1s[k * BSTR + n] = __uint_as_float(f2tf32(e_g1[k] * e_w2[k * 128 + n]));
        B2s[k * BSTR + n] = __uint_as_float(f2tf32(e_g2[k] * c_w1[k * 128 + n]));
    }
    if (tid < 128) {
        sv[SV_WC0 + tid] = e_w1[256 * 128 + tid];
        sv[SV_WC1 + tid] = e_w1[257 * 128 + tid];
        sv[SV_WD  + tid] = e_w1[258 * 128 + tid];
        sv[SV_B1  + tid] = e_b1[tid];
        sv[SV_G2  + tid] = e_g2[tid];
        sv[SV_BE2 + tid] = e_be2[tid];
        sv[SV_CW2 + tid] = c_w2[tid];
    }
    if (tid < 512) {
        int quad = tid >> 7, n = tid & 127;
        float acc = 0.f;
        if (quad == 0) {
            for (int k = 0; k < 128; k++) acc += e_g1[k] * e_w2[k * 128 + n];
            sv[SV_U1 + n] = acc;
        } else if (quad == 1) {
            for (int k = 0; k < 128; k++) acc += e_be1[k] * e_w2[k * 128 + n];
            sv[SV_VB1 + n] = acc + e_b2[n];
        } else if (quad == 2) {
            for (int k = 0; k < 128; k++) acc += e_g2[k] * c_w1[k * 128 + n];
            sv[SV_U2 + n] = acc;
        } else {
            for (int k = 0; k < 128; k++) acc += e_be2[k] * c_w1[k * 128 + n];
            sv[SV_VB2 + n] = acc + c_b1[n];
        }
    }
    float cb2 = c_b2[0];
    __syncthreads();

    int k4 = lane * 4;

    const int ntiles = EE / 128;
    for (int tile = blockIdx.x; tile < ntiles; tile += gridDim.x) {
        int e0 = tile * 128;
        // ---- stage edge meta ----
        if (tid < 128) {
            int e = e0 + tid;
            int si = g_src[e], di = g_dst[e];
            float rx = pos[di * 3 + 0] - pos[si * 3 + 0];
            float ry = pos[di * 3 + 1] - pos[si * 3 + 1];
            float rz = pos[di * 3 + 2] - pos[si * 3 + 2];
            ssrc[tid] = si; sdst[tid] = di;
            sv[SV_RELX + tid] = rx; sv[SV_RELY + tid] = ry; sv[SV_RELZ + tid] = rz;
            sv[SV_R2 + tid]  = rx * rx + ry * ry + rz * rz;
            sv[SV_EA0 + tid] = ea[2 * e];
            sv[SV_EA1 + tid] = ea[2 * e + 1];
        }
        __syncthreads();

        // ---- layer-1: gather + SiLU -> As (raw h, tf32); row stats to smem ----
        {
            float4 wc0 = *(const float4*)(sv + SV_WC0 + k4);
            float4 wc1 = *(const float4*)(sv + SV_WC1 + k4);
            float4 wdv = *(const float4*)(sv + SV_WD  + k4);
            float4 b1v = *(const float4*)(sv + SV_B1  + k4);
#pragma unroll 1
            for (int r = 0; r < 4; r++) {
                int row = warp * 4 + r;
                int si = ssrc[row], di = sdst[row];
                float4 a = *(const float4*)(g_A + (size_t)si * 128 + k4);
                float4 b = *(const float4*)(g_B + (size_t)di * 128 + k4);
                float e0v = sv[SV_EA0 + row], e1v = sv[SV_EA1 + row], r2v = sv[SV_R2 + row];
                float4 o;
                o.x = silu_f(a.x + b.x + e0v * wc0.x + e1v * wc1.x + r2v * wdv.x + b1v.x);
                o.y = silu_f(a.y + b.y + e0v * wc0.y + e1v * wc1.y + r2v * wdv.y + b1v.y);
                o.z = silu_f(a.z + b.z + e0v * wc0.z + e1v * wc1.z + r2v * wdv.z + b1v.z);
                o.w = silu_f(a.w + b.w + e0v * wc0.w + e1v * wc1.w + r2v * wdv.w + b1v.w);
                float s = o.x + o.y + o.z + o.w;
                float q = o.x * o.x + o.y * o.y + o.z * o.z + o.w * o.w;
#pragma unroll
                for (int off = 16; off > 0; off >>= 1) {
                    s += __shfl_xor_sync(0xffffffffu, s, off);
                    q += __shfl_xor_sync(0xffffffffu, q, off);
                }
                uint4 tv;
                tv.x = f2tf32(o.x); tv.y = f2tf32(o.y);
                tv.z = f2tf32(o.z); tv.w = f2tf32(o.w);
                *(uint4*)(As + row * ASTR + k4) = tv;
                if (lane == 0) {
                    float mu = s * (1.0f / 128.0f);
                    sv[SV_MU1 + row] = mu;
                    sv[SV_RS1 + row] = rsqrtf(q * (1.0f / 128.0f) - mu * mu + EPSL);
                }
            }
        }
        __syncthreads();

        // ---- GEMM1: h @ (g1 ∘ e_w2) ----
        float c[4][4];
#pragma unroll
        for (int nt = 0; nt < 4; nt++)
#pragma unroll
            for (int j = 0; j < 4; j++) c[nt][j] = 0.f;
        warp_gemm_tf32(Au, B1u, c, mbase, nbase, g, t);
        __syncthreads();   // all warps done reading As before z rewrite

        // ---- ep1: y = rs1*(d - mu1*u1) + vb1 ; z = silu(y) -> As + stats ----
        {
            int r0 = mbase + g, r1 = r0 + 8;
            float rsA = sv[SV_RS1 + r0], bA = rsA * sv[SV_MU1 + r0];
            float rsB = sv[SV_RS1 + r1], bB = rsB * sv[SV_MU1 + r1];
            float s0 = 0.f, q0 = 0.f, s1 = 0.f, q1 = 0.f;
#pragma unroll
            for (int nt = 0; nt < 4; nt++) {
                int c0 = nbase + nt * 8 + 2 * t;
                float u1a = sv[SV_U1 + c0],  u1b = sv[SV_U1 + c0 + 1];
                float vba = sv[SV_VB1 + c0], vbb = sv[SV_VB1 + c0 + 1];
                float z0 = silu_f(rsA * c[nt][0] - bA * u1a + vba);
                float z1 = silu_f(rsA * c[nt][1] - bA * u1b + vbb);
                float z2 = silu_f(rsB * c[nt][2] - bB * u1a + vba);
                float z3 = silu_f(rsB * c[nt][3] - bB * u1b + vbb);
                c[nt][0] = z0; c[nt][1] = z1; c[nt][2] = z2; c[nt][3] = z3;
                uint2 p0; p0.x = f2tf32(z0); p0.y = f2tf32(z1);
                uint2 p1; p1.x = f2tf32(z2); p1.y = f2tf32(z3);
                *(uint2*)(As + r0 * ASTR + c0) = p0;
                *(uint2*)(As + r1 * ASTR + c0) = p1;
                s0 += z0 + z1; q0 += z0 * z0 + z1 * z1;
                s1 += z2 + z3; q1 += z2 * z2 + z3 * z3;
            }
#pragma unroll
            for (int off = 1; off <= 2; off <<= 1) {
                s0 += __shfl_xor_sync(0xffffffffu, s0, off);
                s1 += __shfl_xor_sync(0xffffffffu, s1, off);
                q0 += __shfl_xor_sync(0xffffffffu, q0, off);
                q1 += __shfl_xor_sync(0xffffffffu, q1, off);
            }
            if (t == 0) {
                sv[SV_SUM + r0 * 4 + wn] = s0;
                sv[SV_SQ  + r0 * 4 + wn] = q0;
                sv[SV_SUM + r1 * 4 + wn] = s1;
                sv[SV_SQ  + r1 * 4 + wn] = q1;
            }
        }
        __syncthreads();
        if (tid < 128) {
            float s = sv[SV_SUM + tid * 4] + sv[SV_SUM + tid * 4 + 1]
                    + sv[SV_SUM + tid * 4 + 2] + sv[SV_SUM + tid * 4 + 3];
            float q = sv[SV_SQ + tid * 4] + sv[SV_SQ + tid * 4 + 1]
                    + sv[SV_SQ + tid * 4 + 2] + sv[SV_SQ + tid * 4 + 3];
            float mu = s * (1.0f / 128.0f);
            sv[SV_MU2 + tid] = mu;
            sv[SV_RS2 + tid] = rsqrtf(q * (1.0f / 128.0f) - mu * mu + EPSL);
        }
        __syncthreads();

        // ---- aggm atomics: m = (z - mu2)*rs2*g2 + be2 ----
        {
            int r0 = mbase + g, r1 = r0 + 8;
            float mu0 = sv[SV_MU2 + r0], rs0 = sv[SV_RS2 + r0];
            float mu1 = sv[SV_MU2 + r1], rs1 = sv[SV_RS2 + r1];
            int d0 = sdst[r0], d1 = sdst[r1];
#pragma unroll
            for (int nt = 0; nt < 4; nt++) {
                int c0 = nbase + nt * 8 + 2 * t;
                float g2a = sv[SV_G2 + c0],  g2b = sv[SV_G2 + c0 + 1];
                float bea = sv[SV_BE2 + c0], beb = sv[SV_BE2 + c0 + 1];
                float m0 = (c[nt][0] - mu0) * rs0 * g2a + bea;
                float m1 = (c[nt][1] - mu0) * rs0 * g2b + beb;
                float m2 = (c[nt][2] - mu1) * rs1 * g2a + bea;
                float m3 = (c[nt][3] - mu1) * rs1 * g2b + beb;
                asm volatile("red.global.add.v2.f32 [%0], {%1, %2};"
                             :: "l"(g_aggm + (size_t)d0 * 128 + c0), "f"(m0), "f"(m1) : "memory");
                asm volatile("red.global.add.v2.f32 [%0], {%1, %2};"
                             :: "l"(g_aggm + (size_t)d1 * 128 + c0), "f"(m2), "f"(m3) : "memory");
            }
        }

        // ---- GEMM2: z @ (g2 ∘ c_w1) ----
#pragma unroll
        for (int nt = 0; nt < 4; nt++)
#pragma unroll
            for (int j = 0; j < 4; j++) c[nt][j] = 0.f;
        warp_gemm_tf32(Au, B2u, c, mbase, nbase, g, t);

        // ---- ep2: val = rs2*(d - mu2*u2) + vb2 ; coef partials ----
        {
            int r0 = mbase + g, r1 = r0 + 8;
            float rs0 = sv[SV_RS2 + r0], b0 = rs0 * sv[SV_MU2 + r0];
            float rs1 = sv[SV_RS2 + r1], b1 = rs1 * sv[SV_MU2 + r1];
            float p0 = 0.f, p1 = 0.f;
#pragma unroll
            for (int nt = 0; nt < 4; nt++) {
                int c0 = nbase + nt * 8 + 2 * t;
                float u2a = sv[SV_U2 + c0],  u2b = sv[SV_U2 + c0 + 1];
                float vba = sv[SV_VB2 + c0], vbb = sv[SV_VB2 + c0 + 1];
                float wa  = sv[SV_CW2 + c0], wb  = sv[SV_CW2 + c0 + 1];
                p0 += silu_f(rs0 * c[nt][0] - b0 * u2a + vba) * wa
                    + silu_f(rs0 * c[nt][1] - b0 * u2b + vbb) * wb;
                p1 += silu_f(rs1 * c[nt][2] - b1 * u2a + vba) * wa
                    + silu_f(rs1 * c[nt][3] - b1 * u2b + vbb) * wb;
            }
#pragma unroll
            for (int off = 1; off <= 2; off <<= 1) {
                p0 += __shfl_xor_sync(0xffffffffu, p0, off);
                p1 += __shfl_xor_sync(0xffffffffu, p1, off);
            }
            if (t == 0) {
                sv[SV_SUM + r0 * 4 + wn] = p0;
                sv[SV_SUM + r1 * 4 + wn] = p1;
            }
        }
        __syncthreads();
        if (tid < 128) {
            float coef = sv[SV_SUM + tid * 4] + sv[SV_SUM + tid * 4 + 1]
                       + sv[SV_SUM + tid * 4 + 2] + sv[SV_SUM + tid * 4 + 3] + cb2;
            int di = sdst[tid];
            atomicAdd(&out_pos[di * 3 + 0], sv[SV_RELX + tid] * coef);
            atomicAdd(&out_pos[di * 3 + 1], sv[SV_RELY + tid] * coef);
            atomicAdd(&out_pos[di * 3 + 2], sv[SV_RELZ + tid] * coef);
        }
        __syncthreads();
    }
}

// ---------------- K3: node MLP + residual ------------------------------------
__global__ __launch_bounds__(256, 1)
void node_kernel(const float* __restrict__ x,
                 const float* __restrict__ n_w1, const float* __restrict__ n_b1,
                 const float* __restrict__ n_g1, const float* __restrict__ n_be1,
                 const float* __restrict__ n_w2, const float* __restrict__ n_b2,
                 float* __restrict__ out_x)
{
    extern __shared__ float smf[];
    float* Bs = smf;
    float* hs = smf + 16384;
    float* sv = hs + 16896;
    int tid = threadIdx.x, ty = tid >> 4, tx = tid & 15, warp = tid >> 5, lane = tid & 31;
    int n0 = blockIdx.x * 128;

    if (tid < 128) {
        sv[tid]       = n_b1[tid];
        sv[128 + tid] = n_g1[tid];
        sv[256 + tid] = n_be1[tid];
        sv[384 + tid] = n_b2[tid];
    }

    for (int idx = tid; idx < 128 * 32; idx += 256) {
        int row = idx >> 5, q = idx & 31;
        float4 v = make_float4(0.f, 0.f, 0.f, 0.f);
        if (n0 + row < NN)
            v = *reinterpret_cast<const float4*>(x + (size_t)(n0 + row) * 128 + q * 4);
        *reinterpret_cast<float4*>(hs + row * HSS + q * 4) = v;
    }
    for (int i = tid; i < 4096; i += 256)
        reinterpret_cast<float4*>(Bs)[i] = reinterpret_cast<const float4*>(n_w1)[i];
    __syncthreads();

    float acc[8][8];
#pragma unroll
    for (int i = 0; i < 8; i++)
#pragma unroll
        for (int j = 0; j < 8; j++) acc[i][j] = 0.f;
    gemm128(hs, Bs, acc, ty, tx);
    __syncthreads();

    for (int idx = tid; idx < 128 * 32; idx += 256) {
        int row = idx >> 5, q = idx & 31;
        float4 v = make_float4(0.f, 0.f, 0.f, 0.f);
        if (n0 + row < NN)
            v = *reinterpret_cast<const float4*>(g_aggm + (size_t)(n0 + row) * 128 + q * 4);
        *reinterpret_cast<float4*>(hs + row * HSS + q * 4) = v;
    }
    for (int i = tid; i < 4096; i += 256)
        reinterpret_cast<float4*>(Bs)[i] = reinterpret_cast<const float4*>(n_w1 + 16384)[i];
    __syncthreads();
    gemm128(hs, Bs, acc, ty, tx);
    __syncthreads();

    {
        int c = tx * 8;
        float4 ba = *reinterpret_cast<const float4*>(sv + c);
        float4 bb = *reinterpret_cast<const float4*>(sv + c + 4);
#pragma unroll
        for (int i = 0; i < 8; i++) {
            int row = ty * 8 + i;
            float4 v0, v1;
            v0.x = silu_f(acc[i][0] + ba.x); v0.y = silu_f(acc[i][1] + ba.y);
            v0.z = silu_f(acc[i][2] + ba.z); v0.w = silu_f(acc[i][3] + ba.w);
            v1.x = silu_f(acc[i][4] + bb.x); v1.y = silu_f(acc[i][5] + bb.y);
            v1.z = silu_f(acc[i][6] + bb.z); v1.w = silu_f(acc[i][7] + bb.w);
            *reinterpret_cast<float4*>(hs + row * HSS + c)     = v0;
            *reinterpret_cast<float4*>(hs + row * HSS + c + 4) = v1;
        }
    }
    __syncthreads();
    ln_rows(hs, sv + 128, sv + 256, warp, lane);
    __syncthreads();

    for (int i = tid; i < 4096; i += 256)
        reinterpret_cast<float4*>(Bs)[i] = reinterpret_cast<const float4*>(n_w2)[i];
    __syncthreads();
    float acc2[8][8];
#pragma unroll
    for (int i = 0; i < 8; i++)
#pragma unroll
        for (int j = 0; j < 8; j++) acc2[i][j] = 0.f;
    gemm128(hs, Bs, acc2, ty, tx);

    {
        int c = tx * 8;
        float4 ba = *reinterpret_cast<const float4*>(sv + 384 + c);
        float4 bb = *reinterpret_cast<const float4*>(sv + 384 + c + 4);
#pragma unroll
        for (int i = 0; i < 8; i++) {
            int row = n0 + ty * 8 + i;
            if (row < NN) {
                float4 xv0 = *reinterpret_cast<const float4*>(x + (size_t)row * 128 + c);
                float4 xv1 = *reinterpret_cast<const float4*>(x + (size_t)row * 128 + c + 4);
                float4 o0, o1;
                o0.x = acc2[i][0] + ba.x + xv0.x; o0.y = acc2[i][1] + ba.y + xv0.y;
                o0.z = acc2[i][2] + ba.z + xv0.z; o0.w = acc2[i][3] + ba.w + xv0.w;
                o1.x = acc2[i][4] + bb.x + xv1.x; o1.y = acc2[i][5] + bb.y + xv1.y;
                o1.z = acc2[i][6] + bb.z + xv1.z; o1.w = acc2[i][7] + bb.w + xv1.w;
                *reinterpret_cast<float4*>(out_x + (size_t)row * 128 + c)     = o0;
                *reinterpret_cast<float4*>(out_x + (size_t)row * 128 + c + 4) = o1;
            }
        }
    }
}

// ---------------- launch ------------------------------------------------------
extern "C" void kernel_launch(void* const* d_in, const int* in_sizes, int n_in,
                              void* d_out, int out_size)
{
    const float*     x     = (const float*)d_in[0];
    const float*     pos   = (const float*)d_in[1];
    const void*      ei    = d_in[2];
    const float*     ea    = (const float*)d_in[3];
    const float*     e_w1  = (const float*)d_in[4];
    const float*     e_b1  = (const float*)d_in[5];
    const float*     e_g1  = (const float*)d_in[6];
    const float*     e_be1 = (const float*)d_in[7];
    const float*     e_w2  = (const float*)d_in[8];
    const float*     e_b2  = (const float*)d_in[9];
    const float*     e_g2  = (const float*)d_in[10];
    const float*     e_be2 = (const float*)d_in[11];
    const float*     n_w1  = (const float*)d_in[12];
    const float*     n_b1  = (const float*)d_in[13];
    const float*     n_g1  = (const float*)d_in[14];
    const float*     n_be1 = (const float*)d_in[15];
    const float*     n_w2  = (const float*)d_in[16];
    const float*     n_b2  = (const float*)d_in[17];
    const float*     c_w1  = (const float*)d_in[18];
    const float*     c_b1  = (const float*)d_in[19];
    const float*     c_w2  = (const float*)d_in[20];
    const float*     c_b2  = (const float*)d_in[21];

    float* out_x   = (float*)d_out;
    float* out_pos = (float*)d_out + (size_t)NN * FEAT;

    const int SMEM_PRE  = (16384 + 16896) * 4;
    const int SMEM_NODE = (16384 + 16896 + 512) * 4;

    cudaFuncSetAttribute(preab_kernel, cudaFuncAttributeMaxDynamicSharedMemorySize, SMEM_PRE);
    cudaFuncSetAttribute(edge_kernel,  cudaFuncAttributeMaxDynamicSharedMemorySize, EDGE_SMEM);
    cudaFuncSetAttribute(node_kernel,  cudaFuncAttributeMaxDynamicSharedMemorySize, SMEM_NODE);

    conv_idx_kernel<<<256, 256>>>(ei);
    init_kernel<<<256, 256>>>(pos, out_pos);
    preab_kernel<<<(NN + 127) / 128, 256, SMEM_PRE>>>(x, e_w1);
    edge_kernel<<<148, 1024, EDGE_SMEM>>>(pos, ea,
                                          e_w1, e_b1, e_g1, e_be1,
                                          e_w2, e_b2, e_g2, e_be2,
                                          c_w1, c_b1, c_w2, c_b2,
                                          out_pos);
    node_kernel<<<(NN + 127) / 128, 256, SMEM_NODE>>>(x, n_w1, n_b1, n_g1, n_be1,
                                                      n_w2, n_b2, out_x);
}

// round 9
// speedup vs baseline: 2.7181x; 1.3691x over previous
#include <cuda_runtime.h>
#include <cstdint>

#define NN   50000
#define EE   800000
#define FEAT 128
#define HID  128
#define EPSL 1e-5f

#define ASTR 132          // MMA A-tile stride (floats)
#define BSTR 136          // MMA weight-tile stride (floats)

// ---------------- scratch (device globals) -----------------------------------
__device__ float g_A[NN * FEAT];      // x @ Wa   (e_w1 rows   0..127)
__device__ float g_B[NN * FEAT];      // x @ Wb   (e_w1 rows 128..255)
__device__ float g_aggm[NN * HID];    // segment-sum of m_ij
__device__ int   g_src[EE];
__device__ int   g_dst[EE];

__device__ __forceinline__ float silu_f(float v) {
    return __fdividef(v, 1.0f + __expf(-v));
}
__device__ __forceinline__ uint32_t f2tf32(float f) {
    uint32_t r; asm("cvt.rna.tf32.f32 %0, %1;" : "=r"(r) : "f"(f)); return r;
}
__device__ __forceinline__ void mma8(float* d, const uint32_t* a, const uint32_t* b) {
    asm volatile("mma.sync.aligned.m16n8k8.row.col.f32.tf32.tf32.f32 "
                 "{%0,%1,%2,%3}, {%4,%5,%6,%7}, {%8,%9}, {%0,%1,%2,%3};"
                 : "+f"(d[0]), "+f"(d[1]), "+f"(d[2]), "+f"(d[3])
                 : "r"(a[0]), "r"(a[1]), "r"(a[2]), "r"(a[3]), "r"(b[0]), "r"(b[1]));
}

// per-warp tf32 GEMM (1024-thr kernels): C[16x32] += A[16x128] * B[128x32]
__device__ __forceinline__ void warp_gemm1(const uint32_t* __restrict__ Au,
                                           const uint32_t* __restrict__ Bu,
                                           float c[4][4],
                                           int mbase, int nbase, int g, int t)
{
#pragma unroll 1
    for (int ks = 0; ks < 16; ks++) {
        int kk = ks * 8;
        uint32_t af[4];
        {
            const uint32_t* p = Au + (mbase + g) * ASTR + kk + t;
            af[0] = p[0];
            af[1] = p[8 * ASTR];
            af[2] = p[4];
            af[3] = p[8 * ASTR + 4];
        }
        uint32_t bf[4][2];
#pragma unroll
        for (int nt = 0; nt < 4; nt++) {
            const uint32_t* p = Bu + (kk + t) * BSTR + nbase + nt * 8 + g;
            bf[nt][0] = p[0];
            bf[nt][1] = p[4 * BSTR];
        }
#pragma unroll
        for (int nt = 0; nt < 4; nt++)
            mma8(c[nt], af, bf[nt]);
    }
}

// per-warp tf32 GEMM (512-thr kernels): C[32x32] += A[32x128] * B[128x32]
__device__ __forceinline__ void warp_gemm2(const uint32_t* __restrict__ Au,
                                           const uint32_t* __restrict__ Bu,
                                           float c[2][4][4],
                                           int mbase, int nbase, int g, int t)
{
#pragma unroll 1
    for (int ks = 0; ks < 16; ks++) {
        int kk = ks * 8;
        uint32_t af[2][4];
#pragma unroll
        for (int mt = 0; mt < 2; mt++) {
            const uint32_t* p = Au + (mbase + mt * 16 + g) * ASTR + kk + t;
            af[mt][0] = p[0];
            af[mt][1] = p[8 * ASTR];
            af[mt][2] = p[4];
            af[mt][3] = p[8 * ASTR + 4];
        }
        uint32_t bf[4][2];
#pragma unroll
        for (int nt = 0; nt < 4; nt++) {
            const uint32_t* p = Bu + (kk + t) * BSTR + nbase + nt * 8 + g;
            bf[nt][0] = p[0];
            bf[nt][1] = p[4 * BSTR];
        }
#pragma unroll
        for (int mt = 0; mt < 2; mt++)
#pragma unroll
            for (int nt = 0; nt < 4; nt++)
                mma8(c[mt][nt], af[mt], bf[nt]);
    }
}

// ---------------- K-1: normalize edge_index dtype ----------------------------
__global__ void conv_idx_kernel(const void* __restrict__ ei_raw)
{
    const long long* e64 = (const long long*)ei_raw;
    const int*       e32 = (const int*)ei_raw;
    bool is64 = true;
#pragma unroll
    for (int j = 0; j < 8; j++) {
        long long v = e64[j];
        if (v < 0 || v >= NN) is64 = false;
    }
    int i = blockIdx.x * blockDim.x + threadIdx.x;
    int stride = gridDim.x * blockDim.x;
    if (is64) {
        for (int e = i; e < EE; e += stride) {
            g_src[e] = (int)e64[e];
            g_dst[e] = (int)e64[EE + e];
        }
    } else {
        for (int e = i; e < EE; e += stride) {
            g_src[e] = e32[e];
            g_dst[e] = e32[EE + e];
        }
    }
}

// ---------------- K0: zero agg_m, pos_out = pos ------------------------------
__global__ void init_kernel(const float* __restrict__ pos, float* __restrict__ out_pos)
{
    int i = blockIdx.x * blockDim.x + threadIdx.x;
    int stride = gridDim.x * blockDim.x;
    for (int j = i; j < NN * HID; j += stride) g_aggm[j] = 0.0f;
    for (int j = i; j < NN * 3;   j += stride) out_pos[j] = pos[j];
}

// ---------------- K1: A = x@Wa, B = x@Wb (tf32 MMA, 512 thr) ------------------
// smem floats: As 0..16896, B1 16896..34304, B2 34304..51712
#define PB_SMEM (51712 * 4)
__global__ __launch_bounds__(512, 1)
void preab_kernel(const float* __restrict__ x, const float* __restrict__ e_w1)
{
    extern __shared__ float sm[];
    float* As  = sm;
    float* B1s = sm + 16896;
    float* B2s = sm + 34304;
    const uint32_t* Au  = (const uint32_t*)As;
    const uint32_t* B1u = (const uint32_t*)B1s;
    const uint32_t* B2u = (const uint32_t*)B2s;

    int tid = threadIdx.x, warp = tid >> 5, lane = tid & 31;
    int g = lane >> 2, t = lane & 3;
    int wm = warp >> 2, wn = warp & 3;
    int mbase = wm * 32, nbase = wn * 32;
    int n0 = blockIdx.x * 128;

    for (int idx = tid; idx < 16384; idx += 512) {
        int row = idx >> 7, k = idx & 127;     // As: row=M, k=K ; weights: row=K, k=N
        float v = (n0 + row < NN) ? x[(size_t)(n0 + row) * 128 + k] : 0.f;
        As[row * ASTR + k]  = __uint_as_float(f2tf32(v));
        B1s[row * BSTR + k] = __uint_as_float(f2tf32(e_w1[row * 128 + k]));
        B2s[row * BSTR + k] = __uint_as_float(f2tf32(e_w1[(128 + row) * 128 + k]));
    }
    __syncthreads();

    float c[2][4][4];
#pragma unroll
    for (int mt = 0; mt < 2; mt++)
#pragma unroll
        for (int nt = 0; nt < 4; nt++)
#pragma unroll
            for (int j = 0; j < 4; j++) c[mt][nt][j] = 0.f;
    warp_gemm2(Au, B1u, c, mbase, nbase, g, t);
#pragma unroll
    for (int mt = 0; mt < 2; mt++) {
        int r0 = mbase + mt * 16 + g, r1 = r0 + 8;
#pragma unroll
        for (int nt = 0; nt < 4; nt++) {
            int c0 = nbase + nt * 8 + 2 * t;
            if (n0 + r0 < NN)
                *(float2*)(g_A + (size_t)(n0 + r0) * 128 + c0) = make_float2(c[mt][nt][0], c[mt][nt][1]);
            if (n0 + r1 < NN)
                *(float2*)(g_A + (size_t)(n0 + r1) * 128 + c0) = make_float2(c[mt][nt][2], c[mt][nt][3]);
        }
    }

#pragma unroll
    for (int mt = 0; mt < 2; mt++)
#pragma unroll
        for (int nt = 0; nt < 4; nt++)
#pragma unroll
            for (int j = 0; j < 4; j++) c[mt][nt][j] = 0.f;
    warp_gemm2(Au, B2u, c, mbase, nbase, g, t);
#pragma unroll
    for (int mt = 0; mt < 2; mt++) {
        int r0 = mbase + mt * 16 + g, r1 = r0 + 8;
#pragma unroll
        for (int nt = 0; nt < 4; nt++) {
            int c0 = nbase + nt * 8 + 2 * t;
            if (n0 + r0 < NN)
                *(float2*)(g_B + (size_t)(n0 + r0) * 128 + c0) = make_float2(c[mt][nt][0], c[mt][nt][1]);
            if (n0 + r1 < NN)
                *(float2*)(g_B + (size_t)(n0 + r1) * 128 + c0) = make_float2(c[mt][nt][2], c[mt][nt][3]);
        }
    }
}

// ---------------- K2: persistent edge kernel (mma.sync tf32, 1024 thr) -------
// smem float layout
#define EO_A    0                       // 128*ASTR = 16896
#define EO_B1   16896                   // 128*BSTR = 17408
#define EO_B2   34304
#define EO_SV   51712
// sv float indices (relative to sv)
#define SV_WC0  0
#define SV_WC1  128
#define SV_WD   256
#define SV_B1   384
#define SV_U1   512
#define SV_VB1  640
#define SV_G2   768
#define SV_BE2  896
#define SV_U2   1024
#define SV_VB2  1152
#define SV_CW2  1280
#define SV_RELX 1408
#define SV_RELY 1536
#define SV_RELZ 1664
#define SV_R2   1792
#define SV_EA0  1920
#define SV_EA1  2048
#define SV_MU1  2176
#define SV_RS1  2304
#define SV_MU2  2432
#define SV_RS2  2560
#define SV_SUM  2688   // [128][4]
#define SV_SQ   3200   // [128][4]
#define SV_IDX  3712   // ints: 128 dst, 128 src
#define SV_FLOATS 3968
#define EDGE_SMEM ((EO_SV + SV_FLOATS) * 4)   // 222720 bytes

__global__ __launch_bounds__(1024, 1)
void edge_kernel(const float* __restrict__ pos,
                 const float* __restrict__ ea,
                 const float* __restrict__ e_w1, const float* __restrict__ e_b1,
                 const float* __restrict__ e_g1, const float* __restrict__ e_be1,
                 const float* __restrict__ e_w2, const float* __restrict__ e_b2,
                 const float* __restrict__ e_g2, const float* __restrict__ e_be2,
                 const float* __restrict__ c_w1, const float* __restrict__ c_b1,
                 const float* __restrict__ c_w2, const float* __restrict__ c_b2,
                 float* __restrict__ out_pos)
{
    extern __shared__ float sm[];
    float* As  = sm + EO_A;
    float* B1s = sm + EO_B1;
    float* B2s = sm + EO_B2;
    float* sv  = sm + EO_SV;
    int*   sdst = (int*)(sv + SV_IDX);
    int*   ssrc = sdst + 128;
    const uint32_t* Au  = (const uint32_t*)As;
    const uint32_t* B1u = (const uint32_t*)B1s;
    const uint32_t* B2u = (const uint32_t*)B2s;

    int tid = threadIdx.x, warp = tid >> 5, lane = tid & 31;
    int g = lane >> 2, t = lane & 3;
    int wm = warp >> 2, wn = warp & 3;
    int mbase = wm * 16, nbase = wn * 32;

    // ---- stage LN-folded weights (tf32) + small vectors ----
    for (int idx = tid; idx < 16384; idx += 1024) {
        int k = idx >> 7, n = idx & 127;
        B1s[k * BSTR + n] = __uint_as_float(f2tf32(e_g1[k] * e_w2[k * 128 + n]));
        B2s[k * BSTR + n] = __uint_as_float(f2tf32(e_g2[k] * c_w1[k * 128 + n]));
    }
    if (tid < 128) {
        sv[SV_WC0 + tid] = e_w1[256 * 128 + tid];
        sv[SV_WC1 + tid] = e_w1[257 * 128 + tid];
        sv[SV_WD  + tid] = e_w1[258 * 128 + tid];
        sv[SV_B1  + tid] = e_b1[tid];
        sv[SV_G2  + tid] = e_g2[tid];
        sv[SV_BE2 + tid] = e_be2[tid];
        sv[SV_CW2 + tid] = c_w2[tid];
    }
    if (tid < 512) {
        int quad = tid >> 7, n = tid & 127;
        float acc = 0.f;
        if (quad == 0) {
            for (int k = 0; k < 128; k++) acc += e_g1[k] * e_w2[k * 128 + n];
            sv[SV_U1 + n] = acc;
        } else if (quad == 1) {
            for (int k = 0; k < 128; k++) acc += e_be1[k] * e_w2[k * 128 + n];
            sv[SV_VB1 + n] = acc + e_b2[n];
        } else if (quad == 2) {
            for (int k = 0; k < 128; k++) acc += e_g2[k] * c_w1[k * 128 + n];
            sv[SV_U2 + n] = acc;
        } else {
            for (int k = 0; k < 128; k++) acc += e_be2[k] * c_w1[k * 128 + n];
            sv[SV_VB2 + n] = acc + c_b1[n];
        }
    }
    float cb2 = c_b2[0];
    __syncthreads();

    int k4 = lane * 4;

    const int ntiles = EE / 128;
    for (int tile = blockIdx.x; tile < ntiles; tile += gridDim.x) {
        int e0 = tile * 128;
        // ---- stage edge meta ----
        if (tid < 128) {
            int e = e0 + tid;
            int si = g_src[e], di = g_dst[e];
            float rx = pos[di * 3 + 0] - pos[si * 3 + 0];
            float ry = pos[di * 3 + 1] - pos[si * 3 + 1];
            float rz = pos[di * 3 + 2] - pos[si * 3 + 2];
            ssrc[tid] = si; sdst[tid] = di;
            sv[SV_RELX + tid] = rx; sv[SV_RELY + tid] = ry; sv[SV_RELZ + tid] = rz;
            sv[SV_R2 + tid]  = rx * rx + ry * ry + rz * rz;
            sv[SV_EA0 + tid] = ea[2 * e];
            sv[SV_EA1 + tid] = ea[2 * e + 1];
        }
        __syncthreads();

        // ---- layer-1: gather + SiLU -> As (raw h, tf32); row stats to smem ----
        {
            float4 wc0 = *(const float4*)(sv + SV_WC0 + k4);
            float4 wc1 = *(const float4*)(sv + SV_WC1 + k4);
            float4 wdv = *(const float4*)(sv + SV_WD  + k4);
            float4 b1v = *(const float4*)(sv + SV_B1  + k4);
#pragma unroll 1
            for (int r = 0; r < 4; r++) {
                int row = warp * 4 + r;
                int si = ssrc[row], di = sdst[row];
                float4 a = *(const float4*)(g_A + (size_t)si * 128 + k4);
                float4 b = *(const float4*)(g_B + (size_t)di * 128 + k4);
                float e0v = sv[SV_EA0 + row], e1v = sv[SV_EA1 + row], r2v = sv[SV_R2 + row];
                float4 o;
                o.x = silu_f(a.x + b.x + e0v * wc0.x + e1v * wc1.x + r2v * wdv.x + b1v.x);
                o.y = silu_f(a.y + b.y + e0v * wc0.y + e1v * wc1.y + r2v * wdv.y + b1v.y);
                o.z = silu_f(a.z + b.z + e0v * wc0.z + e1v * wc1.z + r2v * wdv.z + b1v.z);
                o.w = silu_f(a.w + b.w + e0v * wc0.w + e1v * wc1.w + r2v * wdv.w + b1v.w);
                float s = o.x + o.y + o.z + o.w;
                float q = o.x * o.x + o.y * o.y + o.z * o.z + o.w * o.w;
#pragma unroll
                for (int off = 16; off > 0; off >>= 1) {
                    s += __shfl_xor_sync(0xffffffffu, s, off);
                    q += __shfl_xor_sync(0xffffffffu, q, off);
                }
                uint4 tv;
                tv.x = f2tf32(o.x); tv.y = f2tf32(o.y);
                tv.z = f2tf32(o.z); tv.w = f2tf32(o.w);
                *(uint4*)(As + row * ASTR + k4) = tv;
                if (lane == 0) {
                    float mu = s * (1.0f / 128.0f);
                    sv[SV_MU1 + row] = mu;
                    sv[SV_RS1 + row] = rsqrtf(q * (1.0f / 128.0f) - mu * mu + EPSL);
                }
            }
        }
        __syncthreads();

        // ---- GEMM1: h @ (g1 ∘ e_w2) ----
        float c[4][4];
#pragma unroll
        for (int nt = 0; nt < 4; nt++)
#pragma unroll
            for (int j = 0; j < 4; j++) c[nt][j] = 0.f;
        warp_gemm1(Au, B1u, c, mbase, nbase, g, t);
        __syncthreads();   // all warps done reading As before z rewrite

        // ---- ep1: y = rs1*(d - mu1*u1) + vb1 ; z = silu(y) -> As + stats ----
        {
            int r0 = mbase + g, r1 = r0 + 8;
            float rsA = sv[SV_RS1 + r0], bA = rsA * sv[SV_MU1 + r0];
            float rsB = sv[SV_RS1 + r1], bB = rsB * sv[SV_MU1 + r1];
            float s0 = 0.f, q0 = 0.f, s1 = 0.f, q1 = 0.f;
#pragma unroll
            for (int nt = 0; nt < 4; nt++) {
                int c0 = nbase + nt * 8 + 2 * t;
                float u1a = sv[SV_U1 + c0],  u1b = sv[SV_U1 + c0 + 1];
                float vba = sv[SV_VB1 + c0], vbb = sv[SV_VB1 + c0 + 1];
                float z0 = silu_f(rsA * c[nt][0] - bA * u1a + vba);
                float z1 = silu_f(rsA * c[nt][1] - bA * u1b + vbb);
                float z2 = silu_f(rsB * c[nt][2] - bB * u1a + vba);
                float z3 = silu_f(rsB * c[nt][3] - bB * u1b + vbb);
                c[nt][0] = z0; c[nt][1] = z1; c[nt][2] = z2; c[nt][3] = z3;
                uint2 p0; p0.x = f2tf32(z0); p0.y = f2tf32(z1);
                uint2 p1; p1.x = f2tf32(z2); p1.y = f2tf32(z3);
                *(uint2*)(As + r0 * ASTR + c0) = p0;
                *(uint2*)(As + r1 * ASTR + c0) = p1;
                s0 += z0 + z1; q0 += z0 * z0 + z1 * z1;
                s1 += z2 + z3; q1 += z2 * z2 + z3 * z3;
            }
#pragma unroll
            for (int off = 1; off <= 2; off <<= 1) {
                s0 += __shfl_xor_sync(0xffffffffu, s0, off);
                s1 += __shfl_xor_sync(0xffffffffu, s1, off);
                q0 += __shfl_xor_sync(0xffffffffu, q0, off);
                q1 += __shfl_xor_sync(0xffffffffu, q1, off);
            }
            if (t == 0) {
                sv[SV_SUM + r0 * 4 + wn] = s0;
                sv[SV_SQ  + r0 * 4 + wn] = q0;
                sv[SV_SUM + r1 * 4 + wn] = s1;
                sv[SV_SQ  + r1 * 4 + wn] = q1;
            }
        }
        __syncthreads();
        if (tid < 128) {
            float s = sv[SV_SUM + tid * 4] + sv[SV_SUM + tid * 4 + 1]
                    + sv[SV_SUM + tid * 4 + 2] + sv[SV_SUM + tid * 4 + 3];
            float q = sv[SV_SQ + tid * 4] + sv[SV_SQ + tid * 4 + 1]
                    + sv[SV_SQ + tid * 4 + 2] + sv[SV_SQ + tid * 4 + 3];
            float mu = s * (1.0f / 128.0f);
            sv[SV_MU2 + tid] = mu;
            sv[SV_RS2 + tid] = rsqrtf(q * (1.0f / 128.0f) - mu * mu + EPSL);
        }
        __syncthreads();

        // ---- aggm atomics: m = (z - mu2)*rs2*g2 + be2 ----
        {
            int r0 = mbase + g, r1 = r0 + 8;
            float mu0 = sv[SV_MU2 + r0], rs0 = sv[SV_RS2 + r0];
            float mu1 = sv[SV_MU2 + r1], rs1 = sv[SV_RS2 + r1];
            int d0 = sdst[r0], d1 = sdst[r1];
#pragma unroll
            for (int nt = 0; nt < 4; nt++) {
                int c0 = nbase + nt * 8 + 2 * t;
                float g2a = sv[SV_G2 + c0],  g2b = sv[SV_G2 + c0 + 1];
                float bea = sv[SV_BE2 + c0], beb = sv[SV_BE2 + c0 + 1];
                float m0 = (c[nt][0] - mu0) * rs0 * g2a + bea;
                float m1 = (c[nt][1] - mu0) * rs0 * g2b + beb;
                float m2 = (c[nt][2] - mu1) * rs1 * g2a + bea;
                float m3 = (c[nt][3] - mu1) * rs1 * g2b + beb;
                asm volatile("red.global.add.v2.f32 [%0], {%1, %2};"
                             :: "l"(g_aggm + (size_t)d0 * 128 + c0), "f"(m0), "f"(m1) : "memory");
                asm volatile("red.global.add.v2.f32 [%0], {%1, %2};"
                             :: "l"(g_aggm + (size_t)d1 * 128 + c0), "f"(m2), "f"(m3) : "memory");
            }
        }

        // ---- GEMM2: z @ (g2 ∘ c_w1) ----
#pragma unroll
        for (int nt = 0; nt < 4; nt++)
#pragma unroll
            for (int j = 0; j < 4; j++) c[nt][j] = 0.f;
        warp_gemm1(Au, B2u, c, mbase, nbase, g, t);

        // ---- ep2: val = rs2*(d - mu2*u2) + vb2 ; coef partials ----
        {
            int r0 = mbase + g, r1 = r0 + 8;
            float rs0 = sv[SV_RS2 + r0], b0 = rs0 * sv[SV_MU2 + r0];
            float rs1 = sv[SV_RS2 + r1], b1 = rs1 * sv[SV_MU2 + r1];
            float p0 = 0.f, p1 = 0.f;
#pragma unroll
            for (int nt = 0; nt < 4; nt++) {
                int c0 = nbase + nt * 8 + 2 * t;
                float u2a = sv[SV_U2 + c0],  u2b = sv[SV_U2 + c0 + 1];
                float vba = sv[SV_VB2 + c0], vbb = sv[SV_VB2 + c0 + 1];
                float wa  = sv[SV_CW2 + c0], wb  = sv[SV_CW2 + c0 + 1];
                p0 += silu_f(rs0 * c[nt][0] - b0 * u2a + vba) * wa
                    + silu_f(rs0 * c[nt][1] - b0 * u2b + vbb) * wb;
                p1 += silu_f(rs1 * c[nt][2] - b1 * u2a + vba) * wa
                    + silu_f(rs1 * c[nt][3] - b1 * u2b + vbb) * wb;
            }
#pragma unroll
            for (int off = 1; off <= 2; off <<= 1) {
                p0 += __shfl_xor_sync(0xffffffffu, p0, off);
                p1 += __shfl_xor_sync(0xffffffffu, p1, off);
            }
            if (t == 0) {
                sv[SV_SUM + r0 * 4 + wn] = p0;
                sv[SV_SUM + r1 * 4 + wn] = p1;
            }
        }
        __syncthreads();
        if (tid < 128) {
            float coef = sv[SV_SUM + tid * 4] + sv[SV_SUM + tid * 4 + 1]
                       + sv[SV_SUM + tid * 4 + 2] + sv[SV_SUM + tid * 4 + 3] + cb2;
            int di = sdst[tid];
            atomicAdd(&out_pos[di * 3 + 0], sv[SV_RELX + tid] * coef);
            atomicAdd(&out_pos[di * 3 + 1], sv[SV_RELY + tid] * coef);
            atomicAdd(&out_pos[di * 3 + 2], sv[SV_RELZ + tid] * coef);
        }
        __syncthreads();
    }
}

// ---------------- K3: node MLP + residual (tf32 MMA, 512 thr) ----------------
// smem floats: As 0..16896, Bs 16896..34304, sv 34304..
#define NV_B1   0
#define NV_U    128
#define NV_VB   256
#define NV_MU   384
#define NV_RS   512
#define NV_SUM  640    // [128][4]
#define NV_SQ   1152   // [128][4]
#define NV_FLOATS 1664
#define ND_SMEM ((34304 + NV_FLOATS) * 4)
__global__ __launch_bounds__(512, 1)
void node_kernel(const float* __restrict__ x,
                 const float* __restrict__ n_w1, const float* __restrict__ n_b1,
                 const float* __restrict__ n_g1, const float* __restrict__ n_be1,
                 const float* __restrict__ n_w2, const float* __restrict__ n_b2,
                 float* __restrict__ out_x)
{
    extern __shared__ float sm[];
    float* As = sm;
    float* Bs = sm + 16896;
    float* sv = sm + 34304;
    const uint32_t* Au = (const uint32_t*)As;
    const uint32_t* Bu = (const uint32_t*)Bs;

    int tid = threadIdx.x, warp = tid >> 5, lane = tid & 31;
    int g = lane >> 2, t = lane & 3;
    int wm = warp >> 2, wn = warp & 3;
    int mbase = wm * 32, nbase = wn * 32;
    int n0 = blockIdx.x * 128;

    // sv constants
    if (tid < 128) sv[NV_B1 + tid] = n_b1[tid];
    if (tid >= 128 && tid < 384) {
        int half = (tid - 128) >> 7, n = tid & 127;
        float acc = 0.f;
        if (half == 0) {
            for (int k = 0; k < 128; k++) acc += n_g1[k] * n_w2[k * 128 + n];
            sv[NV_U + n] = acc;
        } else {
            for (int k = 0; k < 128; k++) acc += n_be1[k] * n_w2[k * 128 + n];
            sv[NV_VB + n] = acc + n_b2[n];
        }
    }

    // phase 1: x @ W1a
    for (int idx = tid; idx < 16384; idx += 512) {
        int row = idx >> 7, k = idx & 127;
        float v = (n0 + row < NN) ? x[(size_t)(n0 + row) * 128 + k] : 0.f;
        As[row * ASTR + k] = __uint_as_float(f2tf32(v));
        Bs[row * BSTR + k] = __uint_as_float(f2tf32(n_w1[row * 128 + k]));  // row=K idx, k=N idx
    }
    __syncthreads();

    float c[2][4][4];
#pragma unroll
    for (int mt = 0; mt < 2; mt++)
#pragma unroll
        for (int nt = 0; nt < 4; nt++)
#pragma unroll
            for (int j = 0; j < 4; j++) c[mt][nt][j] = 0.f;
    warp_gemm2(Au, Bu, c, mbase, nbase, g, t);
    __syncthreads();

    // phase 2: + aggm @ W1b
    for (int idx = tid; idx < 16384; idx += 512) {
        int row = idx >> 7, k = idx & 127;
        float v = (n0 + row < NN) ? g_aggm[(size_t)(n0 + row) * 128 + k] : 0.f;
        As[row * ASTR + k] = __uint_as_float(f2tf32(v));
        Bs[row * BSTR + k] = __uint_as_float(f2tf32(n_w1[(128 + row) * 128 + k]));
    }
    __syncthreads();
    warp_gemm2(Au, Bu, c, mbase, nbase, g, t);
    __syncthreads();

    // ep1: z = silu(acc + b1) -> As (tf32) + row stats
#pragma unroll
    for (int mt = 0; mt < 2; mt++) {
        int r0 = mbase + mt * 16 + g, r1 = r0 + 8;
        float s0 = 0.f, q0 = 0.f, s1 = 0.f, q1 = 0.f;
#pragma unroll
        for (int nt = 0; nt < 4; nt++) {
            int c0 = nbase + nt * 8 + 2 * t;
            float ba = sv[NV_B1 + c0], bb = sv[NV_B1 + c0 + 1];
            float z0 = silu_f(c[mt][nt][0] + ba);
            float z1 = silu_f(c[mt][nt][1] + bb);
            float z2 = silu_f(c[mt][nt][2] + ba);
            float z3 = silu_f(c[mt][nt][3] + bb);
            uint2 p0; p0.x = f2tf32(z0); p0.y = f2tf32(z1);
            uint2 p1; p1.x = f2tf32(z2); p1.y = f2tf32(z3);
            *(uint2*)(As + r0 * ASTR + c0) = p0;
            *(uint2*)(As + r1 * ASTR + c0) = p1;
            s0 += z0 + z1; q0 += z0 * z0 + z1 * z1;
            s1 += z2 + z3; q1 += z2 * z2 + z3 * z3;
        }
#pragma unroll
        for (int off = 1; off <= 2; off <<= 1) {
            s0 += __shfl_xor_sync(0xffffffffu, s0, off);
            s1 += __shfl_xor_sync(0xffffffffu, s1, off);
            q0 += __shfl_xor_sync(0xffffffffu, q0, off);
            q1 += __shfl_xor_sync(0xffffffffu, q1, off);
        }
        if (t == 0) {
            sv[NV_SUM + r0 * 4 + wn] = s0;
            sv[NV_SQ  + r0 * 4 + wn] = q0;
            sv[NV_SUM + r1 * 4 + wn] = s1;
            sv[NV_SQ  + r1 * 4 + wn] = q1;
        }
    }
    __syncthreads();
    if (tid < 128) {
        float s = sv[NV_SUM + tid * 4] + sv[NV_SUM + tid * 4 + 1]
                + sv[NV_SUM + tid * 4 + 2] + sv[NV_SUM + tid * 4 + 3];
        float q = sv[NV_SQ + tid * 4] + sv[NV_SQ + tid * 4 + 1]
                + sv[NV_SQ + tid * 4 + 2] + sv[NV_SQ + tid * 4 + 3];
        float mu = s * (1.0f / 128.0f);
        sv[NV_MU + tid] = mu;
        sv[NV_RS + tid] = rsqrtf(q * (1.0f / 128.0f) - mu * mu + EPSL);
    }
    // stage (g1 ∘ W2) into Bs
    for (int idx = tid; idx < 16384; idx += 512) {
        int k = idx >> 7, n = idx & 127;
        Bs[k * BSTR + n] = __uint_as_float(f2tf32(n_g1[k] * n_w2[k * 128 + n]));
    }
    __syncthreads();

    // GEMM2: z @ (g1 ∘ W2)
#pragma unroll
    for (int mt = 0; mt < 2; mt++)
#pragma unroll
        for (int nt = 0; nt < 4; nt++)
#pragma unroll
            for (int j = 0; j < 4; j++) c[mt][nt][j] = 0.f;
    warp_gemm2(Au, Bu, c, mbase, nbase, g, t);

    // ep2: out = x + rs*d - rs*mu*u + vb
#pragma unroll
    for (int mt = 0; mt < 2; mt++) {
        int r0 = mbase + mt * 16 + g, r1 = r0 + 8;
        float rs0 = sv[NV_RS + r0], b0 = rs0 * sv[NV_MU + r0];
        float rs1 = sv[NV_RS + r1], b1 = rs1 * sv[NV_MU + r1];
#pragma unroll
        for (int nt = 0; nt < 4; nt++) {
            int c0 = nbase + nt * 8 + 2 * t;
            float ua = sv[NV_U + c0],  ub = sv[NV_U + c0 + 1];
            float va = sv[NV_VB + c0], vb = sv[NV_VB + c0 + 1];
            if (n0 + r0 < NN) {
                float2 xv = *(const float2*)(x + (size_t)(n0 + r0) * 128 + c0);
                *(float2*)(out_x + (size_t)(n0 + r0) * 128 + c0) =
                    make_float2(xv.x + rs0 * c[mt][nt][0] - b0 * ua + va,
                                xv.y + rs0 * c[mt][nt][1] - b0 * ub + vb);
            }
            if (n0 + r1 < NN) {
                float2 xv = *(const float2*)(x + (size_t)(n0 + r1) * 128 + c0);
                *(float2*)(out_x + (size_t)(n0 + r1) * 128 + c0) =
                    make_float2(xv.x + rs1 * c[mt][nt][2] - b1 * ua + va,
                                xv.y + rs1 * c[mt][nt][3] - b1 * ub + vb);
            }
        }
    }
}

// ---------------- launch ------------------------------------------------------
extern "C" void kernel_launch(void* const* d_in, const int* in_sizes, int n_in,
                              void* d_out, int out_size)
{
    const float*     x     = (const float*)d_in[0];
    const float*     pos   = (const float*)d_in[1];
    const void*      ei    = d_in[2];
    const float*     ea    = (const float*)d_in[3];
    const float*     e_w1  = (const float*)d_in[4];
    const float*     e_b1  = (const float*)d_in[5];
    const float*     e_g1  = (const float*)d_in[6];
    const float*     e_be1 = (const float*)d_in[7];
    const float*     e_w2  = (const float*)d_in[8];
    const float*     e_b2  = (const float*)d_in[9];
    const float*     e_g2  = (const float*)d_in[10];
    const float*     e_be2 = (const float*)d_in[11];
    const float*     n_w1  = (const float*)d_in[12];
    const float*     n_b1  = (const float*)d_in[13];
    const float*     n_g1  = (const float*)d_in[14];
    const float*     n_be1 = (const float*)d_in[15];
    const float*     n_w2  = (const float*)d_in[16];
    const float*     n_b2  = (const float*)d_in[17];
    const float*     c_w1  = (const float*)d_in[18];
    const float*     c_b1  = (const float*)d_in[19];
    const float*     c_w2  = (const float*)d_in[20];
    const float*     c_b2  = (const float*)d_in[21];

    float* out_x   = (float*)d_out;
    float* out_pos = (float*)d_out + (size_t)NN * FEAT;

    cudaFuncSetAttribute(preab_kernel, cudaFuncAttributeMaxDynamicSharedMemorySize, PB_SMEM);
    cudaFuncSetAttribute(edge_kernel,  cudaFuncAttributeMaxDynamicSharedMemorySize, EDGE_SMEM);
    cudaFuncSetAttribute(node_kernel,  cudaFuncAttributeMaxDynamicSharedMemorySize, ND_SMEM);

    conv_idx_kernel<<<256, 256>>>(ei);
    init_kernel<<<256, 256>>>(pos, out_pos);
    preab_kernel<<<(NN + 127) / 128, 512, PB_SMEM>>>(x, e_w1);
    edge_kernel<<<148, 1024, EDGE_SMEM>>>(pos, ea,
                                          e_w1, e_b1, e_g1, e_be1,
                                          e_w2, e_b2, e_g2, e_be2,
                                          c_w1, c_b1, c_w2, c_b2,
                                          out_pos);
    node_kernel<<<(NN + 127) / 128, 512, ND_SMEM>>>(x, n_w1, n_b1, n_g1, n_be1,
                                                    n_w2, n_b2, out_x);
}

// round 10
// speedup vs baseline: 2.7776x; 1.0219x over previous
#include <cuda_runtime.h>
#include <cstdint>

#define NN   50000
#define EE   800000
#define FEAT 128
#define HID  128
#define EPSL 1e-5f

#define ASTR 132          // MMA A-tile stride (floats)
#define BSTR 136          // MMA weight-tile stride (floats)

// ---------------- scratch (device globals) -----------------------------------
__device__ float g_A[NN * FEAT];      // x @ Wa   (e_w1 rows   0..127)
__device__ float g_B[NN * FEAT];      // x @ Wb   (e_w1 rows 128..255)
__device__ float g_aggm[NN * HID];    // segment-sum of m_ij
__device__ int   g_src[EE];
__device__ int   g_dst[EE];

__device__ __forceinline__ float silu_f(float v) {
    return __fdividef(v, 1.0f + __expf(-v));
}
__device__ __forceinline__ uint32_t f2tf32(float f) {
    uint32_t r; asm("cvt.rna.tf32.f32 %0, %1;" : "=r"(r) : "f"(f)); return r;
}
__device__ __forceinline__ void mma8(float* d, const uint32_t* a, const uint32_t* b) {
    asm volatile("mma.sync.aligned.m16n8k8.row.col.f32.tf32.tf32.f32 "
                 "{%0,%1,%2,%3}, {%4,%5,%6,%7}, {%8,%9}, {%0,%1,%2,%3};"
                 : "+f"(d[0]), "+f"(d[1]), "+f"(d[2]), "+f"(d[3])
                 : "r"(a[0]), "r"(a[1]), "r"(a[2]), "r"(a[3]), "r"(b[0]), "r"(b[1]));
}

// per-warp tf32 GEMM (1024-thr kernels): C[16x32] += A[16x128] * B[128x32]
__device__ __forceinline__ void warp_gemm1(const uint32_t* __restrict__ Au,
                                           const uint32_t* __restrict__ Bu,
                                           float c[4][4],
                                           int mbase, int nbase, int g, int t)
{
#pragma unroll 1
    for (int ks = 0; ks < 16; ks++) {
        int kk = ks * 8;
        uint32_t af[4];
        {
            const uint32_t* p = Au + (mbase + g) * ASTR + kk + t;
            af[0] = p[0];
            af[1] = p[8 * ASTR];
            af[2] = p[4];
            af[3] = p[8 * ASTR + 4];
        }
        uint32_t bf[4][2];
#pragma unroll
        for (int nt = 0; nt < 4; nt++) {
            const uint32_t* p = Bu + (kk + t) * BSTR + nbase + nt * 8 + g;
            bf[nt][0] = p[0];
            bf[nt][1] = p[4 * BSTR];
        }
#pragma unroll
        for (int nt = 0; nt < 4; nt++)
            mma8(c[nt], af, bf[nt]);
    }
}

// per-warp tf32 GEMM (512-thr kernels): C[32x32] += A[32x128] * B[128x32]
__device__ __forceinline__ void warp_gemm2(const uint32_t* __restrict__ Au,
                                           const uint32_t* __restrict__ Bu,
                                           float c[2][4][4],
                                           int mbase, int nbase, int g, int t)
{
#pragma unroll 1
    for (int ks = 0; ks < 16; ks++) {
        int kk = ks * 8;
        uint32_t af[2][4];
#pragma unroll
        for (int mt = 0; mt < 2; mt++) {
            const uint32_t* p = Au + (mbase + mt * 16 + g) * ASTR + kk + t;
            af[mt][0] = p[0];
            af[mt][1] = p[8 * ASTR];
            af[mt][2] = p[4];
            af[mt][3] = p[8 * ASTR + 4];
        }
        uint32_t bf[4][2];
#pragma unroll
        for (int nt = 0; nt < 4; nt++) {
            const uint32_t* p = Bu + (kk + t) * BSTR + nbase + nt * 8 + g;
            bf[nt][0] = p[0];
            bf[nt][1] = p[4 * BSTR];
        }
#pragma unroll
        for (int mt = 0; mt < 2; mt++)
#pragma unroll
            for (int nt = 0; nt < 4; nt++)
                mma8(c[mt][nt], af[mt], bf[nt]);
    }
}

// ---------------- K-1: normalize edge_index dtype ----------------------------
__global__ void conv_idx_kernel(const void* __restrict__ ei_raw)
{
    const long long* e64 = (const long long*)ei_raw;
    const int*       e32 = (const int*)ei_raw;
    bool is64 = true;
#pragma unroll
    for (int j = 0; j < 8; j++) {
        long long v = e64[j];
        if (v < 0 || v >= NN) is64 = false;
    }
    int i = blockIdx.x * blockDim.x + threadIdx.x;
    int stride = gridDim.x * blockDim.x;
    if (is64) {
        for (int e = i; e < EE; e += stride) {
            g_src[e] = (int)e64[e];
            g_dst[e] = (int)e64[EE + e];
        }
    } else {
        for (int e = i; e < EE; e += stride) {
            g_src[e] = e32[e];
            g_dst[e] = e32[EE + e];
        }
    }
}

// ---------------- K0: zero agg_m, pos_out = pos ------------------------------
__global__ void init_kernel(const float* __restrict__ pos, float* __restrict__ out_pos)
{
    int i = blockIdx.x * blockDim.x + threadIdx.x;
    int stride = gridDim.x * blockDim.x;
    for (int j = i; j < NN * HID; j += stride) g_aggm[j] = 0.0f;
    for (int j = i; j < NN * 3;   j += stride) out_pos[j] = pos[j];
}

// ---------------- K1: A = x@Wa, B = x@Wb (tf32 MMA, 512 thr) ------------------
#define PB_SMEM (51712 * 4)
__global__ __launch_bounds__(512, 1)
void preab_kernel(const float* __restrict__ x, const float* __restrict__ e_w1)
{
    extern __shared__ float sm[];
    float* As  = sm;
    float* B1s = sm + 16896;
    float* B2s = sm + 34304;
    const uint32_t* Au  = (const uint32_t*)As;
    const uint32_t* B1u = (const uint32_t*)B1s;
    const uint32_t* B2u = (const uint32_t*)B2s;

    int tid = threadIdx.x, warp = tid >> 5, lane = tid & 31;
    int g = lane >> 2, t = lane & 3;
    int wm = warp >> 2, wn = warp & 3;
    int mbase = wm * 32, nbase = wn * 32;
    int n0 = blockIdx.x * 128;

    for (int idx = tid; idx < 16384; idx += 512) {
        int row = idx >> 7, k = idx & 127;     // As: row=M, k=K ; weights: row=K, k=N
        float v = (n0 + row < NN) ? x[(size_t)(n0 + row) * 128 + k] : 0.f;
        As[row * ASTR + k]  = __uint_as_float(f2tf32(v));
        B1s[row * BSTR + k] = __uint_as_float(f2tf32(e_w1[row * 128 + k]));
        B2s[row * BSTR + k] = __uint_as_float(f2tf32(e_w1[(128 + row) * 128 + k]));
    }
    __syncthreads();

    float c[2][4][4];
#pragma unroll
    for (int mt = 0; mt < 2; mt++)
#pragma unroll
        for (int nt = 0; nt < 4; nt++)
#pragma unroll
            for (int j = 0; j < 4; j++) c[mt][nt][j] = 0.f;
    warp_gemm2(Au, B1u, c, mbase, nbase, g, t);
#pragma unroll
    for (int mt = 0; mt < 2; mt++) {
        int r0 = mbase + mt * 16 + g, r1 = r0 + 8;
#pragma unroll
        for (int nt = 0; nt < 4; nt++) {
            int c0 = nbase + nt * 8 + 2 * t;
            if (n0 + r0 < NN)
                *(float2*)(g_A + (size_t)(n0 + r0) * 128 + c0) = make_float2(c[mt][nt][0], c[mt][nt][1]);
            if (n0 + r1 < NN)
                *(float2*)(g_A + (size_t)(n0 + r1) * 128 + c0) = make_float2(c[mt][nt][2], c[mt][nt][3]);
        }
    }

#pragma unroll
    for (int mt = 0; mt < 2; mt++)
#pragma unroll
        for (int nt = 0; nt < 4; nt++)
#pragma unroll
            for (int j = 0; j < 4; j++) c[mt][nt][j] = 0.f;
    warp_gemm2(Au, B2u, c, mbase, nbase, g, t);
#pragma unroll
    for (int mt = 0; mt < 2; mt++) {
        int r0 = mbase + mt * 16 + g, r1 = r0 + 8;
#pragma unroll
        for (int nt = 0; nt < 4; nt++) {
            int c0 = nbase + nt * 8 + 2 * t;
            if (n0 + r0 < NN)
                *(float2*)(g_B + (size_t)(n0 + r0) * 128 + c0) = make_float2(c[mt][nt][0], c[mt][nt][1]);
            if (n0 + r1 < NN)
                *(float2*)(g_B + (size_t)(n0 + r1) * 128 + c0) = make_float2(c[mt][nt][2], c[mt][nt][3]);
        }
    }
}

// ---------------- K2: persistent edge kernel (mma.sync tf32, 1024 thr) -------
// smem float layout
#define EO_A    0                       // 128*ASTR = 16896
#define EO_B1   16896                   // 128*BSTR = 17408
#define EO_B2   34304
#define EO_SV   51712
// sv float indices (relative to sv)
#define SV_WC0  0
#define SV_WC1  128
#define SV_WD   256
#define SV_B1   384
#define SV_U1   512
#define SV_VB1  640
#define SV_G2   768
#define SV_BE2  896
#define SV_U2   1024
#define SV_VB2  1152
#define SV_CW2  1280
#define SV_RELX 1408
#define SV_RELY 1536
#define SV_RELZ 1664
#define SV_R2   1792
#define SV_EA0  1920
#define SV_EA1  2048
#define SV_MU1  2176
#define SV_RS1  2304
#define SV_SUM  2432   // [128][4] ep1 sums
#define SV_SQ   2944   // [128][4] ep1 sumsq
#define SV_SUM2 3456   // [128][4] ep2 coef partials
#define SV_IDX  3968   // ints: 128 dst, 128 src
#define SV_FLOATS 4224
#define EDGE_SMEM ((EO_SV + SV_FLOATS) * 4)   // 223744 bytes

__global__ __launch_bounds__(1024, 1)
void edge_kernel(const float* __restrict__ pos,
                 const float* __restrict__ ea,
                 const float* __restrict__ e_w1, const float* __restrict__ e_b1,
                 const float* __restrict__ e_g1, const float* __restrict__ e_be1,
                 const float* __restrict__ e_w2, const float* __restrict__ e_b2,
                 const float* __restrict__ e_g2, const float* __restrict__ e_be2,
                 const float* __restrict__ c_w1, const float* __restrict__ c_b1,
                 const float* __restrict__ c_w2, const float* __restrict__ c_b2,
                 float* __restrict__ out_pos)
{
    extern __shared__ float sm[];
    float* As  = sm + EO_A;
    float* B1s = sm + EO_B1;
    float* B2s = sm + EO_B2;
    float* sv  = sm + EO_SV;
    int*   sdst = (int*)(sv + SV_IDX);
    int*   ssrc = sdst + 128;
    const uint32_t* Au  = (const uint32_t*)As;
    const uint32_t* B1u = (const uint32_t*)B1s;
    const uint32_t* B2u = (const uint32_t*)B2s;

    int tid = threadIdx.x, warp = tid >> 5, lane = tid & 31;
    int g = lane >> 2, t = lane & 3;
    int wm = warp >> 2, wn = warp & 3;
    int mbase = wm * 16, nbase = wn * 32;

    // ---- stage LN-folded weights (tf32) + small vectors ----
    for (int idx = tid; idx < 16384; idx += 1024) {
        int k = idx >> 7, n = idx & 127;
        B1s[k * BSTR + n] = __uint_as_float(f2tf32(e_g1[k] * e_w2[k * 128 + n]));
        B2s[k * BSTR + n] = __uint_as_float(f2tf32(e_g2[k] * c_w1[k * 128 + n]));
    }
    if (tid < 128) {
        sv[SV_WC0 + tid] = e_w1[256 * 128 + tid];
        sv[SV_WC1 + tid] = e_w1[257 * 128 + tid];
        sv[SV_WD  + tid] = e_w1[258 * 128 + tid];
        sv[SV_B1  + tid] = e_b1[tid];
        sv[SV_G2  + tid] = e_g2[tid];
        sv[SV_BE2 + tid] = e_be2[tid];
        sv[SV_CW2 + tid] = c_w2[tid];
    }
    if (tid < 512) {
        int quad = tid >> 7, n = tid & 127;
        float acc = 0.f;
        if (quad == 0) {
            for (int k = 0; k < 128; k++) acc += e_g1[k] * e_w2[k * 128 + n];
            sv[SV_U1 + n] = acc;
        } else if (quad == 1) {
            for (int k = 0; k < 128; k++) acc += e_be1[k] * e_w2[k * 128 + n];
            sv[SV_VB1 + n] = acc + e_b2[n];
        } else if (quad == 2) {
            for (int k = 0; k < 128; k++) acc += e_g2[k] * c_w1[k * 128 + n];
            sv[SV_U2 + n] = acc;
        } else {
            for (int k = 0; k < 128; k++) acc += e_be2[k] * c_w1[k * 128 + n];
            sv[SV_VB2 + n] = acc + c_b1[n];
        }
    }
    float cb2 = c_b2[0];
    __syncthreads();

    int k4 = lane * 4;
    bool first = true;

    const int ntiles = EE / 128;
    int tile;
    for (tile = blockIdx.x; tile < ntiles; tile += gridDim.x) {
        int e0 = tile * 128;
        // ---- phase A (tid<128): prev-tile pos atomics + stage edge meta ----
        if (tid < 128) {
            if (!first) {
                float coef = sv[SV_SUM2 + tid * 4] + sv[SV_SUM2 + tid * 4 + 1]
                           + sv[SV_SUM2 + tid * 4 + 2] + sv[SV_SUM2 + tid * 4 + 3] + cb2;
                int dip = sdst[tid];
                atomicAdd(&out_pos[dip * 3 + 0], sv[SV_RELX + tid] * coef);
                atomicAdd(&out_pos[dip * 3 + 1], sv[SV_RELY + tid] * coef);
                atomicAdd(&out_pos[dip * 3 + 2], sv[SV_RELZ + tid] * coef);
            }
            int e = e0 + tid;
            int si = g_src[e], di = g_dst[e];
            float rx = pos[di * 3 + 0] - pos[si * 3 + 0];
            float ry = pos[di * 3 + 1] - pos[si * 3 + 1];
            float rz = pos[di * 3 + 2] - pos[si * 3 + 2];
            ssrc[tid] = si; sdst[tid] = di;
            sv[SV_RELX + tid] = rx; sv[SV_RELY + tid] = ry; sv[SV_RELZ + tid] = rz;
            sv[SV_R2 + tid]  = rx * rx + ry * ry + rz * rz;
            sv[SV_EA0 + tid] = ea[2 * e];
            sv[SV_EA1 + tid] = ea[2 * e + 1];
        }
        first = false;
        __syncthreads();

        // ---- layer-1: gather + SiLU -> As (raw h, tf32); row stats to smem ----
        {
            float4 wc0 = *(const float4*)(sv + SV_WC0 + k4);
            float4 wc1 = *(const float4*)(sv + SV_WC1 + k4);
            float4 wdv = *(const float4*)(sv + SV_WD  + k4);
            float4 b1v = *(const float4*)(sv + SV_B1  + k4);
#pragma unroll 2
            for (int r = 0; r < 4; r++) {
                int row = warp * 4 + r;
                int si = ssrc[row], di = sdst[row];
                float4 a = *(const float4*)(g_A + (size_t)si * 128 + k4);
                float4 b = *(const float4*)(g_B + (size_t)di * 128 + k4);
                float e0v = sv[SV_EA0 + row], e1v = sv[SV_EA1 + row], r2v = sv[SV_R2 + row];
                float4 o;
                o.x = silu_f(a.x + b.x + e0v * wc0.x + e1v * wc1.x + r2v * wdv.x + b1v.x);
                o.y = silu_f(a.y + b.y + e0v * wc0.y + e1v * wc1.y + r2v * wdv.y + b1v.y);
                o.z = silu_f(a.z + b.z + e0v * wc0.z + e1v * wc1.z + r2v * wdv.z + b1v.z);
                o.w = silu_f(a.w + b.w + e0v * wc0.w + e1v * wc1.w + r2v * wdv.w + b1v.w);
                float s = o.x + o.y + o.z + o.w;
                float q = o.x * o.x + o.y * o.y + o.z * o.z + o.w * o.w;
#pragma unroll
                for (int off = 16; off > 0; off >>= 1) {
                    s += __shfl_xor_sync(0xffffffffu, s, off);
                    q += __shfl_xor_sync(0xffffffffu, q, off);
                }
                uint4 tv;
                tv.x = f2tf32(o.x); tv.y = f2tf32(o.y);
                tv.z = f2tf32(o.z); tv.w = f2tf32(o.w);
                *(uint4*)(As + row * ASTR + k4) = tv;
                if (lane == 0) {
                    float mu = s * (1.0f / 128.0f);
                    sv[SV_MU1 + row] = mu;
                    sv[SV_RS1 + row] = rsqrtf(q * (1.0f / 128.0f) - mu * mu + EPSL);
                }
            }
        }
        __syncthreads();

        // ---- GEMM1: h @ (g1 ∘ e_w2) ----
        float c[4][4];
#pragma unroll
        for (int nt = 0; nt < 4; nt++)
#pragma unroll
            for (int j = 0; j < 4; j++) c[nt][j] = 0.f;
        warp_gemm1(Au, B1u, c, mbase, nbase, g, t);
        __syncthreads();   // all warps done reading As before z rewrite

        // ---- ep1: y = rs1*(d - mu1*u1) + vb1 ; z = silu(y) -> As + partials ----
        {
            int r0 = mbase + g, r1 = r0 + 8;
            float rsA = sv[SV_RS1 + r0], bA = rsA * sv[SV_MU1 + r0];
            float rsB = sv[SV_RS1 + r1], bB = rsB * sv[SV_MU1 + r1];
            float s0 = 0.f, q0 = 0.f, s1 = 0.f, q1 = 0.f;
#pragma unroll
            for (int nt = 0; nt < 4; nt++) {
                int c0 = nbase + nt * 8 + 2 * t;
                float u1a = sv[SV_U1 + c0],  u1b = sv[SV_U1 + c0 + 1];
                float vba = sv[SV_VB1 + c0], vbb = sv[SV_VB1 + c0 + 1];
                float z0 = silu_f(rsA * c[nt][0] - bA * u1a + vba);
                float z1 = silu_f(rsA * c[nt][1] - bA * u1b + vbb);
                float z2 = silu_f(rsB * c[nt][2] - bB * u1a + vba);
                float z3 = silu_f(rsB * c[nt][3] - bB * u1b + vbb);
                c[nt][0] = z0; c[nt][1] = z1; c[nt][2] = z2; c[nt][3] = z3;
                uint2 p0; p0.x = f2tf32(z0); p0.y = f2tf32(z1);
                uint2 p1; p1.x = f2tf32(z2); p1.y = f2tf32(z3);
                *(uint2*)(As + r0 * ASTR + c0) = p0;
                *(uint2*)(As + r1 * ASTR + c0) = p1;
                s0 += z0 + z1; q0 += z0 * z0 + z1 * z1;
                s1 += z2 + z3; q1 += z2 * z2 + z3 * z3;
            }
#pragma unroll
            for (int off = 1; off <= 2; off <<= 1) {
                s0 += __shfl_xor_sync(0xffffffffu, s0, off);
                s1 += __shfl_xor_sync(0xffffffffu, s1, off);
                q0 += __shfl_xor_sync(0xffffffffu, q0, off);
                q1 += __shfl_xor_sync(0xffffffffu, q1, off);
            }
            if (t == 0) {
                sv[SV_SUM + r0 * 4 + wn] = s0;
                sv[SV_SQ  + r0 * 4 + wn] = q0;
                sv[SV_SUM + r1 * 4 + wn] = s1;
                sv[SV_SQ  + r1 * 4 + wn] = q1;
            }
        }
        __syncthreads();

        // ---- phase B: local LN2 stats, aggm atomics, GEMM2, ep2 partials ----
        {
            int r0 = mbase + g, r1 = r0 + 8;
            float s0 = sv[SV_SUM + r0 * 4] + sv[SV_SUM + r0 * 4 + 1]
                     + sv[SV_SUM + r0 * 4 + 2] + sv[SV_SUM + r0 * 4 + 3];
            float q0 = sv[SV_SQ + r0 * 4] + sv[SV_SQ + r0 * 4 + 1]
                     + sv[SV_SQ + r0 * 4 + 2] + sv[SV_SQ + r0 * 4 + 3];
            float s1 = sv[SV_SUM + r1 * 4] + sv[SV_SUM + r1 * 4 + 1]
                     + sv[SV_SUM + r1 * 4 + 2] + sv[SV_SUM + r1 * 4 + 3];
            float q1 = sv[SV_SQ + r1 * 4] + sv[SV_SQ + r1 * 4 + 1]
                     + sv[SV_SQ + r1 * 4 + 2] + sv[SV_SQ + r1 * 4 + 3];
            float mu0 = s0 * (1.0f / 128.0f);
            float rs0 = rsqrtf(q0 * (1.0f / 128.0f) - mu0 * mu0 + EPSL);
            float mu1 = s1 * (1.0f / 128.0f);
            float rs1 = rsqrtf(q1 * (1.0f / 128.0f) - mu1 * mu1 + EPSL);

            // aggm atomics: m = (z - mu)*rs*g2 + be2
            int d0 = sdst[r0], d1 = sdst[r1];
#pragma unroll
            for (int nt = 0; nt < 4; nt++) {
                int c0 = nbase + nt * 8 + 2 * t;
                float g2a = sv[SV_G2 + c0],  g2b = sv[SV_G2 + c0 + 1];
                float bea = sv[SV_BE2 + c0], beb = sv[SV_BE2 + c0 + 1];
                float m0 = (c[nt][0] - mu0) * rs0 * g2a + bea;
                float m1 = (c[nt][1] - mu0) * rs0 * g2b + beb;
                float m2 = (c[nt][2] - mu1) * rs1 * g2a + bea;
                float m3 = (c[nt][3] - mu1) * rs1 * g2b + beb;
                asm volatile("red.global.add.v2.f32 [%0], {%1, %2};"
                             :: "l"(g_aggm + (size_t)d0 * 128 + c0), "f"(m0), "f"(m1) : "memory");
                asm volatile("red.global.add.v2.f32 [%0], {%1, %2};"
                             :: "l"(g_aggm + (size_t)d1 * 128 + c0), "f"(m2), "f"(m3) : "memory");
            }

            // GEMM2: z @ (g2 ∘ c_w1)
#pragma unroll
            for (int nt = 0; nt < 4; nt++)
#pragma unroll
                for (int j = 0; j < 4; j++) c[nt][j] = 0.f;
            warp_gemm1(Au, B2u, c, mbase, nbase, g, t);

            // ep2: val = rs*(d - mu*u2) + vb2 ; coef partials -> SUM2
            float b0 = rs0 * mu0, b1 = rs1 * mu1;
            float p0 = 0.f, p1 = 0.f;
#pragma unroll
            for (int nt = 0; nt < 4; nt++) {
                int c0 = nbase + nt * 8 + 2 * t;
                float u2a = sv[SV_U2 + c0],  u2b = sv[SV_U2 + c0 + 1];
                float vba = sv[SV_VB2 + c0], vbb = sv[SV_VB2 + c0 + 1];
                float wa  = sv[SV_CW2 + c0], wb  = sv[SV_CW2 + c0 + 1];
                p0 += silu_f(rs0 * c[nt][0] - b0 * u2a + vba) * wa
                    + silu_f(rs0 * c[nt][1] - b0 * u2b + vbb) * wb;
                p1 += silu_f(rs1 * c[nt][2] - b1 * u2a + vba) * wa
                    + silu_f(rs1 * c[nt][3] - b1 * u2b + vbb) * wb;
            }
#pragma unroll
            for (int off = 1; off <= 2; off <<= 1) {
                p0 += __shfl_xor_sync(0xffffffffu, p0, off);
                p1 += __shfl_xor_sync(0xffffffffu, p1, off);
            }
            if (t == 0) {
                sv[SV_SUM2 + r0 * 4 + wn] = p0;
                sv[SV_SUM2 + r1 * 4 + wn] = p1;
            }
        }
        __syncthreads();
    }

    // ---- final tile's pos atomics ----
    if (tid < 128) {
        float coef = sv[SV_SUM2 + tid * 4] + sv[SV_SUM2 + tid * 4 + 1]
                   + sv[SV_SUM2 + tid * 4 + 2] + sv[SV_SUM2 + tid * 4 + 3] + cb2;
        int di = sdst[tid];
        atomicAdd(&out_pos[di * 3 + 0], sv[SV_RELX + tid] * coef);
        atomicAdd(&out_pos[di * 3 + 1], sv[SV_RELY + tid] * coef);
        atomicAdd(&out_pos[di * 3 + 2], sv[SV_RELZ + tid] * coef);
    }
}

// ---------------- K3: node MLP + residual (tf32 MMA, 512 thr) ----------------
#define NV_B1   0
#define NV_U    128
#define NV_VB   256
#define NV_MU   384
#define NV_RS   512
#define NV_SUM  640    // [128][4]
#define NV_SQ   1152   // [128][4]
#define NV_FLOATS 1664
#define ND_SMEM ((34304 + NV_FLOATS) * 4)
__global__ __launch_bounds__(512, 1)
void node_kernel(const float* __restrict__ x,
                 const float* __restrict__ n_w1, const float* __restrict__ n_b1,
                 const float* __restrict__ n_g1, const float* __restrict__ n_be1,
                 const float* __restrict__ n_w2, const float* __restrict__ n_b2,
                 float* __restrict__ out_x)
{
    extern __shared__ float sm[];
    float* As = sm;
    float* Bs = sm + 16896;
    float* sv = sm + 34304;
    const uint32_t* Au = (const uint32_t*)As;
    const uint32_t* Bu = (const uint32_t*)Bs;

    int tid = threadIdx.x, warp = tid >> 5, lane = tid & 31;
    int g = lane >> 2, t = lane & 3;
    int wm = warp >> 2, wn = warp & 3;
    int mbase = wm * 32, nbase = wn * 32;
    int n0 = blockIdx.x * 128;

    // sv constants
    if (tid < 128) sv[NV_B1 + tid] = n_b1[tid];
    if (tid >= 128 && tid < 384) {
        int half = (tid - 128) >> 7, n = tid & 127;
        float acc = 0.f;
        if (half == 0) {
            for (int k = 0; k < 128; k++) acc += n_g1[k] * n_w2[k * 128 + n];
            sv[NV_U + n] = acc;
        } else {
            for (int k = 0; k < 128; k++) acc += n_be1[k] * n_w2[k * 128 + n];
            sv[NV_VB + n] = acc + n_b2[n];
        }
    }

    // phase 1: x @ W1a
    for (int idx = tid; idx < 16384; idx += 512) {
        int row = idx >> 7, k = idx & 127;
        float v = (n0 + row < NN) ? x[(size_t)(n0 + row) * 128 + k] : 0.f;
        As[row * ASTR + k] = __uint_as_float(f2tf32(v));
        Bs[row * BSTR + k] = __uint_as_float(f2tf32(n_w1[row * 128 + k]));  // row=K idx, k=N idx
    }
    __syncthreads();

    float c[2][4][4];
#pragma unroll
    for (int mt = 0; mt < 2; mt++)
#pragma unroll
        for (int nt = 0; nt < 4; nt++)
#pragma unroll
            for (int j = 0; j < 4; j++) c[mt][nt][j] = 0.f;
    warp_gemm2(Au, Bu, c, mbase, nbase, g, t);
    __syncthreads();

    // phase 2: + aggm @ W1b
    for (int idx = tid; idx < 16384; idx += 512) {
        int row = idx >> 7, k = idx & 127;
        float v = (n0 + row < NN) ? g_aggm[(size_t)(n0 + row) * 128 + k] : 0.f;
        As[row * ASTR + k] = __uint_as_float(f2tf32(v));
        Bs[row * BSTR + k] = __uint_as_float(f2tf32(n_w1[(128 + row) * 128 + k]));
    }
    __syncthreads();
    warp_gemm2(Au, Bu, c, mbase, nbase, g, t);
    __syncthreads();

    // ep1: z = silu(acc + b1) -> As (tf32) + row stats
#pragma unroll
    for (int mt = 0; mt < 2; mt++) {
        int r0 = mbase + mt * 16 + g, r1 = r0 + 8;
        float s0 = 0.f, q0 = 0.f, s1 = 0.f, q1 = 0.f;
#pragma unroll
        for (int nt = 0; nt < 4; nt++) {
            int c0 = nbase + nt * 8 + 2 * t;
            float ba = sv[NV_B1 + c0], bb = sv[NV_B1 + c0 + 1];
            float z0 = silu_f(c[mt][nt][0] + ba);
            float z1 = silu_f(c[mt][nt][1] + bb);
            float z2 = silu_f(c[mt][nt][2] + ba);
            float z3 = silu_f(c[mt][nt][3] + bb);
            uint2 p0; p0.x = f2tf32(z0); p0.y = f2tf32(z1);
            uint2 p1; p1.x = f2tf32(z2); p1.y = f2tf32(z3);
            *(uint2*)(As + r0 * ASTR + c0) = p0;
            *(uint2*)(As + r1 * ASTR + c0) = p1;
            s0 += z0 + z1; q0 += z0 * z0 + z1 * z1;
            s1 += z2 + z3; q1 += z2 * z2 + z3 * z3;
        }
#pragma unroll
        for (int off = 1; off <= 2; off <<= 1) {
            s0 += __shfl_xor_sync(0xffffffffu, s0, off);
            s1 += __shfl_xor_sync(0xffffffffu, s1, off);
            q0 += __shfl_xor_sync(0xffffffffu, q0, off);
            q1 += __shfl_xor_sync(0xffffffffu, q1, off);
        }
        if (t == 0) {
            sv[NV_SUM + r0 * 4 + wn] = s0;
            sv[NV_SQ  + r0 * 4 + wn] = q0;
            sv[NV_SUM + r1 * 4 + wn] = s1;
            sv[NV_SQ  + r1 * 4 + wn] = q1;
        }
    }
    __syncthreads();
    if (tid < 128) {
        float s = sv[NV_SUM + tid * 4] + sv[NV_SUM + tid * 4 + 1]
                + sv[NV_SUM + tid * 4 + 2] + sv[NV_SUM + tid * 4 + 3];
        float q = sv[NV_SQ + tid * 4] + sv[NV_SQ + tid * 4 + 1]
                + sv[NV_SQ + tid * 4 + 2] + sv[NV_SQ + tid * 4 + 3];
        float mu = s * (1.0f / 128.0f);
        sv[NV_MU + tid] = mu;
        sv[NV_RS + tid] = rsqrtf(q * (1.0f / 128.0f) - mu * mu + EPSL);
    }
    // stage (g1 ∘ W2) into Bs
    for (int idx = tid; idx < 16384; idx += 512) {
        int k = idx >> 7, n = idx & 127;
        Bs[k * BSTR + n] = __uint_as_float(f2tf32(n_g1[k] * n_w2[k * 128 + n]));
    }
    __syncthreads();

    // GEMM2: z @ (g1 ∘ W2)
#pragma unroll
    for (int mt = 0; mt < 2; mt++)
#pragma unroll
        for (int nt = 0; nt < 4; nt++)
#pragma unroll
            for (int j = 0; j < 4; j++) c[mt][nt][j] = 0.f;
    warp_gemm2(Au, Bu, c, mbase, nbase, g, t);

    // ep2: out = x + rs*d - rs*mu*u + vb
#pragma unroll
    for (int mt = 0; mt < 2; mt++) {
        int r0 = mbase + mt * 16 + g, r1 = r0 + 8;
        float rs0 = sv[NV_RS + r0], b0 = rs0 * sv[NV_MU + r0];
        float rs1 = sv[NV_RS + r1], b1 = rs1 * sv[NV_MU + r1];
#pragma unroll
        for (int nt = 0; nt < 4; nt++) {
            int c0 = nbase + nt * 8 + 2 * t;
            float ua = sv[NV_U + c0],  ub = sv[NV_U + c0 + 1];
            float va = sv[NV_VB + c0], vb = sv[NV_VB + c0 + 1];
            if (n0 + r0 < NN) {
                float2 xv = *(const float2*)(x + (size_t)(n0 + r0) * 128 + c0);
                *(float2*)(out_x + (size_t)(n0 + r0) * 128 + c0) =
                    make_float2(xv.x + rs0 * c[mt][nt][0] - b0 * ua + va,
                                xv.y + rs0 * c[mt][nt][1] - b0 * ub + vb);
            }
            if (n0 + r1 < NN) {
                float2 xv = *(const float2*)(x + (size_t)(n0 + r1) * 128 + c0);
                *(float2*)(out_x + (size_t)(n0 + r1) * 128 + c0) =
                    make_float2(xv.x + rs1 * c[mt][nt][2] - b1 * ua + va,
                                xv.y + rs1 * c[mt][nt][3] - b1 * ub + vb);
            }
        }
    }
}

// ---------------- launch ------------------------------------------------------
extern "C" void kernel_launch(void* const* d_in, const int* in_sizes, int n_in,
                              void* d_out, int out_size)
{
    const float*     x     = (const float*)d_in[0];
    const float*     pos   = (const float*)d_in[1];
    const void*      ei    = d_in[2];
    const float*     ea    = (const float*)d_in[3];
    const float*     e_w1  = (const float*)d_in[4];
    const float*     e_b1  = (const float*)d_in[5];
    const float*     e_g1  = (const float*)d_in[6];
    const float*     e_be1 = (const float*)d_in[7];
    const float*     e_w2  = (const float*)d_in[8];
    const float*     e_b2  = (const float*)d_in[9];
    const float*     e_g2  = (const float*)d_in[10];
    const float*     e_be2 = (const float*)d_in[11];
    const float*     n_w1  = (const float*)d_in[12];
    const float*     n_b1  = (const float*)d_in[13];
    const float*     n_g1  = (const float*)d_in[14];
    const float*     n_be1 = (const float*)d_in[15];
    const float*     n_w2  = (const float*)d_in[16];
    const float*     n_b2  = (const float*)d_in[17];
    const float*     c_w1  = (const float*)d_in[18];
    const float*     c_b1  = (const float*)d_in[19];
    const float*     c_w2  = (const float*)d_in[20];
    const float*     c_b2  = (const float*)d_in[21];

    float* out_x   = (float*)d_out;
    float* out_pos = (float*)d_out + (size_t)NN * FEAT;

    cudaFuncSetAttribute(preab_kernel, cudaFuncAttributeMaxDynamicSharedMemorySize, PB_SMEM);
    cudaFuncSetAttribute(edge_kernel,  cudaFuncAttributeMaxDynamicSharedMemorySize, EDGE_SMEM);
    cudaFuncSetAttribute(node_kernel,  cudaFuncAttributeMaxDynamicSharedMemorySize, ND_SMEM);

    conv_idx_kernel<<<256, 256>>>(ei);
    init_kernel<<<256, 256>>>(pos, out_pos);
    preab_kernel<<<(NN + 127) / 128, 512, PB_SMEM>>>(x, e_w1);
    edge_kernel<<<148, 1024, EDGE_SMEM>>>(pos, ea,
                                          e_w1, e_b1, e_g1, e_be1,
                                          e_w2, e_b2, e_g2, e_be2,
                                          c_w1, c_b1, c_w2, c_b2,
                                          out_pos);
    node_kernel<<<(NN + 127) / 128, 512, ND_SMEM>>>(x, n_w1, n_b1, n_g1, n_be1,
                                                    n_w2, n_b2, out_x);
}

// round 11
// speedup vs baseline: 2.9615x; 1.0662x over previous
#include <cuda_runtime.h>
#include <cstdint>

#define NN   50000
#define EE   800000
#define FEAT 128
#define HID  128
#define EPSL 1e-5f

#define ASTR 132          // MMA A-tile stride (floats)
#define BSTR 136          // MMA weight-tile stride (floats)

// ---------------- scratch (device globals) -----------------------------------
__device__ float g_A[NN * FEAT];      // x @ Wa   (e_w1 rows   0..127)
__device__ float g_B[NN * FEAT];      // x @ Wb   (e_w1 rows 128..255)
__device__ float g_aggm[NN * HID];    // segment-sum of m_ij
__device__ int   g_src[EE];
__device__ int   g_dst[EE];

__device__ __forceinline__ float silu_f(float v) {
    return __fdividef(v, 1.0f + __expf(-v));
}
__device__ __forceinline__ uint32_t f2tf32(float f) {
    uint32_t r; asm("cvt.rna.tf32.f32 %0, %1;" : "=r"(r) : "f"(f)); return r;
}
__device__ __forceinline__ void mma8(float* d, const uint32_t* a, const uint32_t* b) {
    asm volatile("mma.sync.aligned.m16n8k8.row.col.f32.tf32.tf32.f32 "
                 "{%0,%1,%2,%3}, {%4,%5,%6,%7}, {%8,%9}, {%0,%1,%2,%3};"
                 : "+f"(d[0]), "+f"(d[1]), "+f"(d[2]), "+f"(d[3])
                 : "r"(a[0]), "r"(a[1]), "r"(a[2]), "r"(a[3]), "r"(b[0]), "r"(b[1]));
}

// per-warp tf32 GEMM: C[16x32] += A[16x128] * B[128x32]
__device__ __forceinline__ void warp_gemm1(const uint32_t* __restrict__ Au,
                                           const uint32_t* __restrict__ Bu,
                                           float c[4][4],
                                           int mbase, int nbase, int g, int t)
{
#pragma unroll 1
    for (int ks = 0; ks < 16; ks++) {
        int kk = ks * 8;
        uint32_t af[4];
        {
            const uint32_t* p = Au + (mbase + g) * ASTR + kk + t;
            af[0] = p[0];
            af[1] = p[8 * ASTR];
            af[2] = p[4];
            af[3] = p[8 * ASTR + 4];
        }
        uint32_t bf[4][2];
#pragma unroll
        for (int nt = 0; nt < 4; nt++) {
            const uint32_t* p = Bu + (kk + t) * BSTR + nbase + nt * 8 + g;
            bf[nt][0] = p[0];
            bf[nt][1] = p[4 * BSTR];
        }
#pragma unroll
        for (int nt = 0; nt < 4; nt++)
            mma8(c[nt], af, bf[nt]);
    }
}

// per-warp tf32 GEMM (512-thr kernels): C[32x32] += A[32x128] * B[128x32]
__device__ __forceinline__ void warp_gemm2(const uint32_t* __restrict__ Au,
                                           const uint32_t* __restrict__ Bu,
                                           float c[2][4][4],
                                           int mbase, int nbase, int g, int t)
{
#pragma unroll 1
    for (int ks = 0; ks < 16; ks++) {
        int kk = ks * 8;
        uint32_t af[2][4];
#pragma unroll
        for (int mt = 0; mt < 2; mt++) {
            const uint32_t* p = Au + (mbase + mt * 16 + g) * ASTR + kk + t;
            af[mt][0] = p[0];
            af[mt][1] = p[8 * ASTR];
            af[mt][2] = p[4];
            af[mt][3] = p[8 * ASTR + 4];
        }
        uint32_t bf[4][2];
#pragma unroll
        for (int nt = 0; nt < 4; nt++) {
            const uint32_t* p = Bu + (kk + t) * BSTR + nbase + nt * 8 + g;
            bf[nt][0] = p[0];
            bf[nt][1] = p[4 * BSTR];
        }
#pragma unroll
        for (int mt = 0; mt < 2; mt++)
#pragma unroll
            for (int nt = 0; nt < 4; nt++)
                mma8(c[mt][nt], af[mt], bf[nt]);
    }
}

// ---------------- K-1: normalize edge_index dtype ----------------------------
__global__ void conv_idx_kernel(const void* __restrict__ ei_raw)
{
    const long long* e64 = (const long long*)ei_raw;
    const int*       e32 = (const int*)ei_raw;
    bool is64 = true;
#pragma unroll
    for (int j = 0; j < 8; j++) {
        long long v = e64[j];
        if (v < 0 || v >= NN) is64 = false;
    }
    int i = blockIdx.x * blockDim.x + threadIdx.x;
    int stride = gridDim.x * blockDim.x;
    if (is64) {
        for (int e = i; e < EE; e += stride) {
            g_src[e] = (int)e64[e];
            g_dst[e] = (int)e64[EE + e];
        }
    } else {
        for (int e = i; e < EE; e += stride) {
            g_src[e] = e32[e];
            g_dst[e] = e32[EE + e];
        }
    }
}

// ---------------- K0: zero agg_m, pos_out = pos ------------------------------
__global__ void init_kernel(const float* __restrict__ pos, float* __restrict__ out_pos)
{
    int i = blockIdx.x * blockDim.x + threadIdx.x;
    int stride = gridDim.x * blockDim.x;
    for (int j = i; j < NN * HID; j += stride) g_aggm[j] = 0.0f;
    for (int j = i; j < NN * 3;   j += stride) out_pos[j] = pos[j];
}

// ---------------- K1: A = x@Wa, B = x@Wb (tf32 MMA, 512 thr) ------------------
#define PB_SMEM (51712 * 4)
__global__ __launch_bounds__(512, 1)
void preab_kernel(const float* __restrict__ x, const float* __restrict__ e_w1)
{
    extern __shared__ float sm[];
    float* As  = sm;
    float* B1s = sm + 16896;
    float* B2s = sm + 34304;
    const uint32_t* Au  = (const uint32_t*)As;
    const uint32_t* B1u = (const uint32_t*)B1s;
    const uint32_t* B2u = (const uint32_t*)B2s;

    int tid = threadIdx.x, warp = tid >> 5, lane = tid & 31;
    int g = lane >> 2, t = lane & 3;
    int wm = warp >> 2, wn = warp & 3;
    int mbase = wm * 32, nbase = wn * 32;
    int n0 = blockIdx.x * 128;

    for (int idx = tid; idx < 16384; idx += 512) {
        int row = idx >> 7, k = idx & 127;
        float v = (n0 + row < NN) ? x[(size_t)(n0 + row) * 128 + k] : 0.f;
        As[row * ASTR + k]  = __uint_as_float(f2tf32(v));
        B1s[row * BSTR + k] = __uint_as_float(f2tf32(e_w1[row * 128 + k]));
        B2s[row * BSTR + k] = __uint_as_float(f2tf32(e_w1[(128 + row) * 128 + k]));
    }
    __syncthreads();

    float c[2][4][4];
#pragma unroll
    for (int mt = 0; mt < 2; mt++)
#pragma unroll
        for (int nt = 0; nt < 4; nt++)
#pragma unroll
            for (int j = 0; j < 4; j++) c[mt][nt][j] = 0.f;
    warp_gemm2(Au, B1u, c, mbase, nbase, g, t);
#pragma unroll
    for (int mt = 0; mt < 2; mt++) {
        int r0 = mbase + mt * 16 + g, r1 = r0 + 8;
#pragma unroll
        for (int nt = 0; nt < 4; nt++) {
            int c0 = nbase + nt * 8 + 2 * t;
            if (n0 + r0 < NN)
                *(float2*)(g_A + (size_t)(n0 + r0) * 128 + c0) = make_float2(c[mt][nt][0], c[mt][nt][1]);
            if (n0 + r1 < NN)
                *(float2*)(g_A + (size_t)(n0 + r1) * 128 + c0) = make_float2(c[mt][nt][2], c[mt][nt][3]);
        }
    }

#pragma unroll
    for (int mt = 0; mt < 2; mt++)
#pragma unroll
        for (int nt = 0; nt < 4; nt++)
#pragma unroll
            for (int j = 0; j < 4; j++) c[mt][nt][j] = 0.f;
    warp_gemm2(Au, B2u, c, mbase, nbase, g, t);
#pragma unroll
    for (int mt = 0; mt < 2; mt++) {
        int r0 = mbase + mt * 16 + g, r1 = r0 + 8;
#pragma unroll
        for (int nt = 0; nt < 4; nt++) {
            int c0 = nbase + nt * 8 + 2 * t;
            if (n0 + r0 < NN)
                *(float2*)(g_B + (size_t)(n0 + r0) * 128 + c0) = make_float2(c[mt][nt][0], c[mt][nt][1]);
            if (n0 + r1 < NN)
                *(float2*)(g_B + (size_t)(n0 + r1) * 128 + c0) = make_float2(c[mt][nt][2], c[mt][nt][3]);
        }
    }
}

// ---------------- K2: persistent edge kernel ----------------------------------
// Two independent 512-thread groups per CTA, each on its own 64-edge tile
// stream with its own A half-tile and scratch; named barriers per group.
// smem float layout
#define EO_A    0                       // 2 groups x 64 x ASTR = 16896
#define EO_B1   16896                   // 128*BSTR = 17408
#define EO_B2   34304
#define EO_SV   51712                   // shared constants (1408 floats)
#define EO_GRP  53120                   // per-group scratch, 1408 floats each
// shared const indices (relative to sv)
#define SV_WC0  0
#define SV_WC1  128
#define SV_WD   256
#define SV_B1   384
#define SV_U1   512
#define SV_VB1  640
#define SV_G2   768
#define SV_BE2  896
#define SV_U2   1024
#define SV_VB2  1152
#define SV_CW2  1280
// per-group indices (relative to gsv)
#define GV_RELX 0
#define GV_RELY 64
#define GV_RELZ 128
#define GV_R2   192
#define GV_EA0  256
#define GV_EA1  320
#define GV_MU1  384
#define GV_RS1  448
#define GV_SUM  512    // [64][4]
#define GV_SQ   768    // [64][4]
#define GV_SUM2 1024   // [64][4]
#define GV_IDX  1280   // ints: 64 dst, 64 src
#define GRP_FLOATS 1408
#define EDGE_SMEM ((EO_GRP + 2 * GRP_FLOATS) * 4)   // 223744 bytes

#define BARG(id) asm volatile("bar.sync %0, 512;" :: "r"(id) : "memory")

__global__ __launch_bounds__(1024, 1)
void edge_kernel(const float* __restrict__ pos,
                 const float* __restrict__ ea,
                 const float* __restrict__ e_w1, const float* __restrict__ e_b1,
                 const float* __restrict__ e_g1, const float* __restrict__ e_be1,
                 const float* __restrict__ e_w2, const float* __restrict__ e_b2,
                 const float* __restrict__ e_g2, const float* __restrict__ e_be2,
                 const float* __restrict__ c_w1, const float* __restrict__ c_b1,
                 const float* __restrict__ c_w2, const float* __restrict__ c_b2,
                 float* __restrict__ out_pos)
{
    extern __shared__ float sm[];
    float* B1s = sm + EO_B1;
    float* B2s = sm + EO_B2;
    float* sv  = sm + EO_SV;
    const uint32_t* B1u = (const uint32_t*)B1s;
    const uint32_t* B2u = (const uint32_t*)B2s;

    int tid = threadIdx.x, warp = tid >> 5, lane = tid & 31;
    int gid = warp >> 4;            // group 0 / 1
    int wig = warp & 15;            // warp in group
    int gtid = tid & 511;           // thread id in group
    int bar = gid + 1;              // named barrier id
    int g = lane >> 2, t = lane & 3;
    int wm = wig >> 2, wn = wig & 3;
    int mbase = wm * 16, nbase = wn * 32;

    float* As  = sm + EO_A + gid * (64 * ASTR);
    float* gsv = sm + EO_GRP + gid * GRP_FLOATS;
    int*   gdst = (int*)(gsv + GV_IDX);
    int*   gsrc = gdst + 64;
    const uint32_t* Au = (const uint32_t*)As;

    // ---- stage LN-folded weights (tf32) + shared constants (all 1024 thr) ----
    for (int idx = tid; idx < 16384; idx += 1024) {
        int k = idx >> 7, n = idx & 127;
        B1s[k * BSTR + n] = __uint_as_float(f2tf32(e_g1[k] * e_w2[k * 128 + n]));
        B2s[k * BSTR + n] = __uint_as_float(f2tf32(e_g2[k] * c_w1[k * 128 + n]));
    }
    if (tid < 128) {
        sv[SV_WC0 + tid] = e_w1[256 * 128 + tid];
        sv[SV_WC1 + tid] = e_w1[257 * 128 + tid];
        sv[SV_WD  + tid] = e_w1[258 * 128 + tid];
        sv[SV_B1  + tid] = e_b1[tid];
        sv[SV_G2  + tid] = e_g2[tid];
        sv[SV_BE2 + tid] = e_be2[tid];
        sv[SV_CW2 + tid] = c_w2[tid];
    }
    if (tid < 512) {
        int quad = tid >> 7, n = tid & 127;
        float acc = 0.f;
        if (quad == 0) {
            for (int k = 0; k < 128; k++) acc += e_g1[k] * e_w2[k * 128 + n];
            sv[SV_U1 + n] = acc;
        } else if (quad == 1) {
            for (int k = 0; k < 128; k++) acc += e_be1[k] * e_w2[k * 128 + n];
            sv[SV_VB1 + n] = acc + e_b2[n];
        } else if (quad == 2) {
            for (int k = 0; k < 128; k++) acc += e_g2[k] * c_w1[k * 128 + n];
            sv[SV_U2 + n] = acc;
        } else {
            for (int k = 0; k < 128; k++) acc += e_be2[k] * c_w1[k * 128 + n];
            sv[SV_VB2 + n] = acc + c_b1[n];
        }
    }
    float cb2 = c_b2[0];
    __syncthreads();

    int k4 = lane * 4;
    bool first = true;

    const int ntiles = EE / 64;   // 12500
    for (int tile = blockIdx.x * 2 + gid; tile < ntiles; tile += 2 * gridDim.x) {
        int e0 = tile * 64;
        // ---- phase A (gtid<64): prev-tile pos atomics + stage edge meta ----
        if (gtid < 64) {
            if (!first) {
                float coef = gsv[GV_SUM2 + gtid * 4] + gsv[GV_SUM2 + gtid * 4 + 1]
                           + gsv[GV_SUM2 + gtid * 4 + 2] + gsv[GV_SUM2 + gtid * 4 + 3] + cb2;
                int dip = gdst[gtid];
                atomicAdd(&out_pos[dip * 3 + 0], gsv[GV_RELX + gtid] * coef);
                atomicAdd(&out_pos[dip * 3 + 1], gsv[GV_RELY + gtid] * coef);
                atomicAdd(&out_pos[dip * 3 + 2], gsv[GV_RELZ + gtid] * coef);
            }
            int e = e0 + gtid;
            int si = g_src[e], di = g_dst[e];
            float rx = pos[di * 3 + 0] - pos[si * 3 + 0];
            float ry = pos[di * 3 + 1] - pos[si * 3 + 1];
            float rz = pos[di * 3 + 2] - pos[si * 3 + 2];
            gsrc[gtid] = si; gdst[gtid] = di;
            gsv[GV_RELX + gtid] = rx; gsv[GV_RELY + gtid] = ry; gsv[GV_RELZ + gtid] = rz;
            gsv[GV_R2 + gtid]  = rx * rx + ry * ry + rz * rz;
            gsv[GV_EA0 + gtid] = ea[2 * e];
            gsv[GV_EA1 + gtid] = ea[2 * e + 1];
        }
        first = false;
        BARG(bar);

        // ---- layer-1: gather + SiLU -> As (raw h, tf32); row stats ----
        {
            float4 wc0 = *(const float4*)(sv + SV_WC0 + k4);
            float4 wc1 = *(const float4*)(sv + SV_WC1 + k4);
            float4 wdv = *(const float4*)(sv + SV_WD  + k4);
            float4 b1v = *(const float4*)(sv + SV_B1  + k4);
#pragma unroll 2
            for (int r = 0; r < 4; r++) {
                int row = wig * 4 + r;
                int si = gsrc[row], di = gdst[row];
                float4 a = *(const float4*)(g_A + (size_t)si * 128 + k4);
                float4 b = *(const float4*)(g_B + (size_t)di * 128 + k4);
                float e0v = gsv[GV_EA0 + row], e1v = gsv[GV_EA1 + row], r2v = gsv[GV_R2 + row];
                float4 o;
                o.x = silu_f(a.x + b.x + e0v * wc0.x + e1v * wc1.x + r2v * wdv.x + b1v.x);
                o.y = silu_f(a.y + b.y + e0v * wc0.y + e1v * wc1.y + r2v * wdv.y + b1v.y);
                o.z = silu_f(a.z + b.z + e0v * wc0.z + e1v * wc1.z + r2v * wdv.z + b1v.z);
                o.w = silu_f(a.w + b.w + e0v * wc0.w + e1v * wc1.w + r2v * wdv.w + b1v.w);
                float s = o.x + o.y + o.z + o.w;
                float q = o.x * o.x + o.y * o.y + o.z * o.z + o.w * o.w;
#pragma unroll
                for (int off = 16; off > 0; off >>= 1) {
                    s += __shfl_xor_sync(0xffffffffu, s, off);
                    q += __shfl_xor_sync(0xffffffffu, q, off);
                }
                uint4 tv;
                tv.x = f2tf32(o.x); tv.y = f2tf32(o.y);
                tv.z = f2tf32(o.z); tv.w = f2tf32(o.w);
                *(uint4*)(As + row * ASTR + k4) = tv;
                if (lane == 0) {
                    float mu = s * (1.0f / 128.0f);
                    gsv[GV_MU1 + row] = mu;
                    gsv[GV_RS1 + row] = rsqrtf(q * (1.0f / 128.0f) - mu * mu + EPSL);
                }
            }
        }
        BARG(bar);

        // ---- GEMM1: h @ (g1 ∘ e_w2) ----
        float c[4][4];
#pragma unroll
        for (int nt = 0; nt < 4; nt++)
#pragma unroll
            for (int j = 0; j < 4; j++) c[nt][j] = 0.f;
        warp_gemm1(Au, B1u, c, mbase, nbase, g, t);
        BARG(bar);   // group done reading As before z rewrite

        // ---- ep1: y = rs1*(d - mu1*u1) + vb1 ; z = silu(y) -> As + partials ----
        {
            int r0 = mbase + g, r1 = r0 + 8;
            float rsA = gsv[GV_RS1 + r0], bA = rsA * gsv[GV_MU1 + r0];
            float rsB = gsv[GV_RS1 + r1], bB = rsB * gsv[GV_MU1 + r1];
            float s0 = 0.f, q0 = 0.f, s1 = 0.f, q1 = 0.f;
#pragma unroll
            for (int nt = 0; nt < 4; nt++) {
                int c0 = nbase + nt * 8 + 2 * t;
                float u1a = sv[SV_U1 + c0],  u1b = sv[SV_U1 + c0 + 1];
                float vba = sv[SV_VB1 + c0], vbb = sv[SV_VB1 + c0 + 1];
                float z0 = silu_f(rsA * c[nt][0] - bA * u1a + vba);
                float z1 = silu_f(rsA * c[nt][1] - bA * u1b + vbb);
                float z2 = silu_f(rsB * c[nt][2] - bB * u1a + vba);
                float z3 = silu_f(rsB * c[nt][3] - bB * u1b + vbb);
                c[nt][0] = z0; c[nt][1] = z1; c[nt][2] = z2; c[nt][3] = z3;
                uint2 p0; p0.x = f2tf32(z0); p0.y = f2tf32(z1);
                uint2 p1; p1.x = f2tf32(z2); p1.y = f2tf32(z3);
                *(uint2*)(As + r0 * ASTR + c0) = p0;
                *(uint2*)(As + r1 * ASTR + c0) = p1;
                s0 += z0 + z1; q0 += z0 * z0 + z1 * z1;
                s1 += z2 + z3; q1 += z2 * z2 + z3 * z3;
            }
#pragma unroll
            for (int off = 1; off <= 2; off <<= 1) {
                s0 += __shfl_xor_sync(0xffffffffu, s0, off);
                s1 += __shfl_xor_sync(0xffffffffu, s1, off);
                q0 += __shfl_xor_sync(0xffffffffu, q0, off);
                q1 += __shfl_xor_sync(0xffffffffu, q1, off);
            }
            if (t == 0) {
                gsv[GV_SUM + r0 * 4 + wn] = s0;
                gsv[GV_SQ  + r0 * 4 + wn] = q0;
                gsv[GV_SUM + r1 * 4 + wn] = s1;
                gsv[GV_SQ  + r1 * 4 + wn] = q1;
            }
        }
        BARG(bar);

        // ---- phase B: local LN2 stats, aggm atomics, GEMM2, ep2 partials ----
        {
            int r0 = mbase + g, r1 = r0 + 8;
            float s0 = gsv[GV_SUM + r0 * 4] + gsv[GV_SUM + r0 * 4 + 1]
                     + gsv[GV_SUM + r0 * 4 + 2] + gsv[GV_SUM + r0 * 4 + 3];
            float q0 = gsv[GV_SQ + r0 * 4] + gsv[GV_SQ + r0 * 4 + 1]
                     + gsv[GV_SQ + r0 * 4 + 2] + gsv[GV_SQ + r0 * 4 + 3];
            float s1 = gsv[GV_SUM + r1 * 4] + gsv[GV_SUM + r1 * 4 + 1]
                     + gsv[GV_SUM + r1 * 4 + 2] + gsv[GV_SUM + r1 * 4 + 3];
            float q1 = gsv[GV_SQ + r1 * 4] + gsv[GV_SQ + r1 * 4 + 1]
                     + gsv[GV_SQ + r1 * 4 + 2] + gsv[GV_SQ + r1 * 4 + 3];
            float mu0 = s0 * (1.0f / 128.0f);
            float rs0 = rsqrtf(q0 * (1.0f / 128.0f) - mu0 * mu0 + EPSL);
            float mu1 = s1 * (1.0f / 128.0f);
            float rs1 = rsqrtf(q1 * (1.0f / 128.0f) - mu1 * mu1 + EPSL);

            // aggm atomics: m = (z - mu)*rs*g2 + be2
            int d0 = gdst[r0], d1 = gdst[r1];
#pragma unroll
            for (int nt = 0; nt < 4; nt++) {
                int c0 = nbase + nt * 8 + 2 * t;
                float g2a = sv[SV_G2 + c0],  g2b = sv[SV_G2 + c0 + 1];
                float bea = sv[SV_BE2 + c0], beb = sv[SV_BE2 + c0 + 1];
                float m0 = (c[nt][0] - mu0) * rs0 * g2a + bea;
                float m1 = (c[nt][1] - mu0) * rs0 * g2b + beb;
                float m2 = (c[nt][2] - mu1) * rs1 * g2a + bea;
                float m3 = (c[nt][3] - mu1) * rs1 * g2b + beb;
                asm volatile("red.global.add.v2.f32 [%0], {%1, %2};"
                             :: "l"(g_aggm + (size_t)d0 * 128 + c0), "f"(m0), "f"(m1) : "memory");
                asm volatile("red.global.add.v2.f32 [%0], {%1, %2};"
                             :: "l"(g_aggm + (size_t)d1 * 128 + c0), "f"(m2), "f"(m3) : "memory");
            }

            // GEMM2: z @ (g2 ∘ c_w1)
#pragma unroll
            for (int nt = 0; nt < 4; nt++)
#pragma unroll
                for (int j = 0; j < 4; j++) c[nt][j] = 0.f;
            warp_gemm1(Au, B2u, c, mbase, nbase, g, t);

            // ep2: val = rs*(d - mu*u2) + vb2 ; coef partials -> SUM2
            float b0 = rs0 * mu0, b1 = rs1 * mu1;
            float p0 = 0.f, p1 = 0.f;
#pragma unroll
            for (int nt = 0; nt < 4; nt++) {
                int c0 = nbase + nt * 8 + 2 * t;
                float u2a = sv[SV_U2 + c0],  u2b = sv[SV_U2 + c0 + 1];
                float vba = sv[SV_VB2 + c0], vbb = sv[SV_VB2 + c0 + 1];
                float wa  = sv[SV_CW2 + c0], wb  = sv[SV_CW2 + c0 + 1];
                p0 += silu_f(rs0 * c[nt][0] - b0 * u2a + vba) * wa
                    + silu_f(rs0 * c[nt][1] - b0 * u2b + vbb) * wb;
                p1 += silu_f(rs1 * c[nt][2] - b1 * u2a + vba) * wa
                    + silu_f(rs1 * c[nt][3] - b1 * u2b + vbb) * wb;
            }
#pragma unroll
            for (int off = 1; off <= 2; off <<= 1) {
                p0 += __shfl_xor_sync(0xffffffffu, p0, off);
                p1 += __shfl_xor_sync(0xffffffffu, p1, off);
            }
            if (t == 0) {
                gsv[GV_SUM2 + r0 * 4 + wn] = p0;
                gsv[GV_SUM2 + r1 * 4 + wn] = p1;
            }
        }
        BARG(bar);
    }

    // ---- final tile's pos atomics (per group) ----
    if (!first && gtid < 64) {
        float coef = gsv[GV_SUM2 + gtid * 4] + gsv[GV_SUM2 + gtid * 4 + 1]
                   + gsv[GV_SUM2 + gtid * 4 + 2] + gsv[GV_SUM2 + gtid * 4 + 3] + cb2;
        int di = gdst[gtid];
        atomicAdd(&out_pos[di * 3 + 0], gsv[GV_RELX + gtid] * coef);
        atomicAdd(&out_pos[di * 3 + 1], gsv[GV_RELY + gtid] * coef);
        atomicAdd(&out_pos[di * 3 + 2], gsv[GV_RELZ + gtid] * coef);
    }
}

// ---------------- K3: node MLP + residual (tf32 MMA, 512 thr) ----------------
#define NV_B1   0
#define NV_U    128
#define NV_VB   256
#define NV_MU   384
#define NV_RS   512
#define NV_SUM  640    // [128][4]
#define NV_SQ   1152   // [128][4]
#define NV_FLOATS 1664
#define ND_SMEM ((34304 + NV_FLOATS) * 4)
__global__ __launch_bounds__(512, 1)
void node_kernel(const float* __restrict__ x,
                 const float* __restrict__ n_w1, const float* __restrict__ n_b1,
                 const float* __restrict__ n_g1, const float* __restrict__ n_be1,
                 const float* __restrict__ n_w2, const float* __restrict__ n_b2,
                 float* __restrict__ out_x)
{
    extern __shared__ float sm[];
    float* As = sm;
    float* Bs = sm + 16896;
    float* sv = sm + 34304;
    const uint32_t* Au = (const uint32_t*)As;
    const uint32_t* Bu = (const uint32_t*)Bs;

    int tid = threadIdx.x, warp = tid >> 5, lane = tid & 31;
    int g = lane >> 2, t = lane & 3;
    int wm = warp >> 2, wn = warp & 3;
    int mbase = wm * 32, nbase = wn * 32;
    int n0 = blockIdx.x * 128;

    // sv constants
    if (tid < 128) sv[NV_B1 + tid] = n_b1[tid];
    if (tid >= 128 && tid < 384) {
        int half = (tid - 128) >> 7, n = tid & 127;
        float acc = 0.f;
        if (half == 0) {
            for (int k = 0; k < 128; k++) acc += n_g1[k] * n_w2[k * 128 + n];
            sv[NV_U + n] = acc;
        } else {
            for (int k = 0; k < 128; k++) acc += n_be1[k] * n_w2[k * 128 + n];
            sv[NV_VB + n] = acc + n_b2[n];
        }
    }

    // phase 1: x @ W1a
    for (int idx = tid; idx < 16384; idx += 512) {
        int row = idx >> 7, k = idx & 127;
        float v = (n0 + row < NN) ? x[(size_t)(n0 + row) * 128 + k] : 0.f;
        As[row * ASTR + k] = __uint_as_float(f2tf32(v));
        Bs[row * BSTR + k] = __uint_as_float(f2tf32(n_w1[row * 128 + k]));
    }
    __syncthreads();

    float c[2][4][4];
#pragma unroll
    for (int mt = 0; mt < 2; mt++)
#pragma unroll
        for (int nt = 0; nt < 4; nt++)
#pragma unroll
            for (int j = 0; j < 4; j++) c[mt][nt][j] = 0.f;
    warp_gemm2(Au, Bu, c, mbase, nbase, g, t);
    __syncthreads();

    // phase 2: + aggm @ W1b
    for (int idx = tid; idx < 16384; idx += 512) {
        int row = idx >> 7, k = idx & 127;
        float v = (n0 + row < NN) ? g_aggm[(size_t)(n0 + row) * 128 + k] : 0.f;
        As[row * ASTR + k] = __uint_as_float(f2tf32(v));
        Bs[row * BSTR + k] = __uint_as_float(f2tf32(n_w1[(128 + row) * 128 + k]));
    }
    __syncthreads();
    warp_gemm2(Au, Bu, c, mbase, nbase, g, t);
    __syncthreads();

    // ep1: z = silu(acc + b1) -> As (tf32) + row stats
#pragma unroll
    for (int mt = 0; mt < 2; mt++) {
        int r0 = mbase + mt * 16 + g, r1 = r0 + 8;
        float s0 = 0.f, q0 = 0.f, s1 = 0.f, q1 = 0.f;
#pragma unroll
        for (int nt = 0; nt < 4; nt++) {
            int c0 = nbase + nt * 8 + 2 * t;
            float ba = sv[NV_B1 + c0], bb = sv[NV_B1 + c0 + 1];
            float z0 = silu_f(c[mt][nt][0] + ba);
            float z1 = silu_f(c[mt][nt][1] + bb);
            float z2 = silu_f(c[mt][nt][2] + ba);
            float z3 = silu_f(c[mt][nt][3] + bb);
            uint2 p0; p0.x = f2tf32(z0); p0.y = f2tf32(z1);
            uint2 p1; p1.x = f2tf32(z2); p1.y = f2tf32(z3);
            *(uint2*)(As + r0 * ASTR + c0) = p0;
            *(uint2*)(As + r1 * ASTR + c0) = p1;
            s0 += z0 + z1; q0 += z0 * z0 + z1 * z1;
            s1 += z2 + z3; q1 += z2 * z2 + z3 * z3;
        }
#pragma unroll
        for (int off = 1; off <= 2; off <<= 1) {
            s0 += __shfl_xor_sync(0xffffffffu, s0, off);
            s1 += __shfl_xor_sync(0xffffffffu, s1, off);
            q0 += __shfl_xor_sync(0xffffffffu, q0, off);
            q1 += __shfl_xor_sync(0xffffffffu, q1, off);
        }
        if (t == 0) {
            sv[NV_SUM + r0 * 4 + wn] = s0;
            sv[NV_SQ  + r0 * 4 + wn] = q0;
            sv[NV_SUM + r1 * 4 + wn] = s1;
            sv[NV_SQ  + r1 * 4 + wn] = q1;
        }
    }
    __syncthreads();
    if (tid < 128) {
        float s = sv[NV_SUM + tid * 4] + sv[NV_SUM + tid * 4 + 1]
                + sv[NV_SUM + tid * 4 + 2] + sv[NV_SUM + tid * 4 + 3];
        float q = sv[NV_SQ + tid * 4] + sv[NV_SQ + tid * 4 + 1]
                + sv[NV_SQ + tid * 4 + 2] + sv[NV_SQ + tid * 4 + 3];
        float mu = s * (1.0f / 128.0f);
        sv[NV_MU + tid] = mu;
        sv[NV_RS + tid] = rsqrtf(q * (1.0f / 128.0f) - mu * mu + EPSL);
    }
    // stage (g1 ∘ W2) into Bs
    for (int idx = tid; idx < 16384; idx += 512) {
        int k = idx >> 7, n = idx & 127;
        Bs[k * BSTR + n] = __uint_as_float(f2tf32(n_g1[k] * n_w2[k * 128 + n]));
    }
    __syncthreads();

    // GEMM2: z @ (g1 ∘ W2)
#pragma unroll
    for (int mt = 0; mt < 2; mt++)
#pragma unroll
        for (int nt = 0; nt < 4; nt++)
#pragma unroll
            for (int j = 0; j < 4; j++) c[mt][nt][j] = 0.f;
    warp_gemm2(Au, Bu, c, mbase, nbase, g, t);

    // ep2: out = x + rs*d - rs*mu*u + vb
#pragma unroll
    for (int mt = 0; mt < 2; mt++) {
        int r0 = mbase + mt * 16 + g, r1 = r0 + 8;
        float rs0 = sv[NV_RS + r0], b0 = rs0 * sv[NV_MU + r0];
        float rs1 = sv[NV_RS + r1], b1 = rs1 * sv[NV_MU + r1];
#pragma unroll
        for (int nt = 0; nt < 4; nt++) {
            int c0 = nbase + nt * 8 + 2 * t;
            float ua = sv[NV_U + c0],  ub = sv[NV_U + c0 + 1];
            float va = sv[NV_VB + c0], vb = sv[NV_VB + c0 + 1];
            if (n0 + r0 < NN) {
                float2 xv = *(const float2*)(x + (size_t)(n0 + r0) * 128 + c0);
                *(float2*)(out_x + (size_t)(n0 + r0) * 128 + c0) =
                    make_float2(xv.x + rs0 * c[mt][nt][0] - b0 * ua + va,
                                xv.y + rs0 * c[mt][nt][1] - b0 * ub + vb);
            }
            if (n0 + r1 < NN) {
                float2 xv = *(const float2*)(x + (size_t)(n0 + r1) * 128 + c0);
                *(float2*)(out_x + (size_t)(n0 + r1) * 128 + c0) =
                    make_float2(xv.x + rs1 * c[mt][nt][2] - b1 * ua + va,
                                xv.y + rs1 * c[mt][nt][3] - b1 * ub + vb);
            }
        }
    }
}

// ---------------- launch ------------------------------------------------------
extern "C" void kernel_launch(void* const* d_in, const int* in_sizes, int n_in,
                              void* d_out, int out_size)
{
    const float*     x     = (const float*)d_in[0];
    const float*     pos   = (const float*)d_in[1];
    const void*      ei    = d_in[2];
    const float*     ea    = (const float*)d_in[3];
    const float*     e_w1  = (const float*)d_in[4];
    const float*     e_b1  = (const float*)d_in[5];
    const float*     e_g1  = (const float*)d_in[6];
    const float*     e_be1 = (const float*)d_in[7];
    const float*     e_w2  = (const float*)d_in[8];
    const float*     e_b2  = (const float*)d_in[9];
    const float*     e_g2  = (const float*)d_in[10];
    const float*     e_be2 = (const float*)d_in[11];
    const float*     n_w1  = (const float*)d_in[12];
    const float*     n_b1  = (const float*)d_in[13];
    const float*     n_g1  = (const float*)d_in[14];
    const float*     n_be1 = (const float*)d_in[15];
    const float*     n_w2  = (const float*)d_in[16];
    const float*     n_b2  = (const float*)d_in[17];
    const float*     c_w1  = (const float*)d_in[18];
    const float*     c_b1  = (const float*)d_in[19];
    const float*     c_w2  = (const float*)d_in[20];
    const float*     c_b2  = (const float*)d_in[21];

    float* out_x   = (float*)d_out;
    float* out_pos = (float*)d_out + (size_t)NN * FEAT;

    cudaFuncSetAttribute(preab_kernel, cudaFuncAttributeMaxDynamicSharedMemorySize, PB_SMEM);
    cudaFuncSetAttribute(edge_kernel,  cudaFuncAttributeMaxDynamicSharedMemorySize, EDGE_SMEM);
    cudaFuncSetAttribute(node_kernel,  cudaFuncAttributeMaxDynamicSharedMemorySize, ND_SMEM);

    conv_idx_kernel<<<256, 256>>>(ei);
    init_kernel<<<256, 256>>>(pos, out_pos);
    preab_kernel<<<(NN + 127) / 128, 512, PB_SMEM>>>(x, e_w1);
    edge_kernel<<<148, 1024, EDGE_SMEM>>>(pos, ea,
                                          e_w1, e_b1, e_g1, e_be1,
                                          e_w2, e_b2, e_g2, e_be2,
                                          c_w1, c_b1, c_w2, c_b2,
                                          out_pos);
    node_kernel<<<(NN + 127) / 128, 512, ND_SMEM>>>(x, n_w1, n_b1, n_g1, n_be1,
                                                    n_w2, n_b2, out_x);
}

// round 12
// speedup vs baseline: 3.0363x; 1.0252x over previous
#include <cuda_runtime.h>
#include <cstdint>

#define NN   50000
#define EE   800000
#define FEAT 128
#define HID  128
#define EPSL 1e-5f

#define ASTR 132          // MMA A-tile stride (floats)
#define BSTR 136          // MMA weight-tile stride (floats)

// ---------------- scratch (device globals) -----------------------------------
__device__ float g_A[NN * FEAT];      // x @ Wa   (e_w1 rows   0..127)
__device__ float g_B[NN * FEAT];      // x @ Wb   (e_w1 rows 128..255)
__device__ float g_aggm[NN * HID];    // segment-sum of m_ij
__device__ int   g_src[EE];
__device__ int   g_dst[EE];

__device__ __forceinline__ float silu_f(float v) {
    return __fdividef(v, 1.0f + __expf(-v));
}
__device__ __forceinline__ uint32_t f2tf32(float f) {
    uint32_t r; asm("cvt.rna.tf32.f32 %0, %1;" : "=r"(r) : "f"(f)); return r;
}
// column permutation within each 32-block so a thread's 4 B-frag values are contiguous
__device__ __forceinline__ int permn(int n) {
    return (n & ~31) + ((n & 7) << 2) + ((n >> 3) & 3);
}
__device__ __forceinline__ void mma8(float* d, const uint32_t* a, const uint32_t* b) {
    asm volatile("mma.sync.aligned.m16n8k8.row.col.f32.tf32.tf32.f32 "
                 "{%0,%1,%2,%3}, {%4,%5,%6,%7}, {%8,%9}, {%0,%1,%2,%3};"
                 : "+f"(d[0]), "+f"(d[1]), "+f"(d[2]), "+f"(d[3])
                 : "r"(a[0]), "r"(a[1]), "r"(a[2]), "r"(a[3]), "r"(b[0]), "r"(b[1]));
}

// per-warp tf32 GEMM: C[16x32] += A[16x128] * B[128x32]; B is n-permuted
__device__ __forceinline__ void warp_gemm1(const uint32_t* __restrict__ Au,
                                           const uint32_t* __restrict__ Bu,
                                           float c[4][4],
                                           int mbase, int nbase, int g, int t)
{
#pragma unroll 1
    for (int ks = 0; ks < 16; ks++) {
        int kk = ks * 8;
        uint32_t af[4];
        {
            const uint32_t* p = Au + (mbase + g) * ASTR + kk + t;
            af[0] = p[0];
            af[1] = p[8 * ASTR];
            af[2] = p[4];
            af[3] = p[8 * ASTR + 4];
        }
        const uint32_t* pb = Bu + (kk + t) * BSTR + nbase + 4 * g;
        uint4 b0 = *(const uint4*)pb;
        uint4 b1 = *(const uint4*)(pb + 4 * BSTR);
        uint32_t bf[4][2] = {{b0.x, b1.x}, {b0.y, b1.y}, {b0.z, b1.z}, {b0.w, b1.w}};
#pragma unroll
        for (int nt = 0; nt < 4; nt++)
            mma8(c[nt], af, bf[nt]);
    }
}

// per-warp tf32 GEMM (512-thr kernels): C[32x32] += A[32x128] * B[128x32]; B n-permuted
__device__ __forceinline__ void warp_gemm2(const uint32_t* __restrict__ Au,
                                           const uint32_t* __restrict__ Bu,
                                           float c[2][4][4],
                                           int mbase, int nbase, int g, int t)
{
#pragma unroll 1
    for (int ks = 0; ks < 16; ks++) {
        int kk = ks * 8;
        uint32_t af[2][4];
#pragma unroll
        for (int mt = 0; mt < 2; mt++) {
            const uint32_t* p = Au + (mbase + mt * 16 + g) * ASTR + kk + t;
            af[mt][0] = p[0];
            af[mt][1] = p[8 * ASTR];
            af[mt][2] = p[4];
            af[mt][3] = p[8 * ASTR + 4];
        }
        const uint32_t* pb = Bu + (kk + t) * BSTR + nbase + 4 * g;
        uint4 b0 = *(const uint4*)pb;
        uint4 b1 = *(const uint4*)(pb + 4 * BSTR);
        uint32_t bf[4][2] = {{b0.x, b1.x}, {b0.y, b1.y}, {b0.z, b1.z}, {b0.w, b1.w}};
#pragma unroll
        for (int mt = 0; mt < 2; mt++)
#pragma unroll
            for (int nt = 0; nt < 4; nt++)
                mma8(c[mt][nt], af[mt], bf[nt]);
    }
}

// ---------------- K-1: normalize edge_index dtype ----------------------------
__global__ void conv_idx_kernel(const void* __restrict__ ei_raw)
{
    const long long* e64 = (const long long*)ei_raw;
    const int*       e32 = (const int*)ei_raw;
    bool is64 = true;
#pragma unroll
    for (int j = 0; j < 8; j++) {
        long long v = e64[j];
        if (v < 0 || v >= NN) is64 = false;
    }
    int i = blockIdx.x * blockDim.x + threadIdx.x;
    int stride = gridDim.x * blockDim.x;
    if (is64) {
        for (int e = i; e < EE; e += stride) {
            g_src[e] = (int)e64[e];
            g_dst[e] = (int)e64[EE + e];
        }
    } else {
        for (int e = i; e < EE; e += stride) {
            g_src[e] = e32[e];
            g_dst[e] = e32[EE + e];
        }
    }
}

// ---------------- K0: zero agg_m, pos_out = pos ------------------------------
__global__ void init_kernel(const float* __restrict__ pos, float* __restrict__ out_pos)
{
    int i = blockIdx.x * blockDim.x + threadIdx.x;
    int stride = gridDim.x * blockDim.x;
    for (int j = i; j < NN * HID; j += stride) g_aggm[j] = 0.0f;
    for (int j = i; j < NN * 3;   j += stride) out_pos[j] = pos[j];
}

// ---------------- K1: A = x@Wa, B = x@Wb (tf32 MMA, 512 thr) ------------------
#define PB_SMEM (51712 * 4)
__global__ __launch_bounds__(512, 1)
void preab_kernel(const float* __restrict__ x, const float* __restrict__ e_w1)
{
    extern __shared__ float sm[];
    float* As  = sm;
    float* B1s = sm + 16896;
    float* B2s = sm + 34304;
    const uint32_t* Au  = (const uint32_t*)As;
    const uint32_t* B1u = (const uint32_t*)B1s;
    const uint32_t* B2u = (const uint32_t*)B2s;

    int tid = threadIdx.x, warp = tid >> 5, lane = tid & 31;
    int g = lane >> 2, t = lane & 3;
    int wm = warp >> 2, wn = warp & 3;
    int mbase = wm * 32, nbase = wn * 32;
    int n0 = blockIdx.x * 128;

    for (int idx = tid; idx < 16384; idx += 512) {
        int row = idx >> 7, k = idx & 127;
        float v = (n0 + row < NN) ? x[(size_t)(n0 + row) * 128 + k] : 0.f;
        As[row * ASTR + k]  = __uint_as_float(f2tf32(v));
        int kp = permn(k);
        B1s[row * BSTR + kp] = __uint_as_float(f2tf32(e_w1[row * 128 + k]));
        B2s[row * BSTR + kp] = __uint_as_float(f2tf32(e_w1[(128 + row) * 128 + k]));
    }
    __syncthreads();

    float c[2][4][4];
#pragma unroll
    for (int mt = 0; mt < 2; mt++)
#pragma unroll
        for (int nt = 0; nt < 4; nt++)
#pragma unroll
            for (int j = 0; j < 4; j++) c[mt][nt][j] = 0.f;
    warp_gemm2(Au, B1u, c, mbase, nbase, g, t);
#pragma unroll
    for (int mt = 0; mt < 2; mt++) {
        int r0 = mbase + mt * 16 + g, r1 = r0 + 8;
#pragma unroll
        for (int nt = 0; nt < 4; nt++) {
            int c0 = nbase + nt * 8 + 2 * t;
            if (n0 + r0 < NN)
                *(float2*)(g_A + (size_t)(n0 + r0) * 128 + c0) = make_float2(c[mt][nt][0], c[mt][nt][1]);
            if (n0 + r1 < NN)
                *(float2*)(g_A + (size_t)(n0 + r1) * 128 + c0) = make_float2(c[mt][nt][2], c[mt][nt][3]);
        }
    }

#pragma unroll
    for (int mt = 0; mt < 2; mt++)
#pragma unroll
        for (int nt = 0; nt < 4; nt++)
#pragma unroll
            for (int j = 0; j < 4; j++) c[mt][nt][j] = 0.f;
    warp_gemm2(Au, B2u, c, mbase, nbase, g, t);
#pragma unroll
    for (int mt = 0; mt < 2; mt++) {
        int r0 = mbase + mt * 16 + g, r1 = r0 + 8;
#pragma unroll
        for (int nt = 0; nt < 4; nt++) {
            int c0 = nbase + nt * 8 + 2 * t;
            if (n0 + r0 < NN)
                *(float2*)(g_B + (size_t)(n0 + r0) * 128 + c0) = make_float2(c[mt][nt][0], c[mt][nt][1]);
            if (n0 + r1 < NN)
                *(float2*)(g_B + (size_t)(n0 + r1) * 128 + c0) = make_float2(c[mt][nt][2], c[mt][nt][3]);
        }
    }
}

// ---------------- K2: persistent edge kernel ----------------------------------
// Two independent 512-thread groups; interleaved epilogue constants.
#define EO_A    0                       // 2 groups x 64 x ASTR = 16896
#define EO_B1   16896
#define EO_B2   34304
#define EO_SV   51712                   // shared constants (1408 floats)
#define EO_GRP  53120                   // per-group scratch, 1408 floats each
// shared const indices (relative to sv)
#define SV_WC0  0
#define SV_WC1  128
#define SV_WD   256
#define SV_B1   384
#define SV_I1   512    // interleaved (u1, vb1) pairs, 256 floats
#define SV_IG   768    // interleaved (g2, be2) pairs, 256 floats
#define SV_I2   1024   // interleaved (u2, vb2) pairs, 256 floats
#define SV_CW2  1280   // 128 floats
// per-group indices (relative to gsv)
#define GV_RELX 0
#define GV_RELY 64
#define GV_RELZ 128
#define GV_R2   192
#define GV_EA0  256
#define GV_EA1  320
#define GV_MU1  384
#define GV_RS1  448
#define GV_SUM  512    // [64][4]
#define GV_SQ   768    // [64][4]
#define GV_SUM2 1024   // [64][4]
#define GV_IDX  1280   // ints: 64 dst, 64 src
#define GRP_FLOATS 1408
#define EDGE_SMEM ((EO_GRP + 2 * GRP_FLOATS) * 4)   // 223744 bytes

#define BARG(id) asm volatile("bar.sync %0, 512;" :: "r"(id) : "memory")

__global__ __launch_bounds__(1024, 1)
void edge_kernel(const float* __restrict__ pos,
                 const float* __restrict__ ea,
                 const float* __restrict__ e_w1, const float* __restrict__ e_b1,
                 const float* __restrict__ e_g1, const float* __restrict__ e_be1,
                 const float* __restrict__ e_w2, const float* __restrict__ e_b2,
                 const float* __restrict__ e_g2, const float* __restrict__ e_be2,
                 const float* __restrict__ c_w1, const float* __restrict__ c_b1,
                 const float* __restrict__ c_w2, const float* __restrict__ c_b2,
                 float* __restrict__ out_pos)
{
    extern __shared__ float sm[];
    float* B1s = sm + EO_B1;
    float* B2s = sm + EO_B2;
    float* sv  = sm + EO_SV;
    const uint32_t* B1u = (const uint32_t*)B1s;
    const uint32_t* B2u = (const uint32_t*)B2s;

    int tid = threadIdx.x, warp = tid >> 5, lane = tid & 31;
    int gid = warp >> 4;
    int wig = warp & 15;
    int gtid = tid & 511;
    int bar = gid + 1;
    int g = lane >> 2, t = lane & 3;
    int wm = wig >> 2, wn = wig & 3;
    int mbase = wm * 16, nbase = wn * 32;

    float* As  = sm + EO_A + gid * (64 * ASTR);
    float* gsv = sm + EO_GRP + gid * GRP_FLOATS;
    int*   gdst = (int*)(gsv + GV_IDX);
    int*   gsrc = gdst + 64;
    const uint32_t* Au = (const uint32_t*)As;

    // ---- stage LN-folded weights (tf32, n-permuted) + shared constants ----
    for (int idx = tid; idx < 16384; idx += 1024) {
        int k = idx >> 7, n = idx & 127;
        int np = permn(n);
        B1s[k * BSTR + np] = __uint_as_float(f2tf32(e_g1[k] * e_w2[k * 128 + n]));
        B2s[k * BSTR + np] = __uint_as_float(f2tf32(e_g2[k] * c_w1[k * 128 + n]));
    }
    if (tid < 128) {
        sv[SV_WC0 + tid] = e_w1[256 * 128 + tid];
        sv[SV_WC1 + tid] = e_w1[257 * 128 + tid];
        sv[SV_WD  + tid] = e_w1[258 * 128 + tid];
        sv[SV_B1  + tid] = e_b1[tid];
        sv[SV_IG  + 2 * tid]     = e_g2[tid];
        sv[SV_IG  + 2 * tid + 1] = e_be2[tid];
        sv[SV_CW2 + tid] = c_w2[tid];
    }
    if (tid < 512) {
        int quad = tid >> 7, n = tid & 127;
        float acc = 0.f;
        if (quad == 0) {
            for (int k = 0; k < 128; k++) acc += e_g1[k] * e_w2[k * 128 + n];
            sv[SV_I1 + 2 * n] = acc;
        } else if (quad == 1) {
            for (int k = 0; k < 128; k++) acc += e_be1[k] * e_w2[k * 128 + n];
            sv[SV_I1 + 2 * n + 1] = acc + e_b2[n];
        } else if (quad == 2) {
            for (int k = 0; k < 128; k++) acc += e_g2[k] * c_w1[k * 128 + n];
            sv[SV_I2 + 2 * n] = acc;
        } else {
            for (int k = 0; k < 128; k++) acc += e_be2[k] * c_w1[k * 128 + n];
            sv[SV_I2 + 2 * n + 1] = acc + c_b1[n];
        }
    }
    float cb2 = c_b2[0];
    __syncthreads();

    int k4 = lane * 4;
    bool first = true;

    const int ntiles = EE / 64;
    for (int tile = blockIdx.x * 2 + gid; tile < ntiles; tile += 2 * gridDim.x) {
        int e0 = tile * 64;
        // ---- phase A (gtid<64): prev-tile pos atomics + stage edge meta ----
        if (gtid < 64) {
            if (!first) {
                float coef = gsv[GV_SUM2 + gtid * 4] + gsv[GV_SUM2 + gtid * 4 + 1]
                           + gsv[GV_SUM2 + gtid * 4 + 2] + gsv[GV_SUM2 + gtid * 4 + 3] + cb2;
                int dip = gdst[gtid];
                atomicAdd(&out_pos[dip * 3 + 0], gsv[GV_RELX + gtid] * coef);
                atomicAdd(&out_pos[dip * 3 + 1], gsv[GV_RELY + gtid] * coef);
                atomicAdd(&out_pos[dip * 3 + 2], gsv[GV_RELZ + gtid] * coef);
            }
            int e = e0 + gtid;
            int si = g_src[e], di = g_dst[e];
            float rx = pos[di * 3 + 0] - pos[si * 3 + 0];
            float ry = pos[di * 3 + 1] - pos[si * 3 + 1];
            float rz = pos[di * 3 + 2] - pos[si * 3 + 2];
            gsrc[gtid] = si; gdst[gtid] = di;
            gsv[GV_RELX + gtid] = rx; gsv[GV_RELY + gtid] = ry; gsv[GV_RELZ + gtid] = rz;
            gsv[GV_R2 + gtid]  = rx * rx + ry * ry + rz * rz;
            gsv[GV_EA0 + gtid] = ea[2 * e];
            gsv[GV_EA1 + gtid] = ea[2 * e + 1];
        }
        first = false;
        BARG(bar);

        // ---- layer-1: gather + SiLU -> As (raw h, tf32); row stats ----
        {
            float4 wc0 = *(const float4*)(sv + SV_WC0 + k4);
            float4 wc1 = *(const float4*)(sv + SV_WC1 + k4);
            float4 wdv = *(const float4*)(sv + SV_WD  + k4);
            float4 b1v = *(const float4*)(sv + SV_B1  + k4);
#pragma unroll 2
            for (int r = 0; r < 4; r++) {
                int row = wig * 4 + r;
                int si = gsrc[row], di = gdst[row];
                float4 a = *(const float4*)(g_A + (size_t)si * 128 + k4);
                float4 b = *(const float4*)(g_B + (size_t)di * 128 + k4);
                float e0v = gsv[GV_EA0 + row], e1v = gsv[GV_EA1 + row], r2v = gsv[GV_R2 + row];
                float4 o;
                o.x = silu_f(a.x + b.x + e0v * wc0.x + e1v * wc1.x + r2v * wdv.x + b1v.x);
                o.y = silu_f(a.y + b.y + e0v * wc0.y + e1v * wc1.y + r2v * wdv.y + b1v.y);
                o.z = silu_f(a.z + b.z + e0v * wc0.z + e1v * wc1.z + r2v * wdv.z + b1v.z);
                o.w = silu_f(a.w + b.w + e0v * wc0.w + e1v * wc1.w + r2v * wdv.w + b1v.w);
                float s = o.x + o.y + o.z + o.w;
                float q = o.x * o.x + o.y * o.y + o.z * o.z + o.w * o.w;
#pragma unroll
                for (int off = 16; off > 0; off >>= 1) {
                    s += __shfl_xor_sync(0xffffffffu, s, off);
                    q += __shfl_xor_sync(0xffffffffu, q, off);
                }
                uint4 tv;
                tv.x = f2tf32(o.x); tv.y = f2tf32(o.y);
                tv.z = f2tf32(o.z); tv.w = f2tf32(o.w);
                *(uint4*)(As + row * ASTR + k4) = tv;
                if (lane == 0) {
                    float mu = s * (1.0f / 128.0f);
                    gsv[GV_MU1 + row] = mu;
                    gsv[GV_RS1 + row] = rsqrtf(q * (1.0f / 128.0f) - mu * mu + EPSL);
                }
            }
        }
        BARG(bar);

        // ---- GEMM1: h @ (g1 ∘ e_w2) ----
        float c[4][4];
#pragma unroll
        for (int nt = 0; nt < 4; nt++)
#pragma unroll
            for (int j = 0; j < 4; j++) c[nt][j] = 0.f;
        warp_gemm1(Au, B1u, c, mbase, nbase, g, t);
        BARG(bar);

        // ---- ep1: y = rs1*(d - mu1*u1) + vb1 ; z = silu(y) -> As + partials ----
        {
            int r0 = mbase + g, r1 = r0 + 8;
            float rsA = gsv[GV_RS1 + r0], bA = rsA * gsv[GV_MU1 + r0];
            float rsB = gsv[GV_RS1 + r1], bB = rsB * gsv[GV_MU1 + r1];
            float s0 = 0.f, q0 = 0.f, s1 = 0.f, q1 = 0.f;
#pragma unroll
            for (int nt = 0; nt < 4; nt++) {
                int c0 = nbase + nt * 8 + 2 * t;
                float4 P = *(const float4*)(sv + SV_I1 + 2 * c0);   // u1a, vba, u1b, vbb
                float z0 = silu_f(rsA * c[nt][0] - bA * P.x + P.y);
                float z1 = silu_f(rsA * c[nt][1] - bA * P.z + P.w);
                float z2 = silu_f(rsB * c[nt][2] - bB * P.x + P.y);
                float z3 = silu_f(rsB * c[nt][3] - bB * P.z + P.w);
                c[nt][0] = z0; c[nt][1] = z1; c[nt][2] = z2; c[nt][3] = z3;
                uint2 p0; p0.x = f2tf32(z0); p0.y = f2tf32(z1);
                uint2 p1; p1.x = f2tf32(z2); p1.y = f2tf32(z3);
                *(uint2*)(As + r0 * ASTR + c0) = p0;
                *(uint2*)(As + r1 * ASTR + c0) = p1;
                s0 += z0 + z1; q0 += z0 * z0 + z1 * z1;
                s1 += z2 + z3; q1 += z2 * z2 + z3 * z3;
            }
#pragma unroll
            for (int off = 1; off <= 2; off <<= 1) {
                s0 += __shfl_xor_sync(0xffffffffu, s0, off);
                s1 += __shfl_xor_sync(0xffffffffu, s1, off);
                q0 += __shfl_xor_sync(0xffffffffu, q0, off);
                q1 += __shfl_xor_sync(0xffffffffu, q1, off);
            }
            if (t == 0) {
                gsv[GV_SUM + r0 * 4 + wn] = s0;
                gsv[GV_SQ  + r0 * 4 + wn] = q0;
                gsv[GV_SUM + r1 * 4 + wn] = s1;
                gsv[GV_SQ  + r1 * 4 + wn] = q1;
            }
        }
        BARG(bar);

        // ---- phase B: local LN2 stats, aggm atomics, GEMM2, ep2 partials ----
        {
            int r0 = mbase + g, r1 = r0 + 8;
            float s0 = gsv[GV_SUM + r0 * 4] + gsv[GV_SUM + r0 * 4 + 1]
                     + gsv[GV_SUM + r0 * 4 + 2] + gsv[GV_SUM + r0 * 4 + 3];
            float q0 = gsv[GV_SQ + r0 * 4] + gsv[GV_SQ + r0 * 4 + 1]
                     + gsv[GV_SQ + r0 * 4 + 2] + gsv[GV_SQ + r0 * 4 + 3];
            float s1 = gsv[GV_SUM + r1 * 4] + gsv[GV_SUM + r1 * 4 + 1]
                     + gsv[GV_SUM + r1 * 4 + 2] + gsv[GV_SUM + r1 * 4 + 3];
            float q1 = gsv[GV_SQ + r1 * 4] + gsv[GV_SQ + r1 * 4 + 1]
                     + gsv[GV_SQ + r1 * 4 + 2] + gsv[GV_SQ + r1 * 4 + 3];
            float mu0 = s0 * (1.0f / 128.0f);
            float rs0 = rsqrtf(q0 * (1.0f / 128.0f) - mu0 * mu0 + EPSL);
            float mu1 = s1 * (1.0f / 128.0f);
            float rs1 = rsqrtf(q1 * (1.0f / 128.0f) - mu1 * mu1 + EPSL);

            int d0 = gdst[r0], d1 = gdst[r1];
#pragma unroll
            for (int nt = 0; nt < 4; nt++) {
                int c0 = nbase + nt * 8 + 2 * t;
                float4 G = *(const float4*)(sv + SV_IG + 2 * c0);   // g2a, bea, g2b, beb
                float m0 = (c[nt][0] - mu0) * rs0 * G.x + G.y;
                float m1 = (c[nt][1] - mu0) * rs0 * G.z + G.w;
                float m2 = (c[nt][2] - mu1) * rs1 * G.x + G.y;
                float m3 = (c[nt][3] - mu1) * rs1 * G.z + G.w;
                asm volatile("red.global.add.v2.f32 [%0], {%1, %2};"
                             :: "l"(g_aggm + (size_t)d0 * 128 + c0), "f"(m0), "f"(m1) : "memory");
                asm volatile("red.global.add.v2.f32 [%0], {%1, %2};"
                             :: "l"(g_aggm + (size_t)d1 * 128 + c0), "f"(m2), "f"(m3) : "memory");
            }

            // GEMM2: z @ (g2 ∘ c_w1)
#pragma unroll
            for (int nt = 0; nt < 4; nt++)
#pragma unroll
                for (int j = 0; j < 4; j++) c[nt][j] = 0.f;
            warp_gemm1(Au, B2u, c, mbase, nbase, g, t);

            // ep2: val = rs*(d - mu*u2) + vb2 ; coef partials -> SUM2
            float b0 = rs0 * mu0, b1 = rs1 * mu1;
            float p0 = 0.f, p1 = 0.f;
#pragma unroll
            for (int nt = 0; nt < 4; nt++) {
                int c0 = nbase + nt * 8 + 2 * t;
                float4 Q = *(const float4*)(sv + SV_I2 + 2 * c0);   // u2a, vba, u2b, vbb
                float2 W = *(const float2*)(sv + SV_CW2 + c0);
                p0 += silu_f(rs0 * c[nt][0] - b0 * Q.x + Q.y) * W.x
                    + silu_f(rs0 * c[nt][1] - b0 * Q.z + Q.w) * W.y;
                p1 += silu_f(rs1 * c[nt][2] - b1 * Q.x + Q.y) * W.x
                    + silu_f(rs1 * c[nt][3] - b1 * Q.z + Q.w) * W.y;
            }
#pragma unroll
            for (int off = 1; off <= 2; off <<= 1) {
                p0 += __shfl_xor_sync(0xffffffffu, p0, off);
                p1 += __shfl_xor_sync(0xffffffffu, p1, off);
            }
            if (t == 0) {
                gsv[GV_SUM2 + r0 * 4 + wn] = p0;
                gsv[GV_SUM2 + r1 * 4 + wn] = p1;
            }
        }
        BARG(bar);
    }

    // ---- final tile's pos atomics (per group) ----
    if (!first && gtid < 64) {
        float coef = gsv[GV_SUM2 + gtid * 4] + gsv[GV_SUM2 + gtid * 4 + 1]
                   + gsv[GV_SUM2 + gtid * 4 + 2] + gsv[GV_SUM2 + gtid * 4 + 3] + cb2;
        int di = gdst[gtid];
        atomicAdd(&out_pos[di * 3 + 0], gsv[GV_RELX + gtid] * coef);
        atomicAdd(&out_pos[di * 3 + 1], gsv[GV_RELY + gtid] * coef);
        atomicAdd(&out_pos[di * 3 + 2], gsv[GV_RELZ + gtid] * coef);
    }
}

// ---------------- K3: node MLP + residual (tf32 MMA, 512 thr) ----------------
#define NV_B1   0
#define NV_I    128    // interleaved (u, vb) pairs, 256 floats
#define NV_MU   384
#define NV_RS   512
#define NV_SUM  640    // [128][4]
#define NV_SQ   1152   // [128][4]
#define NV_FLOATS 1664
#define ND_SMEM ((34304 + NV_FLOATS) * 4)
__global__ __launch_bounds__(512, 1)
void node_kernel(const float* __restrict__ x,
                 const float* __restrict__ n_w1, const float* __restrict__ n_b1,
                 const float* __restrict__ n_g1, const float* __restrict__ n_be1,
                 const float* __restrict__ n_w2, const float* __restrict__ n_b2,
                 float* __restrict__ out_x)
{
    extern __shared__ float sm[];
    float* As = sm;
    float* Bs = sm + 16896;
    float* sv = sm + 34304;
    const uint32_t* Au = (const uint32_t*)As;
    const uint32_t* Bu = (const uint32_t*)Bs;

    int tid = threadIdx.x, warp = tid >> 5, lane = tid & 31;
    int g = lane >> 2, t = lane & 3;
    int wm = warp >> 2, wn = warp & 3;
    int mbase = wm * 32, nbase = wn * 32;
    int n0 = blockIdx.x * 128;

    if (tid < 128) sv[NV_B1 + tid] = n_b1[tid];
    if (tid >= 128 && tid < 384) {
        int half = (tid - 128) >> 7, n = tid & 127;
        float acc = 0.f;
        if (half == 0) {
            for (int k = 0; k < 128; k++) acc += n_g1[k] * n_w2[k * 128 + n];
            sv[NV_I + 2 * n] = acc;
        } else {
            for (int k = 0; k < 128; k++) acc += n_be1[k] * n_w2[k * 128 + n];
            sv[NV_I + 2 * n + 1] = acc + n_b2[n];
        }
    }

    // phase 1: x @ W1a
    for (int idx = tid; idx < 16384; idx += 512) {
        int row = idx >> 7, k = idx & 127;
        float v = (n0 + row < NN) ? x[(size_t)(n0 + row) * 128 + k] : 0.f;
        As[row * ASTR + k] = __uint_as_float(f2tf32(v));
        Bs[row * BSTR + permn(k)] = __uint_as_float(f2tf32(n_w1[row * 128 + k]));
    }
    __syncthreads();

    float c[2][4][4];
#pragma unroll
    for (int mt = 0; mt < 2; mt++)
#pragma unroll
        for (int nt = 0; nt < 4; nt++)
#pragma unroll
            for (int j = 0; j < 4; j++) c[mt][nt][j] = 0.f;
    warp_gemm2(Au, Bu, c, mbase, nbase, g, t);
    __syncthreads();

    // phase 2: + aggm @ W1b
    for (int idx = tid; idx < 16384; idx += 512) {
        int row = idx >> 7, k = idx & 127;
        float v = (n0 + row < NN) ? g_aggm[(size_t)(n0 + row) * 128 + k] : 0.f;
        As[row * ASTR + k] = __uint_as_float(f2tf32(v));
        Bs[row * BSTR + permn(k)] = __uint_as_float(f2tf32(n_w1[(128 + row) * 128 + k]));
    }
    __syncthreads();
    warp_gemm2(Au, Bu, c, mbase, nbase, g, t);
    __syncthreads();

    // ep1: z = silu(acc + b1) -> As (tf32) + row stats
#pragma unroll
    for (int mt = 0; mt < 2; mt++) {
        int r0 = mbase + mt * 16 + g, r1 = r0 + 8;
        float s0 = 0.f, q0 = 0.f, s1 = 0.f, q1 = 0.f;
#pragma unroll
        for (int nt = 0; nt < 4; nt++) {
            int c0 = nbase + nt * 8 + 2 * t;
            float ba = sv[NV_B1 + c0], bb = sv[NV_B1 + c0 + 1];
            float z0 = silu_f(c[mt][nt][0] + ba);
            float z1 = silu_f(c[mt][nt][1] + bb);
            float z2 = silu_f(c[mt][nt][2] + ba);
            float z3 = silu_f(c[mt][nt][3] + bb);
            uint2 p0; p0.x = f2tf32(z0); p0.y = f2tf32(z1);
            uint2 p1; p1.x = f2tf32(z2); p1.y = f2tf32(z3);
            *(uint2*)(As + r0 * ASTR + c0) = p0;
            *(uint2*)(As + r1 * ASTR + c0) = p1;
            s0 += z0 + z1; q0 += z0 * z0 + z1 * z1;
            s1 += z2 + z3; q1 += z2 * z2 + z3 * z3;
        }
#pragma unroll
        for (int off = 1; off <= 2; off <<= 1) {
            s0 += __shfl_xor_sync(0xffffffffu, s0, off);
            s1 += __shfl_xor_sync(0xffffffffu, s1, off);
            q0 += __shfl_xor_sync(0xffffffffu, q0, off);
            q1 += __shfl_xor_sync(0xffffffffu, q1, off);
        }
        if (t == 0) {
            sv[NV_SUM + r0 * 4 + wn] = s0;
            sv[NV_SQ  + r0 * 4 + wn] = q0;
            sv[NV_SUM + r1 * 4 + wn] = s1;
            sv[NV_SQ  + r1 * 4 + wn] = q1;
        }
    }
    __syncthreads();
    if (tid < 128) {
        float s = sv[NV_SUM + tid * 4] + sv[NV_SUM + tid * 4 + 1]
                + sv[NV_SUM + tid * 4 + 2] + sv[NV_SUM + tid * 4 + 3];
        float q = sv[NV_SQ + tid * 4] + sv[NV_SQ + tid * 4 + 1]
                + sv[NV_SQ + tid * 4 + 2] + sv[NV_SQ + tid * 4 + 3];
        float mu = s * (1.0f / 128.0f);
        sv[NV_MU + tid] = mu;
        sv[NV_RS + tid] = rsqrtf(q * (1.0f / 128.0f) - mu * mu + EPSL);
    }
    // stage (g1 ∘ W2) into Bs (n-permuted)
    for (int idx = tid; idx < 16384; idx += 512) {
        int k = idx >> 7, n = idx & 127;
        Bs[k * BSTR + permn(n)] = __uint_as_float(f2tf32(n_g1[k] * n_w2[k * 128 + n]));
    }
    __syncthreads();

    // GEMM2: z @ (g1 ∘ W2)
#pragma unroll
    for (int mt = 0; mt < 2; mt++)
#pragma unroll
        for (int nt = 0; nt < 4; nt++)
#pragma unroll
            for (int j = 0; j < 4; j++) c[mt][nt][j] = 0.f;
    warp_gemm2(Au, Bu, c, mbase, nbase, g, t);

    // ep2: out = x + rs*d - rs*mu*u + vb
#pragma unroll
    for (int mt = 0; mt < 2; mt++) {
        int r0 = mbase + mt * 16 + g, r1 = r0 + 8;
        float rs0 = sv[NV_RS + r0], b0 = rs0 * sv[NV_MU + r0];
        float rs1 = sv[NV_RS + r1], b1 = rs1 * sv[NV_MU + r1];
#pragma unroll
        for (int nt = 0; nt < 4; nt++) {
            int c0 = nbase + nt * 8 + 2 * t;
            float4 Q = *(const float4*)(sv + NV_I + 2 * c0);   // ua, va, ub, vb
            if (n0 + r0 < NN) {
                float2 xv = *(const float2*)(x + (size_t)(n0 + r0) * 128 + c0);
                *(float2*)(out_x + (size_t)(n0 + r0) * 128 + c0) =
                    make_float2(xv.x + rs0 * c[mt][nt][0] - b0 * Q.x + Q.y,
                                xv.y + rs0 * c[mt][nt][1] - b0 * Q.z + Q.w);
            }
            if (n0 + r1 < NN) {
                float2 xv = *(const float2*)(x + (size_t)(n0 + r1) * 128 + c0);
                *(float2*)(out_x + (size_t)(n0 + r1) * 128 + c0) =
                    make_float2(xv.x + rs1 * c[mt][nt][2] - b1 * Q.x + Q.y,
                                xv.y + rs1 * c[mt][nt][3] - b1 * Q.z + Q.w);
            }
        }
    }
}

// ---------------- launch ------------------------------------------------------
extern "C" void kernel_launch(void* const* d_in, const int* in_sizes, int n_in,
                              void* d_out, int out_size)
{
    const float*     x     = (const float*)d_in[0];
    const float*     pos   = (const float*)d_in[1];
    const void*      ei    = d_in[2];
    const float*     ea    = (const float*)d_in[3];
    const float*     e_w1  = (const float*)d_in[4];
    const float*     e_b1  = (const float*)d_in[5];
    const float*     e_g1  = (const float*)d_in[6];
    const float*     e_be1 = (const float*)d_in[7];
    const float*     e_w2  = (const float*)d_in[8];
    const float*     e_b2  = (const float*)d_in[9];
    const float*     e_g2  = (const float*)d_in[10];
    const float*     e_be2 = (const float*)d_in[11];
    const float*     n_w1  = (const float*)d_in[12];
    const float*     n_b1  = (const float*)d_in[13];
    const float*     n_g1  = (const float*)d_in[14];
    const float*     n_be1 = (const float*)d_in[15];
    const float*     n_w2  = (const float*)d_in[16];
    const float*     n_b2  = (const float*)d_in[17];
    const float*     c_w1  = (const float*)d_in[18];
    const float*     c_b1  = (const float*)d_in[19];
    const float*     c_w2  = (const float*)d_in[20];
    const float*     c_b2  = (const float*)d_in[21];

    float* out_x   = (float*)d_out;
    float* out_pos = (float*)d_out + (size_t)NN * FEAT;

    cudaFuncSetAttribute(preab_kernel, cudaFuncAttributeMaxDynamicSharedMemorySize, PB_SMEM);
    cudaFuncSetAttribute(edge_kernel,  cudaFuncAttributeMaxDynamicSharedMemorySize, EDGE_SMEM);
    cudaFuncSetAttribute(node_kernel,  cudaFuncAttributeMaxDynamicSharedMemorySize, ND_SMEM);

    conv_idx_kernel<<<256, 256>>>(ei);
    init_kernel<<<256, 256>>>(pos, out_pos);
    preab_kernel<<<(NN + 127) / 128, 512, PB_SMEM>>>(x, e_w1);
    edge_kernel<<<148, 1024, EDGE_SMEM>>>(pos, ea,
                                          e_w1, e_b1, e_g1, e_be1,
                                          e_w2, e_b2, e_g2, e_be2,
                                          c_w1, c_b1, c_w2, c_b2,
                                          out_pos);
    node_kernel<<<(NN + 127) / 128, 512, ND_SMEM>>>(x, n_w1, n_b1, n_g1, n_be1,
                                                    n_w2, n_b2, out_x);
}